// round 1
// baseline (speedup 1.0000x reference)
#include <cuda_runtime.h>
#include <cstdint>

#define S_ 4096
#define M_ 32
#define D_ 420
#define H_ 840

// ---------------- scratch (static device globals; no allocations) ----------------
__device__ int   g_rowmap[S_ * M_];              // compact row -> s*32+m
__device__ int   g_nact;                         // number of active rows
__device__ float g_invN[S_];                     // 1/numInputs[s]
__device__ float g_H1[(size_t)S_ * M_ * D_];     // layer-1 output, compact rows
__device__ float g_pooled[(size_t)S_ * D_];      // ragged-mean numerator (atomic)
__device__ float g_Y[(size_t)S_ * H_];           // layer-3 output

// ---------------- setup: prefix-scan numInputs, build compact row map -------------
__global__ void setup_kernel(const int* __restrict__ numInputs) {
    __shared__ int s_warp[8];
    __shared__ int s_woff[8];
    int t = threadIdx.x;              // 256 threads, 16 samples each
    int base = t * 16;
    int local[16];
    int run = 0;
#pragma unroll
    for (int j = 0; j < 16; j++) { local[j] = run; run += numInputs[base + j]; }
    int lane = t & 31, warp = t >> 5;
    int inc = run;
#pragma unroll
    for (int o = 1; o < 32; o <<= 1) {
        int v = __shfl_up_sync(0xffffffffu, inc, o);
        if (lane >= o) inc += v;
    }
    if (lane == 31) s_warp[warp] = inc;
    __syncthreads();
    if (t == 0) {
        int r = 0;
        for (int w = 0; w < 8; w++) { s_woff[w] = r; r += s_warp[w]; }
        g_nact = r;
    }
    __syncthreads();
    int thrOff = s_woff[warp] + (inc - run);   // exclusive prefix of this thread
    for (int j = 0; j < 16; j++) {
        int s = base + j;
        int n = numInputs[s];
        g_invN[s] = 1.0f / (float)n;
        int off = thrOff + local[j];
        for (int m = 0; m < n; m++) g_rowmap[off + m] = s * M_ + m;
    }
}

__global__ void zero_pooled_kernel() {
    int i = blockIdx.x * blockDim.x + threadIdx.x;
    if (i < S_ * D_) g_pooled[i] = 0.0f;
}

// ---------------- fused GEMM:  Out = relu(A @ W^T + b), mode-specialized ----------
// MODE 1: A = all_x gathered via rowmap, Out = g_H1 (compact), rows = g_nact
// MODE 2: A = g_H1, epilogue = segmented atomicAdd into g_pooled, rows = g_nact
// MODE 3: A = g_pooled * invN[row], Out = g_Y, rows = S
// MODE 4: A = g_Y, Out = d_out, rows = S
template <int MODE, int K>
__global__ void __launch_bounds__(256)
gemm_kernel(const float* __restrict__ Aext, const float* __restrict__ W,
            const float* __restrict__ bias, float* __restrict__ OutExt, int N) {
    constexpr int BM = 128, BN = 112, BK = 20, TM = 8, TN = 7;
    static_assert(K % BK == 0, "K must be a multiple of BK");

    __shared__ float As[BM][BK + 1];
    __shared__ float Bs[BN][BK + 1];

    const int nrows = (MODE <= 2) ? g_nact : S_;
    const int row0 = blockIdx.x * BM;
    if (row0 >= nrows) return;
    const int col0 = blockIdx.y * BN;

    const float* Ap = (MODE == 1) ? Aext
                    : (MODE == 2) ? g_H1
                    : (MODE == 3) ? g_pooled
                                  : g_Y;
    float* Op = (MODE == 1) ? g_H1
              : (MODE == 3) ? g_Y
                            : OutExt;   // MODE 4 (MODE 2 unused)
    const int astride = (MODE == 4) ? H_ : D_;

    const int t = threadIdx.x;
    const int tx = t & 15, ty = t >> 4;

    float acc[TM][TN];
#pragma unroll
    for (int i = 0; i < TM; i++)
#pragma unroll
        for (int j = 0; j < TN; j++) acc[i][j] = 0.0f;

    for (int k0 = 0; k0 < K; k0 += BK) {
        // load A tile: 128*20 = 2560 elems, 10 per thread
#pragma unroll
        for (int j = 0; j < 10; j++) {
            int idx = j * 256 + t;
            int r = idx / BK, kk = idx - r * BK;
            int grow = row0 + r;
            float v = 0.0f;
            if (grow < nrows) {
                if (MODE == 1) {
                    v = Ap[(size_t)g_rowmap[grow] * D_ + (k0 + kk)];
                } else if (MODE == 3) {
                    v = Ap[(size_t)grow * astride + (k0 + kk)] * g_invN[grow];
                } else {
                    v = Ap[(size_t)grow * astride + (k0 + kk)];
                }
            }
            As[r][kk] = v;
        }
        // load W tile (W is [N,K] row-major): 112*20 = 2240 elems
#pragma unroll
        for (int j = 0; j < 9; j++) {
            int idx = j * 256 + t;
            if (idx < BN * BK) {
                int n = idx / BK, kk = idx - n * BK;
                int gcol = col0 + n;
                Bs[n][kk] = (gcol < N) ? W[(size_t)gcol * K + (k0 + kk)] : 0.0f;
            }
        }
        __syncthreads();
#pragma unroll
        for (int kk = 0; kk < BK; kk++) {
            float a[TM], b[TN];
#pragma unroll
            for (int i = 0; i < TM; i++) a[i] = As[ty * TM + i][kk];
#pragma unroll
            for (int j = 0; j < TN; j++) b[j] = Bs[tx * TN + j][kk];
#pragma unroll
            for (int i = 0; i < TM; i++)
#pragma unroll
                for (int j = 0; j < TN; j++) acc[i][j] += a[i] * b[j];
        }
        __syncthreads();
    }

    // ---- epilogue ----
    float bj[TN];
#pragma unroll
    for (int j = 0; j < TN; j++) {
        int gcol = col0 + tx * TN + j;
        bj[j] = (gcol < N) ? bias[gcol] : 0.0f;
    }

    if (MODE == 2) {
        // segmented pooling: compact rows are sample-sorted -> merge equal-s rows
        float accum[TN];
#pragma unroll
        for (int j = 0; j < TN; j++) accum[j] = 0.0f;
        int curS = -1;
#pragma unroll
        for (int i = 0; i < TM; i++) {
            int grow = row0 + ty * TM + i;
            if (grow < nrows) {
                int s = g_rowmap[grow] >> 5;   // M_=32
                if (s != curS && curS >= 0) {
#pragma unroll
                    for (int j = 0; j < TN; j++) {
                        int gcol = col0 + tx * TN + j;
                        if (gcol < N)
                            atomicAdd(&g_pooled[(size_t)curS * D_ + gcol], accum[j]);
                    }
#pragma unroll
                    for (int j = 0; j < TN; j++) accum[j] = 0.0f;
                }
                curS = s;
#pragma unroll
                for (int j = 0; j < TN; j++)
                    accum[j] += fmaxf(acc[i][j] + bj[j], 0.0f);
            }
        }
        if (curS >= 0) {
#pragma unroll
            for (int j = 0; j < TN; j++) {
                int gcol = col0 + tx * TN + j;
                if (gcol < N)
                    atomicAdd(&g_pooled[(size_t)curS * D_ + gcol], accum[j]);
            }
        }
    } else {
#pragma unroll
        for (int i = 0; i < TM; i++) {
            int grow = row0 + ty * TM + i;
            if (grow >= nrows) continue;
#pragma unroll
            for (int j = 0; j < TN; j++) {
                int gcol = col0 + tx * TN + j;
                if (gcol >= N) continue;
                float v = acc[i][j] + bj[j];
                Op[(size_t)grow * N + gcol] = fmaxf(v, 0.0f);
            }
        }
    }
}

// ---------------------------------------------------------------------------------
extern "C" void kernel_launch(void* const* d_in, const int* in_sizes, int n_in,
                              void* d_out, int out_size) {
    (void)in_sizes; (void)n_in; (void)out_size;
    const float* all_x     = (const float*)d_in[0];
    const int*   numInputs = (const int*)  d_in[1];
    const float* W1 = (const float*)d_in[2];
    const float* b1 = (const float*)d_in[3];
    const float* W2 = (const float*)d_in[4];
    const float* b2 = (const float*)d_in[5];
    const float* W3 = (const float*)d_in[6];
    const float* b3 = (const float*)d_in[7];
    const float* W4 = (const float*)d_in[8];
    const float* b4 = (const float*)d_in[9];
    float* out = (float*)d_out;

    setup_kernel<<<1, 256>>>(numInputs);
    zero_pooled_kernel<<<(S_ * D_ + 255) / 256, 256>>>();

    // layer 1: H1 = relu(X_active @ W1^T + b1)   [nact, 420]
    gemm_kernel<1, D_><<<dim3((S_ * M_ + 127) / 128, (D_ + 111) / 112), 256>>>(
        all_x, W1, b1, nullptr, D_);
    // layer 2 + ragged sum-pool (atomic into g_pooled)
    gemm_kernel<2, D_><<<dim3((S_ * M_ + 127) / 128, (D_ + 111) / 112), 256>>>(
        nullptr, W2, b2, nullptr, D_);
    // layer 3: Y = relu((pooled/n) @ W3^T + b3)  [S, 840]
    gemm_kernel<3, D_><<<dim3(S_ / 128, (H_ + 111) / 112), 256>>>(
        nullptr, W3, b3, nullptr, H_);
    // layer 4: out = relu(Y @ W4^T + b4)         [S, 420]
    gemm_kernel<4, H_><<<dim3(S_ / 128, (D_ + 111) / 112), 256>>>(
        nullptr, W4, b4, out, D_);
}

// round 2
// speedup vs baseline: 1.1357x; 1.1357x over previous
#include <cuda_runtime.h>
#include <cstdint>

#define S_ 4096
#define M_ 32
#define D_ 420
#define H_ 840

// ---------------- scratch (static device globals; no allocations) ----------------
__device__ int   g_rowmap[S_ * M_];              // compact row -> s*32+m
__device__ int   g_nact;                         // number of active rows
__device__ float g_invN[S_];                     // 1/numInputs[s]
__device__ float g_H1[(size_t)S_ * M_ * D_];     // layer-1 output, compact rows
__device__ float g_pooled[(size_t)S_ * D_];      // ragged-mean numerator (atomic)
__device__ float g_Y[(size_t)S_ * H_];           // layer-3 output

__device__ __forceinline__ void fma2(unsigned long long& d, unsigned long long a,
                                     unsigned long long b) {
    asm("fma.rn.f32x2 %0, %1, %2, %3;" : "=l"(d) : "l"(a), "l"(b), "l"(d));
}

// ---------------- setup: prefix-scan numInputs, build compact row map -------------
__global__ void setup_kernel(const int* __restrict__ numInputs) {
    __shared__ int s_warp[8];
    __shared__ int s_woff[8];
    int t = threadIdx.x;              // 256 threads, 16 samples each
    int base = t * 16;
    int local[16];
    int run = 0;
#pragma unroll
    for (int j = 0; j < 16; j++) { local[j] = run; run += numInputs[base + j]; }
    int lane = t & 31, warp = t >> 5;
    int inc = run;
#pragma unroll
    for (int o = 1; o < 32; o <<= 1) {
        int v = __shfl_up_sync(0xffffffffu, inc, o);
        if (lane >= o) inc += v;
    }
    if (lane == 31) s_warp[warp] = inc;
    __syncthreads();
    if (t == 0) {
        int r = 0;
        for (int w = 0; w < 8; w++) { s_woff[w] = r; r += s_warp[w]; }
        g_nact = r;
    }
    __syncthreads();
    int thrOff = s_woff[warp] + (inc - run);   // exclusive prefix of this thread
    for (int j = 0; j < 16; j++) {
        int s = base + j;
        int n = numInputs[s];
        g_invN[s] = 1.0f / (float)n;
        int off = thrOff + local[j];
        for (int m = 0; m < n; m++) g_rowmap[off + m] = s * M_ + m;
    }
}

__global__ void zero_pooled_kernel() {
    int i = blockIdx.x * blockDim.x + threadIdx.x;
    if (i < S_ * D_) g_pooled[i] = 0.0f;
}

// ---------------- fused GEMM:  Out = relu(A @ W^T + b), mode-specialized ----------
// MODE 1: A = all_x gathered via rowmap, Out = g_H1 (compact), rows = g_nact
// MODE 2: A = g_H1, epilogue = segmented atomicAdd into g_pooled, rows = g_nact
// MODE 3: A = g_pooled * invN[row], Out = g_Y, rows = S
// MODE 4: A = g_Y, Out = d_out, rows = S
//
// Inner loop uses packed fma.rn.f32x2 (FFMA2): accumulators pair adjacent M rows.
// A tile stored k-major (As[kk][m], m-contiguous -> LDS.64 gives a row-pair).
// B tile stored duplicated (Bs[kk][n] = {w,w}) so no pack instructions needed.
template <int MODE, int K>
__global__ void __launch_bounds__(256, 2)
gemm_kernel(const float* __restrict__ Aext, const float* __restrict__ W,
            const float* __restrict__ bias, float* __restrict__ OutExt, int N) {
    constexpr int BM = 128, BN = 112, BK = 20, TN = 7;
    constexpr int ASTR = 130;   // floats per kk-row of As (pad 2: even for LDS.64 align)
    constexpr int BSTR = 114;   // float2 per kk-row of Bs (pad 2)
    static_assert(K % BK == 0, "K must be a multiple of BK");

    __shared__ float  As[BK * ASTR];
    __shared__ float2 Bs[BK * BSTR];

    const int nrows = (MODE <= 2) ? g_nact : S_;
    const int row0 = blockIdx.x * BM;
    if (row0 >= nrows) return;
    const int col0 = blockIdx.y * BN;

    const float* Ap = (MODE == 1) ? Aext
                    : (MODE == 2) ? g_H1
                    : (MODE == 3) ? g_pooled
                                  : g_Y;
    float* Op = (MODE == 1) ? g_H1
              : (MODE == 3) ? g_Y
                            : OutExt;
    const int astride = (MODE == 4) ? H_ : D_;

    const int t = threadIdx.x;
    const int tx = t & 15, ty = t >> 4;

    // ---- per-thread fixed load descriptors (A: 10 elems, B: 9 elems) ----
    int  aoff[10]; int sA[10]; bool aval[10];
    float ascale[10];
#pragma unroll
    for (int j = 0; j < 10; j++) {
        int idx = j * 256 + t;
        int r = idx / BK, kk = idx - r * BK;
        sA[j] = kk * ASTR + r;
        int grow = row0 + r;
        aval[j] = (grow < nrows);
        if (aval[j]) {
            int arow = (MODE == 1) ? g_rowmap[grow] : grow;
            aoff[j] = arow * astride + kk;
            ascale[j] = (MODE == 3) ? g_invN[grow] : 1.0f;
        } else { aoff[j] = 0; ascale[j] = 0.0f; }
    }
    int boff[9]; int sB[9]; bool bval[9]; bool bst[9];
#pragma unroll
    for (int j = 0; j < 9; j++) {
        int idx = j * 256 + t;
        bst[j] = (idx < BN * BK);
        int n = idx / BK, kk = idx - n * BK;
        sB[j] = kk * BSTR + n;
        int gcol = col0 + n;
        bval[j] = bst[j] && (gcol < N);
        boff[j] = bval[j] ? (gcol * K + kk) : 0;
    }

    float Ar[10], Br[9];
    // prologue: load tile 0
#pragma unroll
    for (int j = 0; j < 10; j++) {
        float v = aval[j] ? Ap[aoff[j]] : 0.0f;
        if (MODE == 3) v *= ascale[j];
        Ar[j] = aval[j] ? v : 0.0f;
    }
#pragma unroll
    for (int j = 0; j < 9; j++) Br[j] = bval[j] ? W[boff[j]] : 0.0f;
#pragma unroll
    for (int j = 0; j < 10; j++) As[sA[j]] = Ar[j];
#pragma unroll
    for (int j = 0; j < 9; j++) if (bst[j]) Bs[sB[j]] = make_float2(Br[j], Br[j]);
    __syncthreads();

    unsigned long long acc2[4][TN];
#pragma unroll
    for (int p = 0; p < 4; p++)
#pragma unroll
        for (int j = 0; j < TN; j++) acc2[p][j] = 0ULL;

    for (int k0 = 0; k0 < K; k0 += BK) {
        const bool has_next = (k0 + BK) < K;
        if (has_next) {
#pragma unroll
            for (int j = 0; j < 10; j++) {
                float v = aval[j] ? Ap[aoff[j] + k0 + BK] : 0.0f;
                if (MODE == 3) v *= ascale[j];
                Ar[j] = v;
            }
#pragma unroll
            for (int j = 0; j < 9; j++) Br[j] = bval[j] ? W[boff[j] + k0 + BK] : 0.0f;
        }
#pragma unroll
        for (int kk = 0; kk < BK; kk++) {
            unsigned long long a2[4], b2[TN];
#pragma unroll
            for (int p = 0; p < 4; p++)
                a2[p] = *reinterpret_cast<const unsigned long long*>(
                            &As[kk * ASTR + ty * 8 + 2 * p]);
#pragma unroll
            for (int j = 0; j < TN; j++)
                b2[j] = *reinterpret_cast<const unsigned long long*>(
                            &Bs[kk * BSTR + tx * TN + j]);
#pragma unroll
            for (int p = 0; p < 4; p++)
#pragma unroll
                for (int j = 0; j < TN; j++) fma2(acc2[p][j], a2[p], b2[j]);
        }
        __syncthreads();
        if (has_next) {
#pragma unroll
            for (int j = 0; j < 10; j++) As[sA[j]] = Ar[j];
#pragma unroll
            for (int j = 0; j < 9; j++)
                if (bst[j]) Bs[sB[j]] = make_float2(Br[j], Br[j]);
            __syncthreads();
        }
    }

    // ---- unpack accumulators: row i = ty*8 + 2p + h ----
    float acc[8][TN];
#pragma unroll
    for (int p = 0; p < 4; p++)
#pragma unroll
        for (int j = 0; j < TN; j++) {
            float2 v = *reinterpret_cast<float2*>(&acc2[p][j]);
            acc[2 * p][j] = v.x;
            acc[2 * p + 1][j] = v.y;
        }

    float bj[TN];
#pragma unroll
    for (int j = 0; j < TN; j++) {
        int gcol = col0 + tx * TN + j;
        bj[j] = (gcol < N) ? bias[gcol] : 0.0f;
    }

    if (MODE == 2) {
        // segmented pooling: compact rows are sample-sorted -> merge equal-s rows
        float accum[TN];
#pragma unroll
        for (int j = 0; j < TN; j++) accum[j] = 0.0f;
        int curS = -1;
#pragma unroll
        for (int i = 0; i < 8; i++) {
            int grow = row0 + ty * 8 + i;
            if (grow < nrows) {
                int s = g_rowmap[grow] >> 5;   // M_=32
                if (s != curS && curS >= 0) {
#pragma unroll
                    for (int j = 0; j < TN; j++) {
                        int gcol = col0 + tx * TN + j;
                        if (gcol < N)
                            atomicAdd(&g_pooled[(size_t)curS * D_ + gcol], accum[j]);
                    }
#pragma unroll
                    for (int j = 0; j < TN; j++) accum[j] = 0.0f;
                }
                curS = s;
#pragma unroll
                for (int j = 0; j < TN; j++)
                    accum[j] += fmaxf(acc[i][j] + bj[j], 0.0f);
            }
        }
        if (curS >= 0) {
#pragma unroll
            for (int j = 0; j < TN; j++) {
                int gcol = col0 + tx * TN + j;
                if (gcol < N)
                    atomicAdd(&g_pooled[(size_t)curS * D_ + gcol], accum[j]);
            }
        }
    } else {
#pragma unroll
        for (int i = 0; i < 8; i++) {
            int grow = row0 + ty * 8 + i;
            if (grow >= nrows) continue;
#pragma unroll
            for (int j = 0; j < TN; j++) {
                int gcol = col0 + tx * TN + j;
                if (gcol >= N) continue;
                float v = acc[i][j] + bj[j];
                Op[(size_t)grow * N + gcol] = fmaxf(v, 0.0f);
            }
        }
    }
}

// ---------------------------------------------------------------------------------
extern "C" void kernel_launch(void* const* d_in, const int* in_sizes, int n_in,
                              void* d_out, int out_size) {
    (void)in_sizes; (void)n_in; (void)out_size;
    const float* all_x     = (const float*)d_in[0];
    const int*   numInputs = (const int*)  d_in[1];
    const float* W1 = (const float*)d_in[2];
    const float* b1 = (const float*)d_in[3];
    const float* W2 = (const float*)d_in[4];
    const float* b2 = (const float*)d_in[5];
    const float* W3 = (const float*)d_in[6];
    const float* b3 = (const float*)d_in[7];
    const float* W4 = (const float*)d_in[8];
    const float* b4 = (const float*)d_in[9];
    float* out = (float*)d_out;

    setup_kernel<<<1, 256>>>(numInputs);
    zero_pooled_kernel<<<(S_ * D_ + 255) / 256, 256>>>();

    // layer 1: H1 = relu(X_active @ W1^T + b1)   [nact, 420]
    gemm_kernel<1, D_><<<dim3((S_ * M_ + 127) / 128, (D_ + 111) / 112), 256>>>(
        all_x, W1, b1, nullptr, D_);
    // layer 2 + ragged sum-pool (atomic into g_pooled)
    gemm_kernel<2, D_><<<dim3((S_ * M_ + 127) / 128, (D_ + 111) / 112), 256>>>(
        nullptr, W2, b2, nullptr, D_);
    // layer 3: Y = relu((pooled/n) @ W3^T + b3)  [S, 840]
    gemm_kernel<3, D_><<<dim3(S_ / 128, (H_ + 111) / 112), 256>>>(
        nullptr, W3, b3, nullptr, H_);
    // layer 4: out = relu(Y @ W4^T + b4)         [S, 420]
    gemm_kernel<4, H_><<<dim3(S_ / 128, (D_ + 111) / 112), 256>>>(
        nullptr, W4, b4, out, D_);
}

// round 3
// speedup vs baseline: 1.1528x; 1.0151x over previous
#include <cuda_runtime.h>
#include <cstdint>

#define S_ 4096
#define M_ 32
#define D_ 420
#define H_ 840

// ---------------- scratch (static device globals; no allocations) ----------------
__device__ int   g_rowmap[S_ * M_];              // compact row -> s*32+m
__device__ int   g_nact;                         // number of active rows
__device__ float g_invN[S_];                     // 1/numInputs[s]
__device__ float g_H1[(size_t)S_ * M_ * D_];     // layer-1 output, compact rows
__device__ float g_pooled[(size_t)S_ * D_];      // ragged-mean numerator (atomic)
__device__ float g_Y[(size_t)S_ * H_];           // layer-3 output

__device__ __forceinline__ void fma2(unsigned long long& d, unsigned long long a,
                                     unsigned long long b) {
    asm("fma.rn.f32x2 %0, %1, %2, %3;" : "=l"(d) : "l"(a), "l"(b), "l"(d));
}
__device__ __forceinline__ unsigned long long pack2(float x, float y) {
    unsigned long long r;
    asm("mov.b64 %0, {%1, %2};" : "=l"(r) : "f"(x), "f"(y));
    return r;
}

// ---------------- setup: prefix-scan numInputs, build compact row map -------------
__global__ void setup_kernel(const int* __restrict__ numInputs) {
    __shared__ int s_warp[8];
    __shared__ int s_woff[8];
    int t = threadIdx.x;              // 256 threads, 16 samples each
    int base = t * 16;
    int local[16];
    int run = 0;
#pragma unroll
    for (int j = 0; j < 16; j++) { local[j] = run; run += numInputs[base + j]; }
    int lane = t & 31, warp = t >> 5;
    int inc = run;
#pragma unroll
    for (int o = 1; o < 32; o <<= 1) {
        int v = __shfl_up_sync(0xffffffffu, inc, o);
        if (lane >= o) inc += v;
    }
    if (lane == 31) s_warp[warp] = inc;
    __syncthreads();
    if (t == 0) {
        int r = 0;
        for (int w = 0; w < 8; w++) { s_woff[w] = r; r += s_warp[w]; }
        g_nact = r;
    }
    __syncthreads();
    int thrOff = s_woff[warp] + (inc - run);   // exclusive prefix of this thread
    for (int j = 0; j < 16; j++) {
        int s = base + j;
        int n = numInputs[s];
        g_invN[s] = 1.0f / (float)n;
        int off = thrOff + local[j];
        for (int m = 0; m < n; m++) g_rowmap[off + m] = s * M_ + m;
    }
}

__global__ void zero_pooled_kernel() {
    int i = blockIdx.x * blockDim.x + threadIdx.x;
    if (i < S_ * D_) g_pooled[i] = 0.0f;
}

// ---------------- fused GEMM:  Out = relu(A @ W^T + b), mode-specialized ----------
// MODE 1: A = all_x gathered via rowmap, Out = g_H1 (compact), rows = g_nact
// MODE 2: A = g_H1, epilogue = segmented atomicAdd into g_pooled, rows = g_nact
// MODE 3: A = g_pooled * invN[row], Out = g_Y, rows = S
// MODE 4: A = g_Y, Out = d_out, rows = S
//
// Inner loop: packed fma.rn.f32x2 (FFMA2), accumulators pair adjacent M rows.
// A tile k-major (As[kk][m], m-contiguous) -> 16B vector loads give 2 row-pairs.
// B tile k-major NATURAL (no duplication in smem), padded to 8-float groups per
// thread so two LDS.128 fetch the 7 cols; {w,w} pairs built in registers (ALU).
template <int MODE, int K>
__global__ void __launch_bounds__(256, 2)
gemm_kernel(const float* __restrict__ Aext, const float* __restrict__ W,
            const float* __restrict__ bias, float* __restrict__ OutExt, int N) {
    constexpr int BM = 128, BN = 112, BK = 20, TN = 7;
    constexpr int ASTR = 132;   // floats per kk-row of As (16B-aligned, stride%32=4)
    constexpr int BSTR = 132;   // floats per kk-row of Bs (16 groups * 8 + 4 pad)
    static_assert(K % BK == 0, "K must be a multiple of BK");

    __shared__ float As[BK * ASTR];
    __shared__ float Bs[BK * BSTR];

    const int nrows = (MODE <= 2) ? g_nact : S_;
    const int row0 = blockIdx.x * BM;
    if (row0 >= nrows) return;
    const int col0 = blockIdx.y * BN;

    const float* Ap = (MODE == 1) ? Aext
                    : (MODE == 2) ? g_H1
                    : (MODE == 3) ? g_pooled
                                  : g_Y;
    float* Op = (MODE == 1) ? g_H1
              : (MODE == 3) ? g_Y
                            : OutExt;
    const int astride = (MODE == 4) ? H_ : D_;

    const int t = threadIdx.x;
    const int tx = t & 15, ty = t >> 4;

    // ---- per-thread fixed load descriptors (A: 10 elems, B: 9 elems) ----
    int  aoff[10]; int sA[10]; bool aval[10];
    float ascale[10];
#pragma unroll
    for (int j = 0; j < 10; j++) {
        int idx = j * 256 + t;
        int r = idx / BK, kk = idx - r * BK;
        sA[j] = kk * ASTR + r;
        int grow = row0 + r;
        aval[j] = (grow < nrows);
        if (aval[j]) {
            int arow = (MODE == 1) ? g_rowmap[grow] : grow;
            aoff[j] = arow * astride + kk;
            ascale[j] = (MODE == 3) ? g_invN[grow] : 1.0f;
        } else { aoff[j] = 0; ascale[j] = 0.0f; }
    }
    int boff[9]; int sB[9]; bool bval[9]; bool bst[9];
#pragma unroll
    for (int j = 0; j < 9; j++) {
        int idx = j * 256 + t;
        bst[j] = (idx < BN * BK);
        int n = idx / BK, kk = idx - n * BK;
        sB[j] = kk * BSTR + (n / TN) * 8 + (n % TN);   // 8-float groups, 16B aligned
        int gcol = col0 + n;
        bval[j] = bst[j] && (gcol < N);
        boff[j] = bval[j] ? (gcol * K + kk) : 0;
    }

    float Ar[10], Br[9];
    // prologue: load tile 0
#pragma unroll
    for (int j = 0; j < 10; j++) {
        float v = aval[j] ? Ap[aoff[j]] : 0.0f;
        if (MODE == 3) v *= ascale[j];
        Ar[j] = v;
    }
#pragma unroll
    for (int j = 0; j < 9; j++) Br[j] = bval[j] ? W[boff[j]] : 0.0f;
#pragma unroll
    for (int j = 0; j < 10; j++) As[sA[j]] = Ar[j];
#pragma unroll
    for (int j = 0; j < 9; j++) if (bst[j]) Bs[sB[j]] = Br[j];
    __syncthreads();

    unsigned long long acc2[4][TN];
#pragma unroll
    for (int p = 0; p < 4; p++)
#pragma unroll
        for (int j = 0; j < TN; j++) acc2[p][j] = 0ULL;

    const float4* AsV = reinterpret_cast<const float4*>(As);
    const float4* BsV = reinterpret_cast<const float4*>(Bs);
    const int aV = (ty * 8) >> 2;          // float4 index within kk-row of As
    const int bV = (tx * 8) >> 2;          // float4 index within kk-row of Bs

    for (int k0 = 0; k0 < K; k0 += BK) {
        const bool has_next = (k0 + BK) < K;
        if (has_next) {
#pragma unroll
            for (int j = 0; j < 10; j++) {
                float v = aval[j] ? Ap[aoff[j] + k0 + BK] : 0.0f;
                if (MODE == 3) v *= ascale[j];
                Ar[j] = v;
            }
#pragma unroll
            for (int j = 0; j < 9; j++) Br[j] = bval[j] ? W[boff[j] + k0 + BK] : 0.0f;
        }
#pragma unroll
        for (int kk = 0; kk < BK; kk++) {
            // A: 8 rows = 2x float4 (rows ty*8 .. ty*8+7), pairs feed FMA2 directly
            float4 a0 = AsV[kk * (ASTR / 4) + aV];
            float4 a1 = AsV[kk * (ASTR / 4) + aV + 1];
            unsigned long long a2[4];
            a2[0] = pack2(a0.x, a0.y);
            a2[1] = pack2(a0.z, a0.w);
            a2[2] = pack2(a1.x, a1.y);
            a2[3] = pack2(a1.z, a1.w);
            // B: 7 natural floats via 2x LDS.128; duplicate in registers
            float4 w0 = BsV[kk * (BSTR / 4) + bV];
            float4 w1 = BsV[kk * (BSTR / 4) + bV + 1];
            unsigned long long b2[TN];
            b2[0] = pack2(w0.x, w0.x);
            b2[1] = pack2(w0.y, w0.y);
            b2[2] = pack2(w0.z, w0.z);
            b2[3] = pack2(w0.w, w0.w);
            b2[4] = pack2(w1.x, w1.x);
            b2[5] = pack2(w1.y, w1.y);
            b2[6] = pack2(w1.z, w1.z);
#pragma unroll
            for (int p = 0; p < 4; p++)
#pragma unroll
                for (int j = 0; j < TN; j++) fma2(acc2[p][j], a2[p], b2[j]);
        }
        __syncthreads();
        if (has_next) {
#pragma unroll
            for (int j = 0; j < 10; j++) As[sA[j]] = Ar[j];
#pragma unroll
            for (int j = 0; j < 9; j++) if (bst[j]) Bs[sB[j]] = Br[j];
            __syncthreads();
        }
    }

    // ---- unpack accumulators: row i = ty*8 + 2p + h ----
    float acc[8][TN];
#pragma unroll
    for (int p = 0; p < 4; p++)
#pragma unroll
        for (int j = 0; j < TN; j++) {
            float2 v = *reinterpret_cast<float2*>(&acc2[p][j]);
            acc[2 * p][j] = v.x;
            acc[2 * p + 1][j] = v.y;
        }

    float bj[TN];
#pragma unroll
    for (int j = 0; j < TN; j++) {
        int gcol = col0 + tx * TN + j;
        bj[j] = (gcol < N) ? bias[gcol] : 0.0f;
    }

    if (MODE == 2) {
        // segmented pooling: compact rows are sample-sorted -> merge equal-s rows
        float accum[TN];
#pragma unroll
        for (int j = 0; j < TN; j++) accum[j] = 0.0f;
        int curS = -1;
#pragma unroll
        for (int i = 0; i < 8; i++) {
            int grow = row0 + ty * 8 + i;
            if (grow < nrows) {
                int s = g_rowmap[grow] >> 5;   // M_=32
                if (s != curS && curS >= 0) {
#pragma unroll
                    for (int j = 0; j < TN; j++) {
                        int gcol = col0 + tx * TN + j;
                        if (gcol < N)
                            atomicAdd(&g_pooled[(size_t)curS * D_ + gcol], accum[j]);
                    }
#pragma unroll
                    for (int j = 0; j < TN; j++) accum[j] = 0.0f;
                }
                curS = s;
#pragma unroll
                for (int j = 0; j < TN; j++)
                    accum[j] += fmaxf(acc[i][j] + bj[j], 0.0f);
            }
        }
        if (curS >= 0) {
#pragma unroll
            for (int j = 0; j < TN; j++) {
                int gcol = col0 + tx * TN + j;
                if (gcol < N)
                    atomicAdd(&g_pooled[(size_t)curS * D_ + gcol], accum[j]);
            }
        }
    } else {
#pragma unroll
        for (int i = 0; i < 8; i++) {
            int grow = row0 + ty * 8 + i;
            if (grow >= nrows) continue;
#pragma unroll
            for (int j = 0; j < TN; j++) {
                int gcol = col0 + tx * TN + j;
                if (gcol >= N) continue;
                float v = acc[i][j] + bj[j];
                Op[(size_t)grow * N + gcol] = fmaxf(v, 0.0f);
            }
        }
    }
}

// ---------------------------------------------------------------------------------
extern "C" void kernel_launch(void* const* d_in, const int* in_sizes, int n_in,
                              void* d_out, int out_size) {
    (void)in_sizes; (void)n_in; (void)out_size;
    const float* all_x     = (const float*)d_in[0];
    const int*   numInputs = (const int*)  d_in[1];
    const float* W1 = (const float*)d_in[2];
    const float* b1 = (const float*)d_in[3];
    const float* W2 = (const float*)d_in[4];
    const float* b2 = (const float*)d_in[5];
    const float* W3 = (const float*)d_in[6];
    const float* b3 = (const float*)d_in[7];
    const float* W4 = (const float*)d_in[8];
    const float* b4 = (const float*)d_in[9];
    float* out = (float*)d_out;

    setup_kernel<<<1, 256>>>(numInputs);
    zero_pooled_kernel<<<(S_ * D_ + 255) / 256, 256>>>();

    // layer 1: H1 = relu(X_active @ W1^T + b1)   [nact, 420]
    gemm_kernel<1, D_><<<dim3((S_ * M_ + 127) / 128, (D_ + 111) / 112), 256>>>(
        all_x, W1, b1, nullptr, D_);
    // layer 2 + ragged sum-pool (atomic into g_pooled)
    gemm_kernel<2, D_><<<dim3((S_ * M_ + 127) / 128, (D_ + 111) / 112), 256>>>(
        nullptr, W2, b2, nullptr, D_);
    // layer 3: Y = relu((pooled/n) @ W3^T + b3)  [S, 840]
    gemm_kernel<3, D_><<<dim3(S_ / 128, (H_ + 111) / 112), 256>>>(
        nullptr, W3, b3, nullptr, H_);
    // layer 4: out = relu(Y @ W4^T + b4)         [S, 420]
    gemm_kernel<4, H_><<<dim3(S_ / 128, (D_ + 111) / 112), 256>>>(
        nullptr, W4, b4, out, D_);
}

// round 5
// speedup vs baseline: 2.9394x; 2.5498x over previous
#include <cuda_runtime.h>
#include <cstdint>

#define S_ 4096
#define M_ 32
#define D_ 420
#define H_ 840

// ---------------- scratch (static device globals; no allocations) ----------------
__device__ int   g_rowmap[S_ * M_];              // compact row -> s*32+m
__device__ int   g_nact;                         // number of active rows
__device__ float g_invN[S_];                     // 1/numInputs[s]
__device__ float g_H1[(size_t)S_ * M_ * D_];     // layer-1 output, compact rows
__device__ float g_pooled[(size_t)S_ * D_];      // ragged-mean numerator (atomic)
__device__ float g_Y[(size_t)S_ * H_];           // layer-3 output

__device__ __forceinline__ uint32_t f2tf32(float v) {
    uint32_t u;
    asm("cvt.rna.tf32.f32 %0, %1;" : "=r"(u) : "f"(v));
    return u;
}
__device__ __forceinline__ void mma_m16n8k8(float& d0, float& d1, float& d2, float& d3,
                                            uint32_t a0, uint32_t a1, uint32_t a2,
                                            uint32_t a3, uint32_t b0, uint32_t b1) {
    asm volatile(
        "mma.sync.aligned.m16n8k8.row.col.f32.tf32.tf32.f32 "
        "{%0,%1,%2,%3}, {%4,%5,%6,%7}, {%8,%9}, {%0,%1,%2,%3};"
        : "+f"(d0), "+f"(d1), "+f"(d2), "+f"(d3)
        : "r"(a0), "r"(a1), "r"(a2), "r"(a3), "r"(b0), "r"(b1));
}
__device__ __forceinline__ uint32_t fu(float v) { return __float_as_uint(v); }

// ---------------- setup: prefix-scan numInputs, build compact row map -------------
__global__ void setup_kernel(const int* __restrict__ numInputs) {
    __shared__ int s_warp[8];
    __shared__ int s_woff[8];
    int t = threadIdx.x;
    int base = t * 16;
    int local[16];
    int run = 0;
#pragma unroll
    for (int j = 0; j < 16; j++) { local[j] = run; run += numInputs[base + j]; }
    int lane = t & 31, warp = t >> 5;
    int inc = run;
#pragma unroll
    for (int o = 1; o < 32; o <<= 1) {
        int v = __shfl_up_sync(0xffffffffu, inc, o);
        if (lane >= o) inc += v;
    }
    if (lane == 31) s_warp[warp] = inc;
    __syncthreads();
    if (t == 0) {
        int r = 0;
        for (int w = 0; w < 8; w++) { s_woff[w] = r; r += s_warp[w]; }
        g_nact = r;
    }
    __syncthreads();
    int thrOff = s_woff[warp] + (inc - run);
    for (int j = 0; j < 16; j++) {
        int s = base + j;
        int n = numInputs[s];
        g_invN[s] = 1.0f / (float)n;
        int off = thrOff + local[j];
        for (int m = 0; m < n; m++) g_rowmap[off + m] = s * M_ + m;
    }
}

__global__ void zero_pooled_kernel() {
    int i = blockIdx.x * blockDim.x + threadIdx.x;
    if (i < S_ * D_) g_pooled[i] = 0.0f;
}

// ---------------- mma.sync tf32 GEMM:  Out = relu(A @ W^T + b) --------------------
// MODE 1: A = all_x gathered via rowmap -> g_H1 (compact), rows = g_nact
// MODE 2: A = g_H1, epilogue = smem stage + segmented reduce + atomicAdd g_pooled
// MODE 3: A = g_pooled * invN[row] -> g_Y, rows = S
// MODE 4: A = g_Y -> d_out, rows = S
//
// BM=128, BN=112, BK=32. 8 warps (4 M x 2 N), warp tile 32x56 = 2 m16 x 7 n8.
// Smem strides 36 floats (== 4 mod 32): fragment LDS bank = 4*grp + qid, all 32
// distinct -> conflict-free. fp32 -> tf32 cvt once at staging. Register-prefetch
// double buffering for global loads.
template <int MODE, int K>
__global__ void __launch_bounds__(256)
gemm_mma(const float* __restrict__ Aext, const float* __restrict__ W,
         const float* __restrict__ bias, float* __restrict__ OutExt) {
    constexpr int BM = 128, BK = 32;
    constexpr int KT = (K + BK - 1) / BK;
    constexpr int NW  = (MODE == 3) ? H_ : D_;
    constexpr int AST = (MODE == 4) ? H_ : D_;
    constexpr int OST = (MODE == 3) ? H_ : D_;
    constexpr int ASTR = 36, BSTR = 36;
    constexpr int EPSTR = 116;

    extern __shared__ float smem[];
    float* As = smem;                    // 128*36 floats
    float* Bs = smem + BM * ASTR;        // 112*36 floats

    const int nrows = (MODE <= 2) ? g_nact : S_;
    const int row0 = blockIdx.x * BM;
    if (row0 >= nrows) return;
    const int yoff = blockIdx.y * 112;

    const float* Ap = (MODE == 1) ? Aext
                    : (MODE == 2) ? g_H1
                    : (MODE == 3) ? g_pooled
                                  : g_Y;
    float* Op = (MODE == 1) ? g_H1 : (MODE == 3) ? g_Y : OutExt;

    const int t = threadIdx.x, lane = t & 31, wid = t >> 5;
    const int warpM = wid & 3, warpN = wid >> 2;
    const int grp = lane >> 2, qid = lane & 3;

    // ---- global load descriptors (fixed per thread) ----
    const int q8 = t & 7;                 // float4 index within 32-float k-row
    const int rsub = t >> 3;              // 0..31
    const float* aptr[4]; bool aval[4]; float ascl[4]; int sA[4];
#pragma unroll
    for (int i = 0; i < 4; i++) {
        int m = i * 32 + rsub;
        int grow = row0 + m;
        aval[i] = grow < nrows;
        int arow = aval[i] ? ((MODE == 1) ? g_rowmap[grow] : grow) : 0;
        aptr[i] = Ap + (size_t)arow * AST;
        ascl[i] = (MODE == 3 && aval[i]) ? g_invN[grow] : 1.0f;
        sA[i] = m * ASTR + q8 * 4;
    }
    const float* bptr[4]; bool bval[4]; int sB[4];
#pragma unroll
    for (int i = 0; i < 4; i++) {
        int idx = i * 256 + t;
        int n = idx >> 3;                  // 0..111 (idx < 896)
        int gcol = yoff + n;
        bval[i] = (idx < 896) && (gcol < NW);
        bptr[i] = W + (size_t)(bval[i] ? gcol : 0) * K;
        sB[i] = n * BSTR + q8 * 4;
    }

    float4 Ar[4], Br[4];
    auto load_tile = [&](int kt) {
        int kc = kt * BK + q8 * 4;
        bool kok = kc < K;
#pragma unroll
        for (int i = 0; i < 4; i++) {
            float4 v = make_float4(0.f, 0.f, 0.f, 0.f);
            if (aval[i] && kok) v = *(const float4*)(aptr[i] + kc);
            if (MODE == 3) { v.x *= ascl[i]; v.y *= ascl[i]; v.z *= ascl[i]; v.w *= ascl[i]; }
            Ar[i] = v;
        }
#pragma unroll
        for (int i = 0; i < 4; i++) {
            float4 v = make_float4(0.f, 0.f, 0.f, 0.f);
            if (bval[i] && kok) v = *(const float4*)(bptr[i] + kc);
            Br[i] = v;
        }
    };
    auto store_tile = [&]() {
#pragma unroll
        for (int i = 0; i < 4; i++) {
            uint4 u = make_uint4(f2tf32(Ar[i].x), f2tf32(Ar[i].y),
                                 f2tf32(Ar[i].z), f2tf32(Ar[i].w));
            *(uint4*)(As + sA[i]) = u;
        }
#pragma unroll
        for (int i = 0; i < 4; i++) {
            if (i < 3 || t < 128) {
                uint4 u = make_uint4(f2tf32(Br[i].x), f2tf32(Br[i].y),
                                     f2tf32(Br[i].z), f2tf32(Br[i].w));
                *(uint4*)(Bs + sB[i]) = u;
            }
        }
    };

    float acc[2][7][4];
#pragma unroll
    for (int mt = 0; mt < 2; mt++)
#pragma unroll
        for (int nt = 0; nt < 7; nt++)
#pragma unroll
            for (int c = 0; c < 4; c++) acc[mt][nt][c] = 0.0f;

    const float* AsW = As + (warpM * 32 + grp) * ASTR;
    const float* BsW = Bs + (warpN * 56 + grp) * BSTR;

    load_tile(0);
    store_tile();
    __syncthreads();

    for (int kt = 0; kt < KT; kt++) {
        if (kt + 1 < KT) load_tile(kt + 1);
#pragma unroll
        for (int k8 = 0; k8 < 4; k8++) {
            const int k0 = k8 * 8;
            uint32_t bf[7][2];
#pragma unroll
            for (int nt = 0; nt < 7; nt++) {
                bf[nt][0] = fu(BsW[nt * 8 * BSTR + k0 + qid]);
                bf[nt][1] = fu(BsW[nt * 8 * BSTR + k0 + qid + 4]);
            }
#pragma unroll
            for (int mt = 0; mt < 2; mt++) {
                const float* a = AsW + mt * 16 * ASTR + k0;
                uint32_t a0 = fu(a[qid]);
                uint32_t a1 = fu(a[8 * ASTR + qid]);
                uint32_t a2 = fu(a[qid + 4]);
                uint32_t a3 = fu(a[8 * ASTR + qid + 4]);
#pragma unroll
                for (int nt = 0; nt < 7; nt++)
                    mma_m16n8k8(acc[mt][nt][0], acc[mt][nt][1],
                                acc[mt][nt][2], acc[mt][nt][3],
                                a0, a1, a2, a3, bf[nt][0], bf[nt][1]);
            }
        }
        __syncthreads();
        if (kt + 1 < KT) {
            store_tile();
            __syncthreads();
        }
    }

    // ---- epilogue ----
    // thread (mt,nt) owns rows warpM*32+mt*16+grp (+8), cols warpN*56+nt*8+2*qid (+1)
    if (MODE == 2) {
        // stage relu(acc+bias) into smem, then segmented reduce over sample runs
        float* ep = smem;                                   // 128 x 116
        int* sample    = (int*)(smem + 14848);              // 128
        int* segstart  = sample + 128;                      // 129
        int* segsample = segstart + 129;                    // 128
        int* pnseg     = segsample + 128;
#pragma unroll
        for (int mt = 0; mt < 2; mt++) {
            int r = warpM * 32 + mt * 16 + grp;
#pragma unroll
            for (int nt = 0; nt < 7; nt++) {
                int c = warpN * 56 + nt * 8 + 2 * qid;
                int gcol = yoff + c;
                float b0 = (gcol < NW) ? bias[gcol] : 0.0f;
                float b1 = (gcol + 1 < NW) ? bias[gcol + 1] : 0.0f;
                *(float2*)(ep + r * EPSTR + c) =
                    make_float2(fmaxf(acc[mt][nt][0] + b0, 0.0f),
                                fmaxf(acc[mt][nt][1] + b1, 0.0f));
                *(float2*)(ep + (r + 8) * EPSTR + c) =
                    make_float2(fmaxf(acc[mt][nt][2] + b0, 0.0f),
                                fmaxf(acc[mt][nt][3] + b1, 0.0f));
            }
        }
        if (t < 128) {
            int g = row0 + t;
            sample[t] = (g < nrows) ? (g_rowmap[g] >> 5) : -1;
        }
        __syncthreads();
        if (t == 0) {
            int lim = nrows - row0; if (lim > 128) lim = 128;
            int ns = 0, cur = -2;
            for (int r = 0; r < lim; r++) {
                int s = sample[r];
                if (s != cur) { segstart[ns] = r; segsample[ns] = s; ns++; cur = s; }
            }
            segstart[ns] = lim;
            *pnseg = ns;
        }
        __syncthreads();
        if (t < 224) {
            int c = t % 112, sset = t / 112;
            int gcol = yoff + c;
            if (gcol < D_) {
                int ns = *pnseg;
                for (int seg = sset; seg < ns; seg += 2) {
                    float s = 0.0f;
                    int e = segstart[seg + 1];
                    for (int r = segstart[seg]; r < e; r++) s += ep[r * EPSTR + c];
                    atomicAdd(&g_pooled[(size_t)segsample[seg] * D_ + gcol], s);
                }
            }
        }
    } else {
#pragma unroll
        for (int mt = 0; mt < 2; mt++) {
            int r = row0 + warpM * 32 + mt * 16 + grp;
#pragma unroll
            for (int nt = 0; nt < 7; nt++) {
                int gcol = yoff + warpN * 56 + nt * 8 + 2 * qid;
                if (gcol >= NW) continue;
                float b0 = bias[gcol];
                float b1 = bias[gcol + 1];
                if (r < nrows)
                    *(float2*)(Op + (size_t)r * OST + gcol) =
                        make_float2(fmaxf(acc[mt][nt][0] + b0, 0.0f),
                                    fmaxf(acc[mt][nt][1] + b1, 0.0f));
                if (r + 8 < nrows)
                    *(float2*)(Op + (size_t)(r + 8) * OST + gcol) =
                        make_float2(fmaxf(acc[mt][nt][2] + b0, 0.0f),
                                    fmaxf(acc[mt][nt][3] + b1, 0.0f));
            }
        }
    }
}

// ---------------------------------------------------------------------------------
extern "C" void kernel_launch(void* const* d_in, const int* in_sizes, int n_in,
                              void* d_out, int out_size) {
    (void)in_sizes; (void)n_in; (void)out_size;
    const float* all_x     = (const float*)d_in[0];
    const int*   numInputs = (const int*)  d_in[1];
    const float* W1 = (const float*)d_in[2];
    const float* b1 = (const float*)d_in[3];
    const float* W2 = (const float*)d_in[4];
    const float* b2 = (const float*)d_in[5];
    const float* W3 = (const float*)d_in[6];
    const float* b3 = (const float*)d_in[7];
    const float* W4 = (const float*)d_in[8];
    const float* b4 = (const float*)d_in[9];
    float* out = (float*)d_out;

    const int SMEM_GEMM = (128 * 36 + 112 * 36) * 4;    // 34560
    const int SMEM_M2   = 61440;                        // stage + seg arrays
    static bool attr_done = false;
    if (!attr_done) {
        cudaFuncSetAttribute(gemm_mma<1, D_>, cudaFuncAttributeMaxDynamicSharedMemorySize, SMEM_GEMM);
        cudaFuncSetAttribute(gemm_mma<2, D_>, cudaFuncAttributeMaxDynamicSharedMemorySize, SMEM_M2);
        cudaFuncSetAttribute(gemm_mma<3, D_>, cudaFuncAttributeMaxDynamicSharedMemorySize, SMEM_GEMM);
        cudaFuncSetAttribute(gemm_mma<4, H_>, cudaFuncAttributeMaxDynamicSharedMemorySize, SMEM_GEMM);
        attr_done = true;
    }

    setup_kernel<<<1, 256>>>(numInputs);
    zero_pooled_kernel<<<(S_ * D_ + 255) / 256, 256>>>();

    // layer 1: H1 = relu(X_active @ W1^T + b1)     [nact, 420]
    gemm_mma<1, D_><<<dim3(1024, 4), 256, SMEM_GEMM>>>(all_x, W1, b1, nullptr);
    // layer 2 + ragged sum-pool into g_pooled      [nact, 420] -> [S, 420]
    gemm_mma<2, D_><<<dim3(1024, 4), 256, SMEM_M2>>>(nullptr, W2, b2, nullptr);
    // layer 3: Y = relu((pooled/n) @ W3^T + b3)    [S, 840]
    gemm_mma<3, D_><<<dim3(32, 8), 256, SMEM_GEMM>>>(nullptr, W3, b3, nullptr);
    // layer 4: out = relu(Y @ W4^T + b4)           [S, 420]
    gemm_mma<4, H_><<<dim3(32, 4), 256, SMEM_GEMM>>>(nullptr, W4, b4, out);
}

// round 6
// speedup vs baseline: 3.8124x; 1.2970x over previous
#include <cuda_runtime.h>
#include <cstdint>

#define S_ 4096
#define M_ 32
#define D_ 420
#define H_ 840

// ---------------- scratch (static device globals; no allocations) ----------------
__device__ int   g_rowmap[S_ * M_];              // compact row -> s*32+m
__device__ int   g_nact;                         // number of active rows
__device__ float g_invN[S_];                     // 1/numInputs[s]
__device__ float g_H1[(size_t)S_ * M_ * D_];     // layer-1 output, compact rows
__device__ float g_pooled[(size_t)S_ * D_];      // ragged-mean numerator (atomic)
__device__ float g_Y[(size_t)S_ * H_];           // layer-3 output

__device__ __forceinline__ uint32_t f2tf32(float v) {
    uint32_t u;
    asm("cvt.rna.tf32.f32 %0, %1;" : "=r"(u) : "f"(v));
    return u;
}
__device__ __forceinline__ void mma_m16n8k8(float& d0, float& d1, float& d2, float& d3,
                                            uint32_t a0, uint32_t a1, uint32_t a2,
                                            uint32_t a3, uint32_t b0, uint32_t b1) {
    asm volatile(
        "mma.sync.aligned.m16n8k8.row.col.f32.tf32.tf32.f32 "
        "{%0,%1,%2,%3}, {%4,%5,%6,%7}, {%8,%9}, {%0,%1,%2,%3};"
        : "+f"(d0), "+f"(d1), "+f"(d2), "+f"(d3)
        : "r"(a0), "r"(a1), "r"(a2), "r"(a3), "r"(b0), "r"(b1));
}
__device__ __forceinline__ uint32_t smem_u32(const void* p) {
    uint32_t a;
    asm("{ .reg .u64 t; cvta.to.shared.u64 t, %1; cvt.u32.u64 %0, t; }"
        : "=r"(a) : "l"(p));
    return a;
}
__device__ __forceinline__ void cp16(uint32_t dst, const void* src, uint32_t srcsz) {
    asm volatile("cp.async.cg.shared.global [%0], [%1], 16, %2;"
                 :: "r"(dst), "l"(src), "r"(srcsz) : "memory");
}
#define CP_COMMIT() asm volatile("cp.async.commit_group;" ::: "memory")
#define CP_WAIT(n)  asm volatile("cp.async.wait_group %0;" :: "n"(n) : "memory")

// ---------------- setup: prefix-scan numInputs, build compact row map -------------
__global__ void setup_kernel(const int* __restrict__ numInputs) {
    __shared__ int s_warp[8];
    __shared__ int s_woff[8];
    int t = threadIdx.x;
    int base = t * 16;
    int local[16];
    int run = 0;
#pragma unroll
    for (int j = 0; j < 16; j++) { local[j] = run; run += numInputs[base + j]; }
    int lane = t & 31, warp = t >> 5;
    int inc = run;
#pragma unroll
    for (int o = 1; o < 32; o <<= 1) {
        int v = __shfl_up_sync(0xffffffffu, inc, o);
        if (lane >= o) inc += v;
    }
    if (lane == 31) s_warp[warp] = inc;
    __syncthreads();
    if (t == 0) {
        int r = 0;
        for (int w = 0; w < 8; w++) { s_woff[w] = r; r += s_warp[w]; }
        g_nact = r;
    }
    __syncthreads();
    int thrOff = s_woff[warp] + (inc - run);
    for (int j = 0; j < 16; j++) {
        int s = base + j;
        int n = numInputs[s];
        g_invN[s] = 1.0f / (float)n;
        int off = thrOff + local[j];
        for (int m = 0; m < n; m++) g_rowmap[off + m] = s * M_ + m;
    }
}

__global__ void zero_pooled_kernel() {
    int i = blockIdx.x * blockDim.x + threadIdx.x;
    if (i < S_ * D_) g_pooled[i] = 0.0f;
}

// ---------------- mma.sync tf32 GEMM with cp.async pipeline -----------------------
// MODE 1: A = all_x gathered via rowmap -> g_H1 (compact), rows = g_nact
// MODE 2: A = g_H1, epilogue = smem stage + segmented reduce + atomicAdd g_pooled
// MODE 3: A = g_pooled -> g_Y (1/n folded into epilogue), rows = S
// MODE 4: A = g_Y -> d_out, rows = S
//
// CTA = 128 threads (4 warps, 2Mx2N), BM=64, BN=112, BK=32, warp tile 32x56.
// 2-stage cp.async smem pipeline, raw fp32 in smem, tf32 cvt at fragment load.
// Strides 36 floats (== 4 mod 32) -> conflict-free fragment LDS.
template <int MODE, int K>
__global__ void __launch_bounds__(128, 4)
gemm_cp(const float* __restrict__ Aext, const float* __restrict__ W,
        const float* __restrict__ bias, float* __restrict__ OutExt) {
    constexpr int BM = 64, BK = 32;
    constexpr int KT = (K + BK - 1) / BK;
    constexpr int NW  = (MODE == 3) ? H_ : D_;
    constexpr int AST = (MODE == 4) ? H_ : D_;
    constexpr int OST = (MODE == 3) ? H_ : D_;
    constexpr int ASTR = 36, BSTR = 36;
    constexpr int ATILE = BM * ASTR;          // 2304 floats
    constexpr int BTILE = 112 * BSTR;         // 4032 floats
    constexpr int STAGE = ATILE + BTILE;      // 6336 floats
    constexpr int EPSTR = 116;

    extern __shared__ float smem[];
    const uint32_t sb = smem_u32(smem);

    const int nrows = (MODE <= 2) ? g_nact : S_;
    const int row0 = blockIdx.x * BM;
    if (row0 >= nrows) return;
    const int yoff = blockIdx.y * 112;

    const float* Ap = (MODE == 1) ? Aext
                    : (MODE == 2) ? g_H1
                    : (MODE == 3) ? g_pooled
                                  : g_Y;
    float* Op = (MODE == 1) ? g_H1 : (MODE == 3) ? g_Y : OutExt;

    const int t = threadIdx.x, lane = t & 31, wid = t >> 5;
    const int warpM = wid & 1, warpN = wid >> 1;
    const int grp = lane >> 2, qid = lane & 3;

    // ---- copy descriptors: q8 = t&7 constant (128 % 8 == 0) ----
    const int q8e = (t & 7) * 4;              // k element offset within 32-float row
    const int rsub = t >> 3;                  // 0..15
    const float* asrc[4]; bool avalid[4]; uint32_t adst[4];
#pragma unroll
    for (int i = 0; i < 4; i++) {
        int m = i * 16 + rsub;
        int grow = row0 + m;
        avalid[i] = grow < nrows;
        int arow = avalid[i] ? ((MODE == 1) ? g_rowmap[grow] : grow) : 0;
        asrc[i] = Ap + (size_t)arow * AST + q8e;
        adst[i] = (uint32_t)(m * ASTR + q8e) * 4u;
    }
    const float* bsrc[7]; bool bvalid[7]; uint32_t bdst[7];
#pragma unroll
    for (int i = 0; i < 7; i++) {
        int n = i * 16 + rsub;
        int gcol = yoff + n;
        bvalid[i] = gcol < NW;
        bsrc[i] = W + (size_t)(bvalid[i] ? gcol : 0) * K + q8e;
        bdst[i] = (uint32_t)(ATILE + n * BSTR + q8e) * 4u;
    }

    auto issue = [&](int kt) {
        const int kc = kt * BK + q8e;
        const uint32_t szk = (kc < K) ? 16u : 0u;
        const uint32_t sbase = sb + (uint32_t)(kt & 1) * (STAGE * 4u);
#pragma unroll
        for (int i = 0; i < 4; i++)
            cp16(sbase + adst[i], asrc[i] + kt * BK, avalid[i] ? szk : 0u);
#pragma unroll
        for (int i = 0; i < 7; i++)
            cp16(sbase + bdst[i], bsrc[i] + kt * BK, bvalid[i] ? szk : 0u);
        CP_COMMIT();
    };

    float acc[2][7][4];
#pragma unroll
    for (int mt = 0; mt < 2; mt++)
#pragma unroll
        for (int nt = 0; nt < 7; nt++)
#pragma unroll
            for (int c = 0; c < 4; c++) acc[mt][nt][c] = 0.0f;

    issue(0);
    for (int kt = 0; kt < KT; kt++) {
        if (kt + 1 < KT) { issue(kt + 1); CP_WAIT(1); }
        else             { CP_WAIT(0); }
        __syncthreads();
        const float* AsW = smem + (kt & 1) * STAGE + (warpM * 32 + grp) * ASTR;
        const float* BsW = smem + (kt & 1) * STAGE + ATILE + (warpN * 56 + grp) * BSTR;
#pragma unroll
        for (int k8 = 0; k8 < 4; k8++) {
            const int k0 = k8 * 8;
            uint32_t bf[7][2];
#pragma unroll
            for (int nt = 0; nt < 7; nt++) {
                bf[nt][0] = f2tf32(BsW[nt * 8 * BSTR + k0 + qid]);
                bf[nt][1] = f2tf32(BsW[nt * 8 * BSTR + k0 + qid + 4]);
            }
#pragma unroll
            for (int mt = 0; mt < 2; mt++) {
                const float* a = AsW + mt * 16 * ASTR + k0;
                uint32_t a0 = f2tf32(a[qid]);
                uint32_t a1 = f2tf32(a[8 * ASTR + qid]);
                uint32_t a2 = f2tf32(a[qid + 4]);
                uint32_t a3 = f2tf32(a[8 * ASTR + qid + 4]);
#pragma unroll
                for (int nt = 0; nt < 7; nt++)
                    mma_m16n8k8(acc[mt][nt][0], acc[mt][nt][1],
                                acc[mt][nt][2], acc[mt][nt][3],
                                a0, a1, a2, a3, bf[nt][0], bf[nt][1]);
            }
        }
        __syncthreads();
    }

    // ---- MODE 3: fold 1/n scaling into epilogue ----
    float sc0[2], sc1[2];
#pragma unroll
    for (int mt = 0; mt < 2; mt++) {
        int r = row0 + warpM * 32 + mt * 16 + grp;
        sc0[mt] = (MODE == 3 && r < S_) ? g_invN[r] : 1.0f;
        sc1[mt] = (MODE == 3 && r + 8 < S_) ? g_invN[r + 8] : 1.0f;
    }

    // ---- epilogue ----
    if (MODE == 2) {
        float* ep = smem;                          // 64 x 116 floats
        int* sample    = (int*)(smem + BM * EPSTR);
        int* segstart  = sample + BM;              // BM+1
        int* segsample = segstart + BM + 1;        // BM
        int* pnseg     = segsample + BM;
#pragma unroll
        for (int mt = 0; mt < 2; mt++) {
            int r = warpM * 32 + mt * 16 + grp;
#pragma unroll
            for (int nt = 0; nt < 7; nt++) {
                int c = warpN * 56 + nt * 8 + 2 * qid;
                int gcol = yoff + c;
                float b0 = (gcol < NW) ? bias[gcol] : 0.0f;
                float b1 = (gcol + 1 < NW) ? bias[gcol + 1] : 0.0f;
                *(float2*)(ep + r * EPSTR + c) =
                    make_float2(fmaxf(acc[mt][nt][0] + b0, 0.0f),
                                fmaxf(acc[mt][nt][1] + b1, 0.0f));
                *(float2*)(ep + (r + 8) * EPSTR + c) =
                    make_float2(fmaxf(acc[mt][nt][2] + b0, 0.0f),
                                fmaxf(acc[mt][nt][3] + b1, 0.0f));
            }
        }
        if (t < BM) {
            int g = row0 + t;
            sample[t] = (g < nrows) ? (g_rowmap[g] >> 5) : -1;
        }
        __syncthreads();
        if (t == 0) {
            int lim = nrows - row0; if (lim > BM) lim = BM;
            int ns = 0, cur = -2;
            for (int r = 0; r < lim; r++) {
                int s = sample[r];
                if (s != cur) { segstart[ns] = r; segsample[ns] = s; ns++; cur = s; }
            }
            segstart[ns] = lim;
            *pnseg = ns;
        }
        __syncthreads();
        if (t < 112) {
            int gcol = yoff + t;
            if (gcol < D_) {
                int ns = *pnseg;
                for (int seg = 0; seg < ns; seg++) {
                    float s = 0.0f;
                    int e = segstart[seg + 1];
                    for (int r = segstart[seg]; r < e; r++) s += ep[r * EPSTR + t];
                    atomicAdd(&g_pooled[(size_t)segsample[seg] * D_ + gcol], s);
                }
            }
        }
    } else {
#pragma unroll
        for (int mt = 0; mt < 2; mt++) {
            int r = row0 + warpM * 32 + mt * 16 + grp;
#pragma unroll
            for (int nt = 0; nt < 7; nt++) {
                int gcol = yoff + warpN * 56 + nt * 8 + 2 * qid;
                if (gcol >= NW) continue;
                float b0 = bias[gcol];
                float b1 = bias[gcol + 1];
                if (r < nrows)
                    *(float2*)(Op + (size_t)r * OST + gcol) =
                        make_float2(fmaxf(acc[mt][nt][0] * sc0[mt] + b0, 0.0f),
                                    fmaxf(acc[mt][nt][1] * sc0[mt] + b1, 0.0f));
                if (r + 8 < nrows)
                    *(float2*)(Op + (size_t)(r + 8) * OST + gcol) =
                        make_float2(fmaxf(acc[mt][nt][2] * sc1[mt] + b0, 0.0f),
                                    fmaxf(acc[mt][nt][3] * sc1[mt] + b1, 0.0f));
            }
        }
    }
}

// ---------------------------------------------------------------------------------
extern "C" void kernel_launch(void* const* d_in, const int* in_sizes, int n_in,
                              void* d_out, int out_size) {
    (void)in_sizes; (void)n_in; (void)out_size;
    const float* all_x     = (const float*)d_in[0];
    const int*   numInputs = (const int*)  d_in[1];
    const float* W1 = (const float*)d_in[2];
    const float* b1 = (const float*)d_in[3];
    const float* W2 = (const float*)d_in[4];
    const float* b2 = (const float*)d_in[5];
    const float* W3 = (const float*)d_in[6];
    const float* b3 = (const float*)d_in[7];
    const float* W4 = (const float*)d_in[8];
    const float* b4 = (const float*)d_in[9];
    float* out = (float*)d_out;

    const int SMEM = 2 * (64 * 36 + 112 * 36) * 4;   // 50688 bytes
    static bool attr_done = false;
    if (!attr_done) {
        cudaFuncSetAttribute(gemm_cp<1, D_>, cudaFuncAttributeMaxDynamicSharedMemorySize, SMEM);
        cudaFuncSetAttribute(gemm_cp<2, D_>, cudaFuncAttributeMaxDynamicSharedMemorySize, SMEM);
        cudaFuncSetAttribute(gemm_cp<3, D_>, cudaFuncAttributeMaxDynamicSharedMemorySize, SMEM);
        cudaFuncSetAttribute(gemm_cp<4, H_>, cudaFuncAttributeMaxDynamicSharedMemorySize, SMEM);
        attr_done = true;
    }

    setup_kernel<<<1, 256>>>(numInputs);
    zero_pooled_kernel<<<(S_ * D_ + 255) / 256, 256>>>();

    // layer 1: H1 = relu(X_active @ W1^T + b1)     [nact, 420]
    gemm_cp<1, D_><<<dim3((S_ * M_ + 63) / 64, 4), 128, SMEM>>>(all_x, W1, b1, nullptr);
    // layer 2 + ragged sum-pool into g_pooled      [nact, 420] -> [S, 420]
    gemm_cp<2, D_><<<dim3((S_ * M_ + 63) / 64, 4), 128, SMEM>>>(nullptr, W2, b2, nullptr);
    // layer 3: Y = relu((pooled @ W3^T)/n + b3)    [S, 840]
    gemm_cp<3, D_><<<dim3(S_ / 64, 8), 128, SMEM>>>(nullptr, W3, b3, nullptr);
    // layer 4: out = relu(Y @ W4^T + b4)           [S, 420]
    gemm_cp<4, H_><<<dim3(S_ / 64, 4), 128, SMEM>>>(nullptr, W4, b4, out);
}

// round 7
// speedup vs baseline: 3.8155x; 1.0008x over previous
#include <cuda_runtime.h>
#include <cstdint>

#define S_ 4096
#define M_ 32
#define D_ 420
#define H_ 840

// ---------------- scratch (static device globals; no allocations) ----------------
__device__ int   g_rowmap[S_ * M_];              // compact row -> s*32+m
__device__ int   g_nact;                         // number of active rows
__device__ float g_invN[S_];                     // 1/numInputs[s]
__device__ float g_H1[(size_t)S_ * M_ * D_];     // layer-1 output (tf32-rounded)
__device__ float g_pooled[(size_t)S_ * D_];      // ragged-mean numerator (atomic)
__device__ float g_Y[(size_t)S_ * H_];           // layer-3 output (tf32-rounded)
__device__ float g_W1r[D_ * D_];                 // tf32-rounded weights
__device__ float g_W2r[D_ * D_];
__device__ float g_W3r[H_ * D_];
__device__ float g_W4r[D_ * H_];

__device__ __forceinline__ uint32_t f2tf32(float v) {
    uint32_t u;
    asm("cvt.rna.tf32.f32 %0, %1;" : "=r"(u) : "f"(v));
    return u;
}
__device__ __forceinline__ float roundtf(float v) { return __uint_as_float(f2tf32(v)); }
__device__ __forceinline__ uint32_t fu(float v) { return __float_as_uint(v); }
__device__ __forceinline__ void mma_m16n8k8(float& d0, float& d1, float& d2, float& d3,
                                            uint32_t a0, uint32_t a1, uint32_t a2,
                                            uint32_t a3, uint32_t b0, uint32_t b1) {
    asm volatile(
        "mma.sync.aligned.m16n8k8.row.col.f32.tf32.tf32.f32 "
        "{%0,%1,%2,%3}, {%4,%5,%6,%7}, {%8,%9}, {%0,%1,%2,%3};"
        : "+f"(d0), "+f"(d1), "+f"(d2), "+f"(d3)
        : "r"(a0), "r"(a1), "r"(a2), "r"(a3), "r"(b0), "r"(b1));
}
__device__ __forceinline__ uint32_t smem_u32(const void* p) {
    uint32_t a;
    asm("{ .reg .u64 t; cvta.to.shared.u64 t, %1; cvt.u32.u64 %0, t; }"
        : "=r"(a) : "l"(p));
    return a;
}
__device__ __forceinline__ void cp16(uint32_t dst, const void* src, uint32_t srcsz) {
    asm volatile("cp.async.cg.shared.global [%0], [%1], 16, %2;"
                 :: "r"(dst), "l"(src), "r"(srcsz) : "memory");
}
#define CP_COMMIT() asm volatile("cp.async.commit_group;" ::: "memory")
#define CP_WAIT(n)  asm volatile("cp.async.wait_group %0;" :: "n"(n) : "memory")

// ---------------- setup: prefix-scan numInputs, build compact row map -------------
__global__ void setup_kernel(const int* __restrict__ numInputs) {
    __shared__ int s_warp[8];
    __shared__ int s_woff[8];
    int t = threadIdx.x;
    int base = t * 16;
    int local[16];
    int run = 0;
#pragma unroll
    for (int j = 0; j < 16; j++) { local[j] = run; run += numInputs[base + j]; }
    int lane = t & 31, warp = t >> 5;
    int inc = run;
#pragma unroll
    for (int o = 1; o < 32; o <<= 1) {
        int v = __shfl_up_sync(0xffffffffu, inc, o);
        if (lane >= o) inc += v;
    }
    if (lane == 31) s_warp[warp] = inc;
    __syncthreads();
    if (t == 0) {
        int r = 0;
        for (int w = 0; w < 8; w++) { s_woff[w] = r; r += s_warp[w]; }
        g_nact = r;
    }
    __syncthreads();
    int thrOff = s_woff[warp] + (inc - run);
    for (int j = 0; j < 16; j++) {
        int s = base + j;
        int n = numInputs[s];
        g_invN[s] = 1.0f / (float)n;
        int off = thrOff + local[j];
        for (int m = 0; m < n; m++) g_rowmap[off + m] = s * M_ + m;
    }
}

__global__ void zero_pooled_kernel() {
    int i = blockIdx.x * blockDim.x + threadIdx.x;
    if (i < S_ * D_) g_pooled[i] = 0.0f;
}

// pre-round a weight matrix to tf32-representable floats (identity under later cvt)
template <int WHICH>
__global__ void round_w_kernel(const float* __restrict__ src, int n) {
    float* dst = (WHICH == 1) ? g_W1r : (WHICH == 2) ? g_W2r
               : (WHICH == 3) ? g_W3r : g_W4r;
    int i = blockIdx.x * blockDim.x + threadIdx.x;
    if (i < n) dst[i] = roundtf(src[i]);
}

// ---------------- mma.sync tf32 GEMM with cp.async pipeline -----------------------
// MODE 1: A = all_x (gather, cvt) -> g_H1 rounded, rows = g_nact
// MODE 2: A = g_H1 (pre-rounded, no cvt), epilogue = segmented reduce + atomicAdd
// MODE 3: A = g_pooled (cvt), 1/n in epilogue -> g_Y rounded, rows = S
// MODE 4: A = g_Y (pre-rounded, no cvt) -> d_out, rows = S
//
// CTA = 128 threads (4 warps, 2Mx2N), BM=64, BN=112, BK=32, warp tile 32x56.
// 2-stage cp.async pipeline; B always pre-rounded (g_W*r), so no B cvt ever.
template <int MODE, int K, bool CVTA>
__global__ void __launch_bounds__(128, 4)
gemm_cp(const float* __restrict__ Aext, const float* __restrict__ bias,
        float* __restrict__ OutExt) {
    constexpr int BM = 64, BK = 32;
    constexpr int KT = (K + BK - 1) / BK;
    constexpr int NW  = (MODE == 3) ? H_ : D_;
    constexpr int AST = (MODE == 4) ? H_ : D_;
    constexpr int OST = (MODE == 3) ? H_ : D_;
    constexpr int ASTR = 36, BSTR = 36;
    constexpr int ATILE = BM * ASTR;          // 2304 floats
    constexpr int BTILE = 112 * BSTR;         // 4032 floats
    constexpr int STAGE = ATILE + BTILE;      // 6336 floats
    constexpr int EPSTR = 116;

    extern __shared__ float smem[];
    const uint32_t sb = smem_u32(smem);

    const int nrows = (MODE <= 2) ? g_nact : S_;
    const int row0 = blockIdx.x * BM;
    if (row0 >= nrows) return;
    const int yoff = blockIdx.y * 112;

    const float* Ap = (MODE == 1) ? Aext
                    : (MODE == 2) ? g_H1
                    : (MODE == 3) ? g_pooled
                                  : g_Y;
    const float* W = (MODE == 1) ? g_W1r : (MODE == 2) ? g_W2r
                   : (MODE == 3) ? g_W3r : g_W4r;
    float* Op = (MODE == 1) ? g_H1 : (MODE == 3) ? g_Y : OutExt;

    const int t = threadIdx.x, lane = t & 31, wid = t >> 5;
    const int warpM = wid & 1, warpN = wid >> 1;
    const int grp = lane >> 2, qid = lane & 3;

    // ---- copy descriptors ----
    const int q8e = (t & 7) * 4;
    const int rsub = t >> 3;
    const float* asrc[4]; bool avalid[4]; uint32_t adst[4];
#pragma unroll
    for (int i = 0; i < 4; i++) {
        int m = i * 16 + rsub;
        int grow = row0 + m;
        avalid[i] = grow < nrows;
        int arow = avalid[i] ? ((MODE == 1) ? g_rowmap[grow] : grow) : 0;
        asrc[i] = Ap + (size_t)arow * AST + q8e;
        adst[i] = (uint32_t)(m * ASTR + q8e) * 4u;
    }
    const float* bsrc[7]; bool bvalid[7]; uint32_t bdst[7];
#pragma unroll
    for (int i = 0; i < 7; i++) {
        int n = i * 16 + rsub;
        int gcol = yoff + n;
        bvalid[i] = gcol < NW;
        bsrc[i] = W + (size_t)(bvalid[i] ? gcol : 0) * K + q8e;
        bdst[i] = (uint32_t)(ATILE + n * BSTR + q8e) * 4u;
    }

    auto issue = [&](int kt) {
        const int kc = kt * BK + q8e;
        const uint32_t szk = (kc < K) ? 16u : 0u;
        const uint32_t sbase = sb + (uint32_t)(kt & 1) * (STAGE * 4u);
#pragma unroll
        for (int i = 0; i < 4; i++)
            cp16(sbase + adst[i], asrc[i] + kt * BK, avalid[i] ? szk : 0u);
#pragma unroll
        for (int i = 0; i < 7; i++)
            cp16(sbase + bdst[i], bsrc[i] + kt * BK, bvalid[i] ? szk : 0u);
        CP_COMMIT();
    };

    float acc[2][7][4];
#pragma unroll
    for (int mt = 0; mt < 2; mt++)
#pragma unroll
        for (int nt = 0; nt < 7; nt++)
#pragma unroll
            for (int c = 0; c < 4; c++) acc[mt][nt][c] = 0.0f;

    issue(0);
    for (int kt = 0; kt < KT; kt++) {
        if (kt + 1 < KT) { issue(kt + 1); CP_WAIT(1); }
        else             { CP_WAIT(0); }
        __syncthreads();
        const float* AsW = smem + (kt & 1) * STAGE + (warpM * 32 + grp) * ASTR;
        const float* BsW = smem + (kt & 1) * STAGE + ATILE + (warpN * 56 + grp) * BSTR;
#pragma unroll
        for (int k8 = 0; k8 < 4; k8++) {
            const int k0 = k8 * 8;
            uint32_t bf[7][2];
#pragma unroll
            for (int nt = 0; nt < 7; nt++) {
                bf[nt][0] = fu(BsW[nt * 8 * BSTR + k0 + qid]);
                bf[nt][1] = fu(BsW[nt * 8 * BSTR + k0 + qid + 4]);
            }
#pragma unroll
            for (int mt = 0; mt < 2; mt++) {
                const float* a = AsW + mt * 16 * ASTR + k0;
                uint32_t a0, a1, a2, a3;
                if (CVTA) {
                    a0 = f2tf32(a[qid]);
                    a1 = f2tf32(a[8 * ASTR + qid]);
                    a2 = f2tf32(a[qid + 4]);
                    a3 = f2tf32(a[8 * ASTR + qid + 4]);
                } else {
                    a0 = fu(a[qid]);
                    a1 = fu(a[8 * ASTR + qid]);
                    a2 = fu(a[qid + 4]);
                    a3 = fu(a[8 * ASTR + qid + 4]);
                }
#pragma unroll
                for (int nt = 0; nt < 7; nt++)
                    mma_m16n8k8(acc[mt][nt][0], acc[mt][nt][1],
                                acc[mt][nt][2], acc[mt][nt][3],
                                a0, a1, a2, a3, bf[nt][0], bf[nt][1]);
            }
        }
        __syncthreads();
    }

    // ---- MODE 3: fold 1/n scaling into epilogue ----
    float sc0[2], sc1[2];
#pragma unroll
    for (int mt = 0; mt < 2; mt++) {
        int r = row0 + warpM * 32 + mt * 16 + grp;
        sc0[mt] = (MODE == 3 && r < S_) ? g_invN[r] : 1.0f;
        sc1[mt] = (MODE == 3 && r + 8 < S_) ? g_invN[r + 8] : 1.0f;
    }

    // ---- epilogue ----
    if (MODE == 2) {
        float* ep = smem;                          // 64 x 116 floats
        int* sample    = (int*)(smem + BM * EPSTR);
        int* segstart  = sample + BM;
        int* segsample = segstart + BM + 1;
        int* pnseg     = segsample + BM;
#pragma unroll
        for (int mt = 0; mt < 2; mt++) {
            int r = warpM * 32 + mt * 16 + grp;
#pragma unroll
            for (int nt = 0; nt < 7; nt++) {
                int c = warpN * 56 + nt * 8 + 2 * qid;
                int gcol = yoff + c;
                float b0 = (gcol < NW) ? bias[gcol] : 0.0f;
                float b1 = (gcol + 1 < NW) ? bias[gcol + 1] : 0.0f;
                *(float2*)(ep + r * EPSTR + c) =
                    make_float2(fmaxf(acc[mt][nt][0] + b0, 0.0f),
                                fmaxf(acc[mt][nt][1] + b1, 0.0f));
                *(float2*)(ep + (r + 8) * EPSTR + c) =
                    make_float2(fmaxf(acc[mt][nt][2] + b0, 0.0f),
                                fmaxf(acc[mt][nt][3] + b1, 0.0f));
            }
        }
        if (t < BM) {
            int g = row0 + t;
            sample[t] = (g < nrows) ? (g_rowmap[g] >> 5) : -1;
        }
        __syncthreads();
        if (t == 0) {
            int lim = nrows - row0; if (lim > BM) lim = BM;
            int ns = 0, cur = -2;
            for (int r = 0; r < lim; r++) {
                int s = sample[r];
                if (s != cur) { segstart[ns] = r; segsample[ns] = s; ns++; cur = s; }
            }
            segstart[ns] = lim;
            *pnseg = ns;
        }
        __syncthreads();
        if (t < 112) {
            int gcol = yoff + t;
            if (gcol < D_) {
                int ns = *pnseg;
                for (int seg = 0; seg < ns; seg++) {
                    float s = 0.0f;
                    int e = segstart[seg + 1];
                    for (int r = segstart[seg]; r < e; r++) s += ep[r * EPSTR + t];
                    atomicAdd(&g_pooled[(size_t)segsample[seg] * D_ + gcol], s);
                }
            }
        }
    } else {
#pragma unroll
        for (int mt = 0; mt < 2; mt++) {
            int r = row0 + warpM * 32 + mt * 16 + grp;
#pragma unroll
            for (int nt = 0; nt < 7; nt++) {
                int gcol = yoff + warpN * 56 + nt * 8 + 2 * qid;
                if (gcol >= NW) continue;
                float b0 = bias[gcol];
                float b1 = bias[gcol + 1];
                if (r < nrows) {
                    float v0 = fmaxf(acc[mt][nt][0] * sc0[mt] + b0, 0.0f);
                    float v1 = fmaxf(acc[mt][nt][1] * sc0[mt] + b1, 0.0f);
                    if (MODE == 1 || MODE == 3) { v0 = roundtf(v0); v1 = roundtf(v1); }
                    *(float2*)(Op + (size_t)r * OST + gcol) = make_float2(v0, v1);
                }
                if (r + 8 < nrows) {
                    float v2 = fmaxf(acc[mt][nt][2] * sc1[mt] + b0, 0.0f);
                    float v3 = fmaxf(acc[mt][nt][3] * sc1[mt] + b1, 0.0f);
                    if (MODE == 1 || MODE == 3) { v2 = roundtf(v2); v3 = roundtf(v3); }
                    *(float2*)(Op + (size_t)(r + 8) * OST + gcol) = make_float2(v2, v3);
                }
            }
        }
    }
}

// ---------------------------------------------------------------------------------
extern "C" void kernel_launch(void* const* d_in, const int* in_sizes, int n_in,
                              void* d_out, int out_size) {
    (void)in_sizes; (void)n_in; (void)out_size;
    const float* all_x     = (const float*)d_in[0];
    const int*   numInputs = (const int*)  d_in[1];
    const float* W1 = (const float*)d_in[2];
    const float* b1 = (const float*)d_in[3];
    const float* W2 = (const float*)d_in[4];
    const float* b2 = (const float*)d_in[5];
    const float* W3 = (const float*)d_in[6];
    const float* b3 = (const float*)d_in[7];
    const float* W4 = (const float*)d_in[8];
    const float* b4 = (const float*)d_in[9];
    float* out = (float*)d_out;

    const int SMEM = 2 * (64 * 36 + 112 * 36) * 4;   // 50688 bytes
    static bool attr_done = false;
    if (!attr_done) {
        cudaFuncSetAttribute(gemm_cp<1, D_, true>,  cudaFuncAttributeMaxDynamicSharedMemorySize, SMEM);
        cudaFuncSetAttribute(gemm_cp<2, D_, false>, cudaFuncAttributeMaxDynamicSharedMemorySize, SMEM);
        cudaFuncSetAttribute(gemm_cp<3, D_, true>,  cudaFuncAttributeMaxDynamicSharedMemorySize, SMEM);
        cudaFuncSetAttribute(gemm_cp<4, H_, false>, cudaFuncAttributeMaxDynamicSharedMemorySize, SMEM);
        attr_done = true;
    }

    setup_kernel<<<1, 256>>>(numInputs);
    zero_pooled_kernel<<<(S_ * D_ + 255) / 256, 256>>>();
    round_w_kernel<1><<<(D_ * D_ + 255) / 256, 256>>>(W1, D_ * D_);
    round_w_kernel<2><<<(D_ * D_ + 255) / 256, 256>>>(W2, D_ * D_);
    round_w_kernel<3><<<(H_ * D_ + 255) / 256, 256>>>(W3, H_ * D_);
    round_w_kernel<4><<<(D_ * H_ + 255) / 256, 256>>>(W4, D_ * H_);

    // layer 1: H1 = relu(X_active @ W1^T + b1)     [nact, 420] (rounded)
    gemm_cp<1, D_, true><<<dim3((S_ * M_ + 63) / 64, 4), 128, SMEM>>>(all_x, b1, nullptr);
    // layer 2 + ragged sum-pool into g_pooled      [nact, 420] -> [S, 420]
    gemm_cp<2, D_, false><<<dim3((S_ * M_ + 63) / 64, 4), 128, SMEM>>>(nullptr, b2, nullptr);
    // layer 3: Y = relu((pooled @ W3^T)/n + b3)    [S, 840] (rounded)
    gemm_cp<3, D_, true><<<dim3(S_ / 64, 8), 128, SMEM>>>(nullptr, b3, nullptr);
    // layer 4: out = relu(Y @ W4^T + b4)           [S, 420]
    gemm_cp<4, H_, false><<<dim3(S_ / 64, 4), 128, SMEM>>>(nullptr, b4, out);
}

// round 11
// speedup vs baseline: 4.9502x; 1.2974x over previous
#include <cuda_runtime.h>
#include <cuda_fp16.h>
#include <cstdint>

#define S_ 4096
#define M_ 32
#define D_ 420
#define H_ 840
#define KP_ 424   // padded fp16 K-stride for K=420 rows (848B, 16B-aligned)

// ------------- scratch (static device globals; 256B-aligned for cp.async) --------
__device__ __align__(256) int    g_rowmap[S_ * M_];             // compact row -> s*32+m
__device__ int    g_nact;                                       // number of active rows
__device__ __align__(256) float  g_invN[S_];                    // 1/numInputs[s]
__device__ __align__(256) __half g_H1h[(size_t)S_ * M_ * KP_];  // layer-1 out (fp16, padded K)
__device__ __align__(256) float  g_pooled[(size_t)S_ * D_];     // ragged-mean numerator
__device__ __align__(256) __half g_Yh[(size_t)S_ * H_];         // layer-3 out (fp16)
__device__ __align__(256) __half g_W1h[D_ * KP_];               // fp16 weights [N][KP]
__device__ __align__(256) __half g_W2h[D_ * KP_];
__device__ __align__(256) __half g_W3h[H_ * KP_];
__device__ __align__(256) __half g_W4h[D_ * H_];                // K=840, natural

__device__ __forceinline__ uint32_t packh2(float lo, float hi) {
    uint32_t r;
    asm("cvt.rn.f16x2.f32 %0, %1, %2;" : "=r"(r) : "f"(hi), "f"(lo));
    return r;
}
__device__ __forceinline__ void mma_f16(float& d0, float& d1, float& d2, float& d3,
                                        uint32_t a0, uint32_t a1, uint32_t a2,
                                        uint32_t a3, uint32_t b0, uint32_t b1) {
    asm volatile(
        "mma.sync.aligned.m16n8k16.row.col.f32.f16.f16.f32 "
        "{%0,%1,%2,%3}, {%4,%5,%6,%7}, {%8,%9}, {%0,%1,%2,%3};"
        : "+f"(d0), "+f"(d1), "+f"(d2), "+f"(d3)
        : "r"(a0), "r"(a1), "r"(a2), "r"(a3), "r"(b0), "r"(b1));
}
__device__ __forceinline__ uint32_t smem_u32(const void* p) {
    uint32_t a;
    asm("{ .reg .u64 t; cvta.to.shared.u64 t, %1; cvt.u32.u64 %0, t; }"
        : "=r"(a) : "l"(p));
    return a;
}
__device__ __forceinline__ void cp16(uint32_t dst, const void* src, uint32_t srcsz) {
    asm volatile("cp.async.cg.shared.global [%0], [%1], 16, %2;"
                 :: "r"(dst), "l"(src), "r"(srcsz) : "memory");
}
#define CP_COMMIT() asm volatile("cp.async.commit_group;" ::: "memory")
#define CP_WAIT(n)  asm volatile("cp.async.wait_group %0;" :: "n"(n) : "memory")

// ---------------- setup: prefix-scan numInputs, build compact row map -------------
__global__ void setup_kernel(const int* __restrict__ numInputs) {
    __shared__ int s_warp[8];
    __shared__ int s_woff[8];
    int t = threadIdx.x;
    int base = t * 16;
    int local[16];
    int run = 0;
#pragma unroll
    for (int j = 0; j < 16; j++) { local[j] = run; run += numInputs[base + j]; }
    int lane = t & 31, warp = t >> 5;
    int inc = run;
#pragma unroll
    for (int o = 1; o < 32; o <<= 1) {
        int v = __shfl_up_sync(0xffffffffu, inc, o);
        if (lane >= o) inc += v;
    }
    if (lane == 31) s_warp[warp] = inc;
    __syncthreads();
    if (t == 0) {
        int r = 0;
        for (int w = 0; w < 8; w++) { s_woff[w] = r; r += s_warp[w]; }
        g_nact = r;
    }
    __syncthreads();
    int thrOff = s_woff[warp] + (inc - run);
    for (int j = 0; j < 16; j++) {
        int s = base + j;
        int n = numInputs[s];
        g_invN[s] = 1.0f / (float)n;
        int off = thrOff + local[j];
        for (int m = 0; m < n; m++) g_rowmap[off + m] = s * M_ + m;
    }
}

// fused prep: zero g_pooled, convert weights to fp16 (padded stride, pad zeroed),
// and zero the K-pad of g_H1h (cols 420..423 of every row).
__global__ void prep_kernel(const float* __restrict__ W1, const float* __restrict__ W2,
                            const float* __restrict__ W3, const float* __restrict__ W4) {
    const int NP = S_ * D_;
    const int NW12 = D_ * KP_, NW3 = H_ * KP_, NW4 = D_ * H_;
    const int NH1P = S_ * M_ * 4;                 // pad elems of g_H1h
    int i = blockIdx.x * blockDim.x + threadIdx.x;
    if (i < NP) { g_pooled[i] = 0.0f; return; }
    i -= NP;
    if (i < NW12) {
        int r = i / KP_, c = i - r * KP_;
        g_W1h[i] = (c < D_) ? __float2half_rn(W1[r * D_ + c]) : __half(0.0f);
        return;
    }
    i -= NW12;
    if (i < NW12) {
        int r = i / KP_, c = i - r * KP_;
        g_W2h[i] = (c < D_) ? __float2half_rn(W2[r * D_ + c]) : __half(0.0f);
        return;
    }
    i -= NW12;
    if (i < NW3) {
        int r = i / KP_, c = i - r * KP_;
        g_W3h[i] = (c < D_) ? __float2half_rn(W3[r * D_ + c]) : __half(0.0f);
        return;
    }
    i -= NW3;
    if (i < NW4) { g_W4h[i] = __float2half_rn(W4[i]); return; }
    i -= NW4;
    if (i < NH1P) {
        int r = i >> 2, c = i & 3;
        g_H1h[(size_t)r * KP_ + D_ + c] = __half(0.0f);
    }
}

// ---------------- fp16 mma GEMM with cp.async pipeline ----------------------------
// MODE 1 (CVTA): A = all_x fp32 gathered -> g_H1h (fp16, stride KP_), rows = g_nact
// MODE 2:        A = g_H1h fp16, epilogue = segmented reduce + atomicAdd g_pooled
// MODE 3 (CVTA): A = g_pooled fp32, 1/n in epilogue -> g_Yh (fp16), rows = S
// MODE 4:        A = g_Yh fp16 -> d_out fp32, rows = S
template <int MODE, int K, bool CVTA>
__global__ void __launch_bounds__(128, 4)
gemm_h(const float* __restrict__ Aext, const float* __restrict__ bias,
       float* __restrict__ OutExt) {
    constexpr int BM = 64, BK = 32;
    constexpr int KT = (K + BK - 1) / BK;
    constexpr int NW  = (MODE == 3) ? H_ : D_;
    constexpr int ASTF = D_;                       // fp32 A row stride (modes 1,3)
    constexpr int ASTH = (MODE == 4) ? H_ : KP_;   // fp16 A row stride (modes 2,4)
    constexpr int WST  = (MODE == 4) ? H_ : KP_;   // weight row stride
    constexpr int KLIM = (MODE == 4) ? H_ : KP_;   // aligned copy limit (pad zeroed)
    constexpr int ATILEB = CVTA ? (64 * 36 * 4) : (64 * 40 * 2);  // 9216 : 5120
    constexpr int BTILEB = 112 * 40 * 2;                          // 8960
    constexpr int STAGEB = ATILEB + BTILEB;
    constexpr int EPSTR = 116;

    extern __shared__ __align__(16) char smemc[];
    const uint32_t sb = smem_u32(smemc);

    const int nrows = (MODE <= 2) ? g_nact : S_;
    const int row0 = blockIdx.x * BM;
    if (row0 >= nrows) return;
    const int yoff = blockIdx.y * 112;

    const float*  ApF = (MODE == 1) ? Aext : g_pooled;
    const __half* ApH = (MODE == 2) ? g_H1h : g_Yh;
    const __half* Wh  = (MODE == 1) ? g_W1h : (MODE == 2) ? g_W2h
                      : (MODE == 3) ? g_W3h : g_W4h;

    const int t = threadIdx.x, lane = t & 31, wid = t >> 5;
    const int warpM = wid & 1, warpN = wid >> 1;
    const int grp = lane >> 2, qid = lane & 3;

    // ---- copy descriptors ----
    const void* asrc[4]; uint32_t adst[4]; int akoff[4]; bool avalid[4];
    if (CVTA) {
#pragma unroll
        for (int i = 0; i < 4; i++) {
            int idx = i * 128 + t;            // 0..511 = 64 rows x 8 granules
            int m = idx >> 3, g = idx & 7;    // granule = 4 floats
            int grow = row0 + m;
            avalid[i] = grow < nrows;
            int arow = avalid[i] ? ((MODE == 1) ? g_rowmap[grow] : grow) : 0;
            asrc[i] = ApF + (size_t)arow * ASTF + g * 4;
            adst[i] = (uint32_t)(m * 144 + g * 16);
            akoff[i] = g * 4;
        }
    } else {
#pragma unroll
        for (int i = 0; i < 2; i++) {
            int idx = i * 128 + t;            // 0..255 = 64 rows x 4 granules
            int m = idx >> 2, g = idx & 3;    // granule = 8 halfs
            int grow = row0 + m;
            avalid[i] = grow < nrows;
            asrc[i] = ApH + (size_t)(avalid[i] ? grow : 0) * ASTH + g * 8;
            adst[i] = (uint32_t)(m * 80 + g * 16);
            akoff[i] = g * 8;
        }
    }
    // B tile: 112 rows x 4 granules = 448 slots; idx in [448,512) has NO slot
    // and must not issue (its zfill would write past the tile -> smem OOB).
    const __half* bsrc[4]; uint32_t bdst[4]; int bkoff[4]; bool bvalid[4]; bool bstore[4];
#pragma unroll
    for (int i = 0; i < 4; i++) {
        int idx = i * 128 + t;                // 0..511
        int n = idx >> 2, g = idx & 3;
        bstore[i] = idx < 448;
        int gcol = yoff + n;
        bvalid[i] = bstore[i] && (gcol < NW);
        bsrc[i] = Wh + (size_t)(bvalid[i] ? gcol : 0) * WST + g * 8;
        bdst[i] = (uint32_t)(ATILEB + (bstore[i] ? n : 0) * 80 + g * 16);
        bkoff[i] = g * 8;
    }

    auto issue = [&](int kt) {
        const uint32_t sbase = sb + (uint32_t)(kt & 1) * STAGEB;
        const int kb = kt * BK;
        if (CVTA) {
#pragma unroll
            for (int i = 0; i < 4; i++) {
                uint32_t sz = (avalid[i] && (kb + akoff[i]) < K) ? 16u : 0u;
                cp16(sbase + adst[i], (const float*)asrc[i] + kb, sz);
            }
        } else {
#pragma unroll
            for (int i = 0; i < 2; i++) {
                uint32_t sz = (avalid[i] && (kb + akoff[i] + 8) <= KLIM) ? 16u : 0u;
                cp16(sbase + adst[i], (const __half*)asrc[i] + kb, sz);
            }
        }
#pragma unroll
        for (int i = 0; i < 4; i++) {
            if (bstore[i]) {
                uint32_t sz = (bvalid[i] && (kb + bkoff[i] + 8) <= KLIM) ? 16u : 0u;
                cp16(sbase + bdst[i], bsrc[i] + kb, sz);
            }
        }
        CP_COMMIT();
    };

    float acc[2][7][4];
#pragma unroll
    for (int mt = 0; mt < 2; mt++)
#pragma unroll
        for (int nt = 0; nt < 7; nt++)
#pragma unroll
            for (int c = 0; c < 4; c++) acc[mt][nt][c] = 0.0f;

    issue(0);
    for (int kt = 0; kt < KT; kt++) {
        if (kt + 1 < KT) { issue(kt + 1); CP_WAIT(1); }
        else             { CP_WAIT(0); }
        __syncthreads();
        const char* st = smemc + (kt & 1) * STAGEB;
        const char* AsW = st + (warpM * 32 + grp) * (CVTA ? 144 : 80);
        const char* BsW = st + ATILEB + (warpN * 56 + grp) * 80;
#pragma unroll
        for (int s16 = 0; s16 < 2; s16++) {
            uint32_t bf[7][2];
#pragma unroll
            for (int nt = 0; nt < 7; nt++) {
                const char* bp = BsW + nt * 640 + s16 * 32 + qid * 4;
                bf[nt][0] = *(const uint32_t*)bp;
                bf[nt][1] = *(const uint32_t*)(bp + 16);
            }
#pragma unroll
            for (int mt = 0; mt < 2; mt++) {
                uint32_t a0, a1, a2, a3;
                if (CVTA) {
                    const char* ap = AsW + mt * 16 * 144 + s16 * 64 + qid * 8;
                    float2 p0 = *(const float2*)ap;
                    float2 p1 = *(const float2*)(ap + 1152);
                    float2 p2 = *(const float2*)(ap + 32);
                    float2 p3 = *(const float2*)(ap + 1184);
                    a0 = packh2(p0.x, p0.y);
                    a1 = packh2(p1.x, p1.y);
                    a2 = packh2(p2.x, p2.y);
                    a3 = packh2(p3.x, p3.y);
                } else {
                    const char* ap = AsW + mt * 16 * 80 + s16 * 32 + qid * 4;
                    a0 = *(const uint32_t*)ap;
                    a1 = *(const uint32_t*)(ap + 640);
                    a2 = *(const uint32_t*)(ap + 16);
                    a3 = *(const uint32_t*)(ap + 656);
                }
#pragma unroll
                for (int nt = 0; nt < 7; nt++)
                    mma_f16(acc[mt][nt][0], acc[mt][nt][1],
                            acc[mt][nt][2], acc[mt][nt][3],
                            a0, a1, a2, a3, bf[nt][0], bf[nt][1]);
            }
        }
        __syncthreads();
    }

    // ---- MODE 3: fold 1/n scaling into epilogue ----
    float sc0[2], sc1[2];
#pragma unroll
    for (int mt = 0; mt < 2; mt++) {
        int r = row0 + warpM * 32 + mt * 16 + grp;
        sc0[mt] = (MODE == 3 && r < S_) ? g_invN[r] : 1.0f;
        sc1[mt] = (MODE == 3 && r + 8 < S_) ? g_invN[r + 8] : 1.0f;
    }

    // ---- epilogue ----
    if (MODE == 2) {
        float* ep = (float*)smemc;                 // 64 x 116 floats
        int* sample    = (int*)(ep + BM * EPSTR);
        int* segstart  = sample + BM;
        int* segsample = segstart + BM + 1;
        int* pnseg     = segsample + BM;
#pragma unroll
        for (int mt = 0; mt < 2; mt++) {
            int r = warpM * 32 + mt * 16 + grp;
#pragma unroll
            for (int nt = 0; nt < 7; nt++) {
                int c = warpN * 56 + nt * 8 + 2 * qid;
                int gcol = yoff + c;
                float b0 = (gcol < NW) ? bias[gcol] : 0.0f;
                float b1 = (gcol + 1 < NW) ? bias[gcol + 1] : 0.0f;
                *(float2*)(ep + r * EPSTR + c) =
                    make_float2(fmaxf(acc[mt][nt][0] + b0, 0.0f),
                                fmaxf(acc[mt][nt][1] + b1, 0.0f));
                *(float2*)(ep + (r + 8) * EPSTR + c) =
                    make_float2(fmaxf(acc[mt][nt][2] + b0, 0.0f),
                                fmaxf(acc[mt][nt][3] + b1, 0.0f));
            }
        }
        if (t < BM) {
            int g = row0 + t;
            sample[t] = (g < nrows) ? (g_rowmap[g] >> 5) : -1;
        }
        __syncthreads();
        if (t == 0) {
            int lim = nrows - row0; if (lim > BM) lim = BM;
            int ns = 0, cur = -2;
            for (int r = 0; r < lim; r++) {
                int s = sample[r];
                if (s != cur) { segstart[ns] = r; segsample[ns] = s; ns++; cur = s; }
            }
            segstart[ns] = lim;
            *pnseg = ns;
        }
        __syncthreads();
        if (t < 112) {
            int gcol = yoff + t;
            if (gcol < D_) {
                int ns = *pnseg;
                for (int seg = 0; seg < ns; seg++) {
                    float s = 0.0f;
                    int e = segstart[seg + 1];
                    for (int r = segstart[seg]; r < e; r++) s += ep[r * EPSTR + t];
                    atomicAdd(&g_pooled[(size_t)segsample[seg] * D_ + gcol], s);
                }
            }
        }
    } else {
#pragma unroll
        for (int mt = 0; mt < 2; mt++) {
            int r = row0 + warpM * 32 + mt * 16 + grp;
#pragma unroll
            for (int nt = 0; nt < 7; nt++) {
                int gcol = yoff + warpN * 56 + nt * 8 + 2 * qid;
                if (gcol >= NW) continue;
                float b0 = bias[gcol];
                float b1 = bias[gcol + 1];
                float v0 = fmaxf(acc[mt][nt][0] * sc0[mt] + b0, 0.0f);
                float v1 = fmaxf(acc[mt][nt][1] * sc0[mt] + b1, 0.0f);
                float v2 = fmaxf(acc[mt][nt][2] * sc1[mt] + b0, 0.0f);
                float v3 = fmaxf(acc[mt][nt][3] * sc1[mt] + b1, 0.0f);
                if (MODE == 4) {
                    if (r < nrows)
                        *(float2*)(OutExt + (size_t)r * D_ + gcol) = make_float2(v0, v1);
                    if (r + 8 < nrows)
                        *(float2*)(OutExt + (size_t)(r + 8) * D_ + gcol) = make_float2(v2, v3);
                } else {
                    __half* OH = (MODE == 1) ? g_H1h : g_Yh;
                    const int ost = (MODE == 1) ? KP_ : H_;
                    if (r < nrows)
                        *(uint32_t*)(OH + (size_t)r * ost + gcol) = packh2(v0, v1);
                    if (r + 8 < nrows)
                        *(uint32_t*)(OH + (size_t)(r + 8) * ost + gcol) = packh2(v2, v3);
                }
            }
        }
    }
}

// ---------------------------------------------------------------------------------
extern "C" void kernel_launch(void* const* d_in, const int* in_sizes, int n_in,
                              void* d_out, int out_size) {
    (void)in_sizes; (void)n_in; (void)out_size;
    const float* all_x     = (const float*)d_in[0];
    const int*   numInputs = (const int*)  d_in[1];
    const float* W1 = (const float*)d_in[2];
    const float* b1 = (const float*)d_in[3];
    const float* W2 = (const float*)d_in[4];
    const float* b2 = (const float*)d_in[5];
    const float* W3 = (const float*)d_in[6];
    const float* b3 = (const float*)d_in[7];
    const float* W4 = (const float*)d_in[8];
    const float* b4 = (const float*)d_in[9];
    float* out = (float*)d_out;

    const int SMEM_CVT = 2 * (64 * 36 * 4 + 112 * 40 * 2);   // 36352 (modes 1,3)
    const int SMEM_H   = 2 * (64 * 40 * 2 + 112 * 40 * 2);   // 28160 (mode 4)
    const int SMEM_M2  = 30720;                              // mode 2 (epilogue stage)
    cudaFuncSetAttribute(gemm_h<1, D_, true>,  cudaFuncAttributeMaxDynamicSharedMemorySize, SMEM_CVT);
    cudaFuncSetAttribute(gemm_h<2, D_, false>, cudaFuncAttributeMaxDynamicSharedMemorySize, SMEM_M2);
    cudaFuncSetAttribute(gemm_h<3, D_, true>,  cudaFuncAttributeMaxDynamicSharedMemorySize, SMEM_CVT);
    cudaFuncSetAttribute(gemm_h<4, H_, false>, cudaFuncAttributeMaxDynamicSharedMemorySize, SMEM_H);

    setup_kernel<<<1, 256>>>(numInputs);
    {
        int total = S_ * D_ + 2 * D_ * KP_ + H_ * KP_ + D_ * H_ + S_ * M_ * 4;
        prep_kernel<<<(total + 255) / 256, 256>>>(W1, W2, W3, W4);
    }

    // layer 1: H1 = relu(X_active @ W1^T + b1)     [nact, 420] -> fp16 (stride KP_)
    gemm_h<1, D_, true><<<dim3((S_ * M_ + 63) / 64, 4), 128, SMEM_CVT>>>(all_x, b1, nullptr);
    // layer 2 + ragged sum-pool into g_pooled      [nact, 420] -> [S, 420]
    gemm_h<2, D_, false><<<dim3((S_ * M_ + 63) / 64, 4), 128, SMEM_M2>>>(nullptr, b2, nullptr);
    // layer 3: Y = relu((pooled @ W3^T)/n + b3)    [S, 840] -> fp16
    gemm_h<3, D_, true><<<dim3(S_ / 64, 8), 128, SMEM_CVT>>>(nullptr, b3, nullptr);
    // layer 4: out = relu(Y @ W4^T + b4)           [S, 420]
    gemm_h<4, H_, false><<<dim3(S_ / 64, 4), 128, SMEM_H>>>(nullptr, b4, out);
}

// round 12
// speedup vs baseline: 4.9842x; 1.0069x over previous
#include <cuda_runtime.h>
#include <cuda_fp16.h>
#include <cstdint>

#define S_ 4096
#define M_ 32
#define D_ 420
#define H_ 840
#define KP_ 424   // padded fp16 K-stride for K=420 rows (848B, 16B-aligned)

// ------------- scratch (static device globals; 256B-aligned for cp.async) --------
__device__ __align__(256) int    g_rowmap[S_ * M_];             // compact row -> s*32+m
__device__ int    g_nact;                                       // number of active rows
__device__ __align__(256) float  g_invN[S_];                    // 1/numInputs[s]
__device__ __align__(256) __half g_H1h[(size_t)S_ * M_ * KP_];  // layer-1 out (fp16, padded K)
__device__ __align__(256) float  g_pooled[(size_t)S_ * D_];     // ragged-mean numerator
__device__ __align__(256) __half g_Yh[(size_t)S_ * H_];         // layer-3 out (fp16)
__device__ __align__(256) __half g_W1h[D_ * KP_];               // fp16 weights [N][KP]
__device__ __align__(256) __half g_W2h[D_ * KP_];
__device__ __align__(256) __half g_W3h[H_ * KP_];
__device__ __align__(256) __half g_W4h[D_ * H_];                // K=840, natural

__device__ __forceinline__ uint32_t packh2(float lo, float hi) {
    uint32_t r;
    asm("cvt.rn.f16x2.f32 %0, %1, %2;" : "=r"(r) : "f"(hi), "f"(lo));
    return r;
}
__device__ __forceinline__ void mma_f16(float& d0, float& d1, float& d2, float& d3,
                                        uint32_t a0, uint32_t a1, uint32_t a2,
                                        uint32_t a3, uint32_t b0, uint32_t b1) {
    asm volatile(
        "mma.sync.aligned.m16n8k16.row.col.f32.f16.f16.f32 "
        "{%0,%1,%2,%3}, {%4,%5,%6,%7}, {%8,%9}, {%0,%1,%2,%3};"
        : "+f"(d0), "+f"(d1), "+f"(d2), "+f"(d3)
        : "r"(a0), "r"(a1), "r"(a2), "r"(a3), "r"(b0), "r"(b1));
}
__device__ __forceinline__ void ldsm4(uint32_t& r0, uint32_t& r1, uint32_t& r2,
                                      uint32_t& r3, uint32_t addr) {
    asm volatile("ldmatrix.sync.aligned.m8n8.x4.shared.b16 {%0,%1,%2,%3}, [%4];"
                 : "=r"(r0), "=r"(r1), "=r"(r2), "=r"(r3) : "r"(addr));
}
__device__ __forceinline__ void ldsm2(uint32_t& r0, uint32_t& r1, uint32_t addr) {
    asm volatile("ldmatrix.sync.aligned.m8n8.x2.shared.b16 {%0,%1}, [%2];"
                 : "=r"(r0), "=r"(r1) : "r"(addr));
}
__device__ __forceinline__ uint32_t smem_u32(const void* p) {
    uint32_t a;
    asm("{ .reg .u64 t; cvta.to.shared.u64 t, %1; cvt.u32.u64 %0, t; }"
        : "=r"(a) : "l"(p));
    return a;
}
__device__ __forceinline__ void cp16(uint32_t dst, const void* src, uint32_t srcsz) {
    asm volatile("cp.async.cg.shared.global [%0], [%1], 16, %2;"
                 :: "r"(dst), "l"(src), "r"(srcsz) : "memory");
}
#define CP_COMMIT() asm volatile("cp.async.commit_group;" ::: "memory")
#define CP_WAIT(n)  asm volatile("cp.async.wait_group %0;" :: "n"(n) : "memory")

// ---------------- setup: prefix-scan numInputs, build compact row map -------------
__global__ void setup_kernel(const int* __restrict__ numInputs) {
    __shared__ int s_warp[8];
    __shared__ int s_woff[8];
    int t = threadIdx.x;
    int base = t * 16;
    int local[16];
    int run = 0;
#pragma unroll
    for (int j = 0; j < 16; j++) { local[j] = run; run += numInputs[base + j]; }
    int lane = t & 31, warp = t >> 5;
    int inc = run;
#pragma unroll
    for (int o = 1; o < 32; o <<= 1) {
        int v = __shfl_up_sync(0xffffffffu, inc, o);
        if (lane >= o) inc += v;
    }
    if (lane == 31) s_warp[warp] = inc;
    __syncthreads();
    if (t == 0) {
        int r = 0;
        for (int w = 0; w < 8; w++) { s_woff[w] = r; r += s_warp[w]; }
        g_nact = r;
    }
    __syncthreads();
    int thrOff = s_woff[warp] + (inc - run);
    for (int j = 0; j < 16; j++) {
        int s = base + j;
        int n = numInputs[s];
        g_invN[s] = 1.0f / (float)n;
        int off = thrOff + local[j];
        for (int m = 0; m < n; m++) g_rowmap[off + m] = s * M_ + m;
    }
}

// fused prep: zero g_pooled, convert weights to fp16 (padded stride, pad zeroed),
// and zero the K-pad of g_H1h (cols 420..423 of every row).
__global__ void prep_kernel(const float* __restrict__ W1, const float* __restrict__ W2,
                            const float* __restrict__ W3, const float* __restrict__ W4) {
    const int NP = S_ * D_;
    const int NW12 = D_ * KP_, NW3 = H_ * KP_, NW4 = D_ * H_;
    const int NH1P = S_ * M_ * 4;                 // pad elems of g_H1h
    int i = blockIdx.x * blockDim.x + threadIdx.x;
    if (i < NP) { g_pooled[i] = 0.0f; return; }
    i -= NP;
    if (i < NW12) {
        int r = i / KP_, c = i - r * KP_;
        g_W1h[i] = (c < D_) ? __float2half_rn(W1[r * D_ + c]) : __half(0.0f);
        return;
    }
    i -= NW12;
    if (i < NW12) {
        int r = i / KP_, c = i - r * KP_;
        g_W2h[i] = (c < D_) ? __float2half_rn(W2[r * D_ + c]) : __half(0.0f);
        return;
    }
    i -= NW12;
    if (i < NW3) {
        int r = i / KP_, c = i - r * KP_;
        g_W3h[i] = (c < D_) ? __float2half_rn(W3[r * D_ + c]) : __half(0.0f);
        return;
    }
    i -= NW3;
    if (i < NW4) { g_W4h[i] = __float2half_rn(W4[i]); return; }
    i -= NW4;
    if (i < NH1P) {
        int r = i >> 2, c = i & 3;
        g_H1h[(size_t)r * KP_ + D_ + c] = __half(0.0f);
    }
}

// ---------------- fp16 mma GEMM, 3-stage cp.async + ldmatrix ---------------------
// MODE 1 (CVTA): A = all_x fp32 gathered -> g_H1h (fp16, stride KP_), rows = g_nact
// MODE 2:        A = g_H1h fp16, epilogue = segmented reduce + atomicAdd g_pooled
// MODE 3 (CVTA): A = g_pooled fp32, 1/n in epilogue -> g_Yh (fp16), rows = S
// MODE 4:        A = g_Yh fp16 -> d_out fp32, rows = S
template <int MODE, int K, bool CVTA>
__global__ void __launch_bounds__(128, 4)
gemm_h(const float* __restrict__ Aext, const float* __restrict__ bias,
       float* __restrict__ OutExt) {
    constexpr int BM = 64, BK = 32;
    constexpr int KT = (K + BK - 1) / BK;
    constexpr int NW  = (MODE == 3) ? H_ : D_;
    constexpr int ASTF = D_;                       // fp32 A row stride (modes 1,3)
    constexpr int ASTH = (MODE == 4) ? H_ : KP_;   // fp16 A row stride (modes 2,4)
    constexpr int WST  = (MODE == 4) ? H_ : KP_;   // weight row stride
    constexpr int KLIM = (MODE == 4) ? H_ : KP_;   // aligned copy limit (pad zeroed)
    constexpr int ATILEB = CVTA ? (64 * 36 * 4) : (64 * 40 * 2);  // 9216 : 5120
    constexpr int BTILEB = 112 * 40 * 2;                          // 8960
    constexpr int STAGEB = ATILEB + BTILEB;
    constexpr int EPSTR = 116;

    extern __shared__ __align__(16) char smemc[];
    const uint32_t sb = smem_u32(smemc);

    const int nrows = (MODE <= 2) ? g_nact : S_;
    const int row0 = blockIdx.x * BM;
    if (row0 >= nrows) return;
    const int yoff = blockIdx.y * 112;

    const float*  ApF = (MODE == 1) ? Aext : g_pooled;
    const __half* ApH = (MODE == 2) ? g_H1h : g_Yh;
    const __half* Wh  = (MODE == 1) ? g_W1h : (MODE == 2) ? g_W2h
                      : (MODE == 3) ? g_W3h : g_W4h;

    const int t = threadIdx.x, lane = t & 31, wid = t >> 5;
    const int warpM = wid & 1, warpN = wid >> 1;
    const int grp = lane >> 2, qid = lane & 3;
    const int r8 = lane & 7, sub = lane >> 3;      // ldmatrix lane decomposition

    // ---- ldmatrix per-lane base offsets (relative to stage start) ----
    // B x4 pairs: nt = 2j + (sub>>1), matrices (b0,b1) selected by (sub&1)*16
    const uint32_t bB = (uint32_t)(ATILEB + (warpN * 56 + (sub >> 1) * 8 + r8) * 80
                                   + (sub & 1) * 16);
    // B x2 (nt = 6): lanes 0..15 supply addresses
    const uint32_t bB6 = (uint32_t)(ATILEB + (warpN * 56 + 48 + r8) * 80
                                    + (sub & 1) * 16);
    // A x4 (non-CVTA): matrices a0..a3 = (row-half, k-half) selected by sub
    const uint32_t aB = (uint32_t)((warpM * 32 + (sub & 1) * 8 + r8) * 80
                                   + (sub >> 1) * 16);

    // ---- copy descriptors ----
    const void* asrc[4]; uint32_t adst[4]; int akoff[4]; bool avalid[4];
    if (CVTA) {
#pragma unroll
        for (int i = 0; i < 4; i++) {
            int idx = i * 128 + t;            // 0..511 = 64 rows x 8 granules
            int m = idx >> 3, g = idx & 7;    // granule = 4 floats
            int grow = row0 + m;
            avalid[i] = grow < nrows;
            int arow = avalid[i] ? ((MODE == 1) ? g_rowmap[grow] : grow) : 0;
            asrc[i] = ApF + (size_t)arow * ASTF + g * 4;
            adst[i] = (uint32_t)(m * 144 + g * 16);
            akoff[i] = g * 4;
        }
    } else {
#pragma unroll
        for (int i = 0; i < 2; i++) {
            int idx = i * 128 + t;            // 0..255 = 64 rows x 4 granules
            int m = idx >> 2, g = idx & 3;    // granule = 8 halfs
            int grow = row0 + m;
            avalid[i] = grow < nrows;
            asrc[i] = ApH + (size_t)(avalid[i] ? grow : 0) * ASTH + g * 8;
            adst[i] = (uint32_t)(m * 80 + g * 16);
            akoff[i] = g * 8;
        }
    }
    // B tile: 112 rows x 4 granules = 448 slots; idx >= 448 must not issue.
    const __half* bsrc[4]; uint32_t bdst[4]; int bkoff[4]; bool bvalid[4]; bool bstore[4];
#pragma unroll
    for (int i = 0; i < 4; i++) {
        int idx = i * 128 + t;                // 0..511
        int n = idx >> 2, g = idx & 3;
        bstore[i] = idx < 448;
        int gcol = yoff + n;
        bvalid[i] = bstore[i] && (gcol < NW);
        bsrc[i] = Wh + (size_t)(bvalid[i] ? gcol : 0) * WST + g * 8;
        bdst[i] = (uint32_t)(ATILEB + (bstore[i] ? n : 0) * 80 + g * 16);
        bkoff[i] = g * 8;
    }

    auto issue = [&](int kt) {
        const uint32_t sbase = sb + (uint32_t)(kt % 3) * STAGEB;
        const int kb = kt * BK;
        if (CVTA) {
#pragma unroll
            for (int i = 0; i < 4; i++) {
                uint32_t sz = (avalid[i] && (kb + akoff[i]) < K) ? 16u : 0u;
                cp16(sbase + adst[i], (const float*)asrc[i] + kb, sz);
            }
        } else {
#pragma unroll
            for (int i = 0; i < 2; i++) {
                uint32_t sz = (avalid[i] && (kb + akoff[i] + 8) <= KLIM) ? 16u : 0u;
                cp16(sbase + adst[i], (const __half*)asrc[i] + kb, sz);
            }
        }
#pragma unroll
        for (int i = 0; i < 4; i++) {
            if (bstore[i]) {
                uint32_t sz = (bvalid[i] && (kb + bkoff[i] + 8) <= KLIM) ? 16u : 0u;
                cp16(sbase + bdst[i], bsrc[i] + kb, sz);
            }
        }
        CP_COMMIT();
    };

    float acc[2][7][4];
#pragma unroll
    for (int mt = 0; mt < 2; mt++)
#pragma unroll
        for (int nt = 0; nt < 7; nt++)
#pragma unroll
            for (int c = 0; c < 4; c++) acc[mt][nt][c] = 0.0f;

    issue(0);
    issue(1);
    for (int kt = 0; kt < KT; kt++) {
        if (kt + 1 < KT) { CP_WAIT(1); } else { CP_WAIT(0); }
        __syncthreads();
        if (kt + 2 < KT) issue(kt + 2);

        const uint32_t stb = sb + (uint32_t)(kt % 3) * STAGEB;
        const char* stc = smemc + (size_t)(kt % 3) * STAGEB;
#pragma unroll
        for (int s16 = 0; s16 < 2; s16++) {
            const uint32_t ks = (uint32_t)(s16 * 32);
            uint32_t bf[7][2];
            ldsm4(bf[0][0], bf[0][1], bf[1][0], bf[1][1], stb + bB + ks);
            ldsm4(bf[2][0], bf[2][1], bf[3][0], bf[3][1], stb + bB + 1280 + ks);
            ldsm4(bf[4][0], bf[4][1], bf[5][0], bf[5][1], stb + bB + 2560 + ks);
            ldsm2(bf[6][0], bf[6][1], stb + bB6 + ks);
#pragma unroll
            for (int mt = 0; mt < 2; mt++) {
                uint32_t a0, a1, a2, a3;
                if (CVTA) {
                    const char* ap = stc + (warpM * 32 + grp) * 144
                                   + mt * 16 * 144 + s16 * 64 + qid * 8;
                    float2 p0 = *(const float2*)ap;
                    float2 p1 = *(const float2*)(ap + 1152);
                    float2 p2 = *(const float2*)(ap + 32);
                    float2 p3 = *(const float2*)(ap + 1184);
                    a0 = packh2(p0.x, p0.y);
                    a1 = packh2(p1.x, p1.y);
                    a2 = packh2(p2.x, p2.y);
                    a3 = packh2(p3.x, p3.y);
                } else {
                    ldsm4(a0, a1, a2, a3, stb + aB + (uint32_t)(mt * 1280) + ks);
                }
#pragma unroll
                for (int nt = 0; nt < 7; nt++)
                    mma_f16(acc[mt][nt][0], acc[mt][nt][1],
                            acc[mt][nt][2], acc[mt][nt][3],
                            a0, a1, a2, a3, bf[nt][0], bf[nt][1]);
            }
        }
    }

    // ---- MODE 3: fold 1/n scaling into epilogue ----
    float sc0[2], sc1[2];
#pragma unroll
    for (int mt = 0; mt < 2; mt++) {
        int r = row0 + warpM * 32 + mt * 16 + grp;
        sc0[mt] = (MODE == 3 && r < S_) ? g_invN[r] : 1.0f;
        sc1[mt] = (MODE == 3 && r + 8 < S_) ? g_invN[r + 8] : 1.0f;
    }

    // ---- epilogue ----
    if (MODE == 2) {
        __syncthreads();   // all warps done reading stage buffers before reuse
        float* ep = (float*)smemc;                 // 64 x 116 floats
        int* sample    = (int*)(ep + BM * EPSTR);
        int* segstart  = sample + BM;
        int* segsample = segstart + BM + 1;
        int* pnseg     = segsample + BM;
#pragma unroll
        for (int mt = 0; mt < 2; mt++) {
            int r = warpM * 32 + mt * 16 + grp;
#pragma unroll
            for (int nt = 0; nt < 7; nt++) {
                int c = warpN * 56 + nt * 8 + 2 * qid;
                int gcol = yoff + c;
                float b0 = (gcol < NW) ? bias[gcol] : 0.0f;
                float b1 = (gcol + 1 < NW) ? bias[gcol + 1] : 0.0f;
                *(float2*)(ep + r * EPSTR + c) =
                    make_float2(fmaxf(acc[mt][nt][0] + b0, 0.0f),
                                fmaxf(acc[mt][nt][1] + b1, 0.0f));
                *(float2*)(ep + (r + 8) * EPSTR + c) =
                    make_float2(fmaxf(acc[mt][nt][2] + b0, 0.0f),
                                fmaxf(acc[mt][nt][3] + b1, 0.0f));
            }
        }
        if (t < BM) {
            int g = row0 + t;
            sample[t] = (g < nrows) ? (g_rowmap[g] >> 5) : -1;
        }
        __syncthreads();
        if (t == 0) {
            int lim = nrows - row0; if (lim > BM) lim = BM;
            int ns = 0, cur = -2;
            for (int r = 0; r < lim; r++) {
                int s = sample[r];
                if (s != cur) { segstart[ns] = r; segsample[ns] = s; ns++; cur = s; }
            }
            segstart[ns] = lim;
            *pnseg = ns;
        }
        __syncthreads();
        if (t < 112) {
            int gcol = yoff + t;
            if (gcol < D_) {
                int ns = *pnseg;
                for (int seg = 0; seg < ns; seg++) {
                    float s = 0.0f;
                    int e = segstart[seg + 1];
                    for (int r = segstart[seg]; r < e; r++) s += ep[r * EPSTR + t];
                    atomicAdd(&g_pooled[(size_t)segsample[seg] * D_ + gcol], s);
                }
            }
        }
    } else {
#pragma unroll
        for (int mt = 0; mt < 2; mt++) {
            int r = row0 + warpM * 32 + mt * 16 + grp;
#pragma unroll
            for (int nt = 0; nt < 7; nt++) {
                int gcol = yoff + warpN * 56 + nt * 8 + 2 * qid;
                if (gcol >= NW) continue;
                float b0 = bias[gcol];
                float b1 = bias[gcol + 1];
                float v0 = fmaxf(acc[mt][nt][0] * sc0[mt] + b0, 0.0f);
                float v1 = fmaxf(acc[mt][nt][1] * sc0[mt] + b1, 0.0f);
                float v2 = fmaxf(acc[mt][nt][2] * sc1[mt] + b0, 0.0f);
                float v3 = fmaxf(acc[mt][nt][3] * sc1[mt] + b1, 0.0f);
                if (MODE == 4) {
                    if (r < nrows)
                        *(float2*)(OutExt + (size_t)r * D_ + gcol) = make_float2(v0, v1);
                    if (r + 8 < nrows)
                        *(float2*)(OutExt + (size_t)(r + 8) * D_ + gcol) = make_float2(v2, v3);
                } else {
                    __half* OH = (MODE == 1) ? g_H1h : g_Yh;
                    const int ost = (MODE == 1) ? KP_ : H_;
                    if (r < nrows)
                        *(uint32_t*)(OH + (size_t)r * ost + gcol) = packh2(v0, v1);
                    if (r + 8 < nrows)
                        *(uint32_t*)(OH + (size_t)(r + 8) * ost + gcol) = packh2(v2, v3);
                }
            }
        }
    }
}

// ---------------------------------------------------------------------------------
extern "C" void kernel_launch(void* const* d_in, const int* in_sizes, int n_in,
                              void* d_out, int out_size) {
    (void)in_sizes; (void)n_in; (void)out_size;
    const float* all_x     = (const float*)d_in[0];
    const int*   numInputs = (const int*)  d_in[1];
    const float* W1 = (const float*)d_in[2];
    const float* b1 = (const float*)d_in[3];
    const float* W2 = (const float*)d_in[4];
    const float* b2 = (const float*)d_in[5];
    const float* W3 = (const float*)d_in[6];
    const float* b3 = (const float*)d_in[7];
    const float* W4 = (const float*)d_in[8];
    const float* b4 = (const float*)d_in[9];
    float* out = (float*)d_out;

    const int SMEM_CVT = 3 * (64 * 36 * 4 + 112 * 40 * 2);   // 54528 (modes 1,3)
    const int SMEM_H   = 3 * (64 * 40 * 2 + 112 * 40 * 2);   // 42240 (modes 2,4)
    cudaFuncSetAttribute(gemm_h<1, D_, true>,  cudaFuncAttributeMaxDynamicSharedMemorySize, SMEM_CVT);
    cudaFuncSetAttribute(gemm_h<2, D_, false>, cudaFuncAttributeMaxDynamicSharedMemorySize, SMEM_H);
    cudaFuncSetAttribute(gemm_h<3, D_, true>,  cudaFuncAttributeMaxDynamicSharedMemorySize, SMEM_CVT);
    cudaFuncSetAttribute(gemm_h<4, H_, false>, cudaFuncAttributeMaxDynamicSharedMemorySize, SMEM_H);

    setup_kernel<<<1, 256>>>(numInputs);
    {
        int total = S_ * D_ + 2 * D_ * KP_ + H_ * KP_ + D_ * H_ + S_ * M_ * 4;
        prep_kernel<<<(total + 255) / 256, 256>>>(W1, W2, W3, W4);
    }

    // layer 1: H1 = relu(X_active @ W1^T + b1)     [nact, 420] -> fp16 (stride KP_)
    gemm_h<1, D_, true><<<dim3((S_ * M_ + 63) / 64, 4), 128, SMEM_CVT>>>(all_x, b1, nullptr);
    // layer 2 + ragged sum-pool into g_pooled      [nact, 420] -> [S, 420]
    gemm_h<2, D_, false><<<dim3((S_ * M_ + 63) / 64, 4), 128, SMEM_H>>>(nullptr, b2, nullptr);
    // layer 3: Y = relu((pooled @ W3^T)/n + b3)    [S, 840] -> fp16
    gemm_h<3, D_, true><<<dim3(S_ / 64, 8), 128, SMEM_CVT>>>(nullptr, b3, nullptr);
    // layer 4: out = relu(Y @ W4^T + b4)           [S, 420]
    gemm_h<4, H_, false><<<dim3(S_ / 64, 4), 128, SMEM_H>>>(nullptr, b4, out);
}

// round 13
// speedup vs baseline: 5.2453x; 1.0524x over previous
#include <cuda_runtime.h>
#include <cuda_fp16.h>
#include <cstdint>

#define S_ 4096
#define M_ 32
#define D_ 420
#define H_ 840
#define KP_ 424   // padded fp16 K-stride for K=420 rows (848B, 16B-aligned)

// ------------- scratch (static device globals; 256B-aligned for cp.async) --------
__device__ __align__(256) int    g_rowmap[S_ * M_];             // compact row -> s*32+m
__device__ int    g_nact;                                       // number of active rows
__device__ __align__(256) float  g_invN[S_];                    // 1/numInputs[s]
__device__ __align__(256) __half g_H1h[(size_t)S_ * M_ * KP_];  // layer-1 out (fp16, padded K)
__device__ __align__(256) float  g_pooled[(size_t)S_ * D_];     // ragged-mean numerator
__device__ __align__(256) __half g_Yh[(size_t)S_ * H_];         // layer-3 out (fp16)
__device__ __align__(256) __half g_W1h[D_ * KP_];               // fp16 weights [N][KP]
__device__ __align__(256) __half g_W2h[D_ * KP_];
__device__ __align__(256) __half g_W3h[H_ * KP_];
__device__ __align__(256) __half g_W4h[D_ * H_];                // K=840, natural

__device__ __forceinline__ uint32_t packh2(float lo, float hi) {
    uint32_t r;
    asm("cvt.rn.f16x2.f32 %0, %1, %2;" : "=r"(r) : "f"(hi), "f"(lo));
    return r;
}
__device__ __forceinline__ void mma_f16(float& d0, float& d1, float& d2, float& d3,
                                        uint32_t a0, uint32_t a1, uint32_t a2,
                                        uint32_t a3, uint32_t b0, uint32_t b1) {
    asm volatile(
        "mma.sync.aligned.m16n8k16.row.col.f32.f16.f16.f32 "
        "{%0,%1,%2,%3}, {%4,%5,%6,%7}, {%8,%9}, {%0,%1,%2,%3};"
        : "+f"(d0), "+f"(d1), "+f"(d2), "+f"(d3)
        : "r"(a0), "r"(a1), "r"(a2), "r"(a3), "r"(b0), "r"(b1));
}
__device__ __forceinline__ void ldsm4(uint32_t& r0, uint32_t& r1, uint32_t& r2,
                                      uint32_t& r3, uint32_t addr) {
    asm volatile("ldmatrix.sync.aligned.m8n8.x4.shared.b16 {%0,%1,%2,%3}, [%4];"
                 : "=r"(r0), "=r"(r1), "=r"(r2), "=r"(r3) : "r"(addr));
}
__device__ __forceinline__ void ldsm2(uint32_t& r0, uint32_t& r1, uint32_t addr) {
    asm volatile("ldmatrix.sync.aligned.m8n8.x2.shared.b16 {%0,%1}, [%2];"
                 : "=r"(r0), "=r"(r1) : "r"(addr));
}
__device__ __forceinline__ uint32_t smem_u32(const void* p) {
    uint32_t a;
    asm("{ .reg .u64 t; cvta.to.shared.u64 t, %1; cvt.u32.u64 %0, t; }"
        : "=r"(a) : "l"(p));
    return a;
}
__device__ __forceinline__ void cp16(uint32_t dst, const void* src, uint32_t srcsz) {
    asm volatile("cp.async.cg.shared.global [%0], [%1], 16, %2;"
                 :: "r"(dst), "l"(src), "r"(srcsz) : "memory");
}
#define CP_COMMIT() asm volatile("cp.async.commit_group;" ::: "memory")
#define CP_WAIT(n)  asm volatile("cp.async.wait_group %0;" :: "n"(n) : "memory")

// ---------------- setup: prefix-scan numInputs, build compact row map -------------
__global__ void setup_kernel(const int* __restrict__ numInputs) {
    __shared__ int s_warp[8];
    __shared__ int s_woff[8];
    int t = threadIdx.x;
    int base = t * 16;
    int local[16];
    int run = 0;
#pragma unroll
    for (int j = 0; j < 16; j++) { local[j] = run; run += numInputs[base + j]; }
    int lane = t & 31, warp = t >> 5;
    int inc = run;
#pragma unroll
    for (int o = 1; o < 32; o <<= 1) {
        int v = __shfl_up_sync(0xffffffffu, inc, o);
        if (lane >= o) inc += v;
    }
    if (lane == 31) s_warp[warp] = inc;
    __syncthreads();
    if (t == 0) {
        int r = 0;
        for (int w = 0; w < 8; w++) { s_woff[w] = r; r += s_warp[w]; }
        g_nact = r;
    }
    __syncthreads();
    int thrOff = s_woff[warp] + (inc - run);
    for (int j = 0; j < 16; j++) {
        int s = base + j;
        int n = numInputs[s];
        g_invN[s] = 1.0f / (float)n;
        int off = thrOff + local[j];
        for (int m = 0; m < n; m++) g_rowmap[off + m] = s * M_ + m;
    }
}

// fused prep: zero g_pooled, convert weights to fp16 (padded stride, pad zeroed),
// and zero the K-pad of g_H1h (cols 420..423 of every row).
__global__ void prep_kernel(const float* __restrict__ W1, const float* __restrict__ W2,
                            const float* __restrict__ W3, const float* __restrict__ W4) {
    const int NP = S_ * D_;
    const int NW12 = D_ * KP_, NW3 = H_ * KP_, NW4 = D_ * H_;
    const int NH1P = S_ * M_ * 4;                 // pad elems of g_H1h
    int i = blockIdx.x * blockDim.x + threadIdx.x;
    if (i < NP) { g_pooled[i] = 0.0f; return; }
    i -= NP;
    if (i < NW12) {
        int r = i / KP_, c = i - r * KP_;
        g_W1h[i] = (c < D_) ? __float2half_rn(W1[r * D_ + c]) : __half(0.0f);
        return;
    }
    i -= NW12;
    if (i < NW12) {
        int r = i / KP_, c = i - r * KP_;
        g_W2h[i] = (c < D_) ? __float2half_rn(W2[r * D_ + c]) : __half(0.0f);
        return;
    }
    i -= NW12;
    if (i < NW3) {
        int r = i / KP_, c = i - r * KP_;
        g_W3h[i] = (c < D_) ? __float2half_rn(W3[r * D_ + c]) : __half(0.0f);
        return;
    }
    i -= NW3;
    if (i < NW4) { g_W4h[i] = __float2half_rn(W4[i]); return; }
    i -= NW4;
    if (i < NH1P) {
        int r = i >> 2, c = i & 3;
        g_H1h[(size_t)r * KP_ + D_ + c] = __half(0.0f);
    }
}

// ---------------- fp16 mma GEMM, BM=128, warp tile 64x56 --------------------------
// MODE 1 (CVTA): A = all_x fp32 gathered -> g_H1h (fp16, stride KP_), rows = g_nact
// MODE 2:        A = g_H1h fp16, epilogue = segmented reduce + atomicAdd g_pooled
// MODE 3 (CVTA): A = g_pooled fp32, 1/n in epilogue -> g_Yh (fp16), rows = S
// MODE 4:        A = g_Yh fp16 -> d_out fp32, rows = S
//
// CTA = 128 threads, 4 warps 2Mx2N, BM=128, BN=112, BK=32, warp tile 64x56
// (acc = 112 regs) -> 29.9 FLOP per smem byte, ~1.5x the old 32x56 tile.
template <int MODE, int K, bool CVTA>
__global__ void __launch_bounds__(128, CVTA ? 2 : 3)
gemm_h(const float* __restrict__ Aext, const float* __restrict__ bias,
       float* __restrict__ OutExt) {
    constexpr int BM = 128, BK = 32;
    constexpr int KT = (K + BK - 1) / BK;
    constexpr int NW  = (MODE == 3) ? H_ : D_;
    constexpr int ASTF = D_;                       // fp32 A row stride (modes 1,3)
    constexpr int ASTH = (MODE == 4) ? H_ : KP_;   // fp16 A row stride (modes 2,4)
    constexpr int WST  = (MODE == 4) ? H_ : KP_;   // weight row stride
    constexpr int KLIM = (MODE == 4) ? H_ : KP_;   // aligned copy limit (pad zeroed)
    constexpr int ATILEB = CVTA ? (BM * 144) : (BM * 80);   // 18432 : 10240
    constexpr int BTILEB = 112 * 80;                        // 8960
    constexpr int STAGEB = ATILEB + BTILEB;
    constexpr int EPSTR = 116;

    extern __shared__ __align__(16) char smemc[];
    const uint32_t sb = smem_u32(smemc);

    const int nrows = (MODE <= 2) ? g_nact : S_;
    const int row0 = blockIdx.x * BM;
    if (row0 >= nrows) return;
    const int yoff = blockIdx.y * 112;

    const float*  ApF = (MODE == 1) ? Aext : g_pooled;
    const __half* ApH = (MODE == 2) ? g_H1h : g_Yh;
    const __half* Wh  = (MODE == 1) ? g_W1h : (MODE == 2) ? g_W2h
                      : (MODE == 3) ? g_W3h : g_W4h;

    const int t = threadIdx.x, lane = t & 31, wid = t >> 5;
    const int warpM = wid & 1, warpN = wid >> 1;
    const int grp = lane >> 2, qid = lane & 3;
    const int r8 = lane & 7, sub = lane >> 3;      // ldmatrix lane decomposition

    // ---- ldmatrix per-lane base offsets (relative to stage start) ----
    const uint32_t bB = (uint32_t)(ATILEB + (warpN * 56 + (sub >> 1) * 8 + r8) * 80
                                   + (sub & 1) * 16);
    const uint32_t bB6 = (uint32_t)(ATILEB + (warpN * 56 + 48 + r8) * 80
                                    + (sub & 1) * 16);
    const uint32_t aB = (uint32_t)((warpM * 64 + (sub & 1) * 8 + r8) * 80
                                   + (sub >> 1) * 16);

    // ---- A copy descriptors (kept in regs; B recomputed in issue) ----
    const void* asrc[CVTA ? 8 : 4]; bool avalid[CVTA ? 8 : 4];
    if (CVTA) {
#pragma unroll
        for (int i = 0; i < 8; i++) {
            int idx = i * 128 + t;            // 0..1023 = 128 rows x 8 granules
            int m = idx >> 3, g = idx & 7;    // granule = 4 floats
            int grow = row0 + m;
            avalid[i] = grow < nrows;
            int arow = avalid[i] ? ((MODE == 1) ? g_rowmap[grow] : grow) : 0;
            asrc[i] = ApF + (size_t)arow * ASTF + g * 4;
        }
    } else {
#pragma unroll
        for (int i = 0; i < 4; i++) {
            int idx = i * 128 + t;            // 0..511 = 128 rows x 4 granules
            int m = idx >> 2, g = idx & 3;    // granule = 8 halfs
            int grow = row0 + m;
            avalid[i] = grow < nrows;
            asrc[i] = ApH + (size_t)(avalid[i] ? grow : 0) * ASTH + g * 8;
        }
    }

    auto issue = [&](int kt) {
        const uint32_t sbase = sb + (uint32_t)(kt % 3) * STAGEB;
        const int kb = kt * BK;
        if (CVTA) {
#pragma unroll
            for (int i = 0; i < 8; i++) {
                int idx = i * 128 + t;
                int m = idx >> 3, g = idx & 7;
                uint32_t sz = (avalid[i] && (kb + g * 4) < K) ? 16u : 0u;
                cp16(sbase + (uint32_t)(m * 144 + g * 16),
                     (const float*)asrc[i] + kb, sz);
            }
        } else {
#pragma unroll
            for (int i = 0; i < 4; i++) {
                int idx = i * 128 + t;
                int m = idx >> 2, g = idx & 3;
                uint32_t sz = (avalid[i] && (kb + g * 8 + 8) <= KLIM) ? 16u : 0u;
                cp16(sbase + (uint32_t)(m * 80 + g * 16),
                     (const __half*)asrc[i] + kb, sz);
            }
        }
        // B tile: 112 rows x 4 granules = 448 slots; idx >= 448 must not issue.
#pragma unroll
        for (int i = 0; i < 4; i++) {
            int idx = i * 128 + t;
            if (idx < 448) {
                int n = idx >> 2, g = idx & 3;
                int gcol = yoff + n;
                bool v = gcol < NW;
                uint32_t sz = (v && (kb + g * 8 + 8) <= KLIM) ? 16u : 0u;
                cp16(sbase + (uint32_t)(ATILEB + n * 80 + g * 16),
                     Wh + (size_t)(v ? gcol : 0) * WST + g * 8 + kb, sz);
            }
        }
        CP_COMMIT();
    };

    float acc[4][7][4];
#pragma unroll
    for (int mt = 0; mt < 4; mt++)
#pragma unroll
        for (int nt = 0; nt < 7; nt++)
#pragma unroll
            for (int c = 0; c < 4; c++) acc[mt][nt][c] = 0.0f;

    issue(0);
    issue(1);
    for (int kt = 0; kt < KT; kt++) {
        if (kt + 1 < KT) { CP_WAIT(1); } else { CP_WAIT(0); }
        __syncthreads();
        if (kt + 2 < KT) issue(kt + 2);

        const uint32_t stb = sb + (uint32_t)(kt % 3) * STAGEB;
        const char* stc = smemc + (size_t)(kt % 3) * STAGEB;
#pragma unroll
        for (int s16 = 0; s16 < 2; s16++) {
            const uint32_t ks = (uint32_t)(s16 * 32);
            uint32_t bf[7][2];
            ldsm4(bf[0][0], bf[0][1], bf[1][0], bf[1][1], stb + bB + ks);
            ldsm4(bf[2][0], bf[2][1], bf[3][0], bf[3][1], stb + bB + 1280 + ks);
            ldsm4(bf[4][0], bf[4][1], bf[5][0], bf[5][1], stb + bB + 2560 + ks);
            ldsm2(bf[6][0], bf[6][1], stb + bB6 + ks);
#pragma unroll
            for (int mt = 0; mt < 4; mt++) {
                uint32_t a0, a1, a2, a3;
                if (CVTA) {
                    const char* ap = stc + (warpM * 64 + grp) * 144
                                   + mt * 16 * 144 + s16 * 64 + qid * 8;
                    float2 p0 = *(const float2*)ap;
                    float2 p1 = *(const float2*)(ap + 1152);
                    float2 p2 = *(const float2*)(ap + 32);
                    float2 p3 = *(const float2*)(ap + 1184);
                    a0 = packh2(p0.x, p0.y);
                    a1 = packh2(p1.x, p1.y);
                    a2 = packh2(p2.x, p2.y);
                    a3 = packh2(p3.x, p3.y);
                } else {
                    ldsm4(a0, a1, a2, a3, stb + aB + (uint32_t)(mt * 1280) + ks);
                }
#pragma unroll
                for (int nt = 0; nt < 7; nt++)
                    mma_f16(acc[mt][nt][0], acc[mt][nt][1],
                            acc[mt][nt][2], acc[mt][nt][3],
                            a0, a1, a2, a3, bf[nt][0], bf[nt][1]);
            }
        }
    }

    // ---- MODE 3: fold 1/n scaling into epilogue ----
    float sc0[4], sc1[4];
#pragma unroll
    for (int mt = 0; mt < 4; mt++) {
        int r = row0 + warpM * 64 + mt * 16 + grp;
        sc0[mt] = (MODE == 3 && r < S_) ? g_invN[r] : 1.0f;
        sc1[mt] = (MODE == 3 && r + 8 < S_) ? g_invN[r + 8] : 1.0f;
    }

    // ---- epilogue ----
    if (MODE == 2) {
        __syncthreads();   // all warps done reading stage buffers before reuse
        float* ep = (float*)smemc;                 // 128 x 116 floats
        int* sample    = (int*)(ep + BM * EPSTR);
        int* segstart  = sample + BM;
        int* segsample = segstart + BM + 1;
        int* pnseg     = segsample + BM;
#pragma unroll
        for (int mt = 0; mt < 4; mt++) {
            int r = warpM * 64 + mt * 16 + grp;
#pragma unroll
            for (int nt = 0; nt < 7; nt++) {
                int c = warpN * 56 + nt * 8 + 2 * qid;
                int gcol = yoff + c;
                float b0 = (gcol < NW) ? bias[gcol] : 0.0f;
                float b1 = (gcol + 1 < NW) ? bias[gcol + 1] : 0.0f;
                *(float2*)(ep + r * EPSTR + c) =
                    make_float2(fmaxf(acc[mt][nt][0] + b0, 0.0f),
                                fmaxf(acc[mt][nt][1] + b1, 0.0f));
                *(float2*)(ep + (r + 8) * EPSTR + c) =
                    make_float2(fmaxf(acc[mt][nt][2] + b0, 0.0f),
                                fmaxf(acc[mt][nt][3] + b1, 0.0f));
            }
        }
        if (t < BM) {
            int g = row0 + t;
            sample[t] = (g < nrows) ? (g_rowmap[g] >> 5) : -1;
        }
        __syncthreads();
        if (t == 0) {
            int lim = nrows - row0; if (lim > BM) lim = BM;
            int ns = 0, cur = -2;
            for (int r = 0; r < lim; r++) {
                int s = sample[r];
                if (s != cur) { segstart[ns] = r; segsample[ns] = s; ns++; cur = s; }
            }
            segstart[ns] = lim;
            *pnseg = ns;
        }
        __syncthreads();
        if (t < 112) {
            int gcol = yoff + t;
            if (gcol < D_) {
                int ns = *pnseg;
                for (int seg = 0; seg < ns; seg++) {
                    float s = 0.0f;
                    int e = segstart[seg + 1];
                    for (int r = segstart[seg]; r < e; r++) s += ep[r * EPSTR + t];
                    atomicAdd(&g_pooled[(size_t)segsample[seg] * D_ + gcol], s);
                }
            }
        }
    } else {
#pragma unroll
        for (int mt = 0; mt < 4; mt++) {
            int r = row0 + warpM * 64 + mt * 16 + grp;
#pragma unroll
            for (int nt = 0; nt < 7; nt++) {
                int gcol = yoff + warpN * 56 + nt * 8 + 2 * qid;
                if (gcol >= NW) continue;
                float b0 = bias[gcol];
                float b1 = bias[gcol + 1];
                float v0 = fmaxf(acc[mt][nt][0] * sc0[mt] + b0, 0.0f);
                float v1 = fmaxf(acc[mt][nt][1] * sc0[mt] + b1, 0.0f);
                float v2 = fmaxf(acc[mt][nt][2] * sc1[mt] + b0, 0.0f);
                float v3 = fmaxf(acc[mt][nt][3] * sc1[mt] + b1, 0.0f);
                if (MODE == 4) {
                    if (r < nrows)
                        *(float2*)(OutExt + (size_t)r * D_ + gcol) = make_float2(v0, v1);
                    if (r + 8 < nrows)
                        *(float2*)(OutExt + (size_t)(r + 8) * D_ + gcol) = make_float2(v2, v3);
                } else {
                    __half* OH = (MODE == 1) ? g_H1h : g_Yh;
                    const int ost = (MODE == 1) ? KP_ : H_;
                    if (r < nrows)
                        *(uint32_t*)(OH + (size_t)r * ost + gcol) = packh2(v0, v1);
                    if (r + 8 < nrows)
                        *(uint32_t*)(OH + (size_t)(r + 8) * ost + gcol) = packh2(v2, v3);
                }
            }
        }
    }
}

// ---------------------------------------------------------------------------------
extern "C" void kernel_launch(void* const* d_in, const int* in_sizes, int n_in,
                              void* d_out, int out_size) {
    (void)in_sizes; (void)n_in; (void)out_size;
    const float* all_x     = (const float*)d_in[0];
    const int*   numInputs = (const int*)  d_in[1];
    const float* W1 = (const float*)d_in[2];
    const float* b1 = (const float*)d_in[3];
    const float* W2 = (const float*)d_in[4];
    const float* b2 = (const float*)d_in[5];
    const float* W3 = (const float*)d_in[6];
    const float* b3 = (const float*)d_in[7];
    const float* W4 = (const float*)d_in[8];
    const float* b4 = (const float*)d_in[9];
    float* out = (float*)d_out;

    const int SMEM_CVT = 3 * (128 * 144 + 112 * 80);   // 82176 (modes 1,3)
    const int SMEM_H   = 3 * (128 * 80 + 112 * 80);    // 57600 (mode 4)
    const int SMEM_M2  = 61440;                        // mode 2 (max of stages, ep stage)
    cudaFuncSetAttribute(gemm_h<1, D_, true>,  cudaFuncAttributeMaxDynamicSharedMemorySize, SMEM_CVT);
    cudaFuncSetAttribute(gemm_h<2, D_, false>, cudaFuncAttributeMaxDynamicSharedMemorySize, SMEM_M2);
    cudaFuncSetAttribute(gemm_h<3, D_, true>,  cudaFuncAttributeMaxDynamicSharedMemorySize, SMEM_CVT);
    cudaFuncSetAttribute(gemm_h<4, H_, false>, cudaFuncAttributeMaxDynamicSharedMemorySize, SMEM_H);

    setup_kernel<<<1, 256>>>(numInputs);
    {
        int total = S_ * D_ + 2 * D_ * KP_ + H_ * KP_ + D_ * H_ + S_ * M_ * 4;
        prep_kernel<<<(total + 255) / 256, 256>>>(W1, W2, W3, W4);
    }

    // layer 1: H1 = relu(X_active @ W1^T + b1)     [nact, 420] -> fp16 (stride KP_)
    gemm_h<1, D_, true><<<dim3((S_ * M_ + 127) / 128, 4), 128, SMEM_CVT>>>(all_x, b1, nullptr);
    // layer 2 + ragged sum-pool into g_pooled      [nact, 420] -> [S, 420]
    gemm_h<2, D_, false><<<dim3((S_ * M_ + 127) / 128, 4), 128, SMEM_M2>>>(nullptr, b2, nullptr);
    // layer 3: Y = relu((pooled @ W3^T)/n + b3)    [S, 840] -> fp16
    gemm_h<3, D_, true><<<dim3(S_ / 128, 8), 128, SMEM_CVT>>>(nullptr, b3, nullptr);
    // layer 4: out = relu(Y @ W4^T + b4)           [S, 420]
    gemm_h<4, H_, false><<<dim3(S_ / 128, 4), 128, SMEM_H>>>(nullptr, b4, out);
}

// round 14
// speedup vs baseline: 5.3290x; 1.0160x over previous
#include <cuda_runtime.h>
#include <cuda_fp16.h>
#include <cstdint>

#define S_ 4096
#define M_ 32
#define D_ 420
#define H_ 840
#define KP_ 424   // padded fp16 K-stride for K=420 rows (848B, 16B-aligned)

// ------------- scratch (static device globals; 256B-aligned for cp.async) --------
__device__ __align__(256) int    g_rowmap[S_ * M_];             // compact row -> s*32+m
__device__ int    g_nact;                                       // number of active rows
__device__ __align__(256) float  g_invN[S_];                    // 1/numInputs[s]
__device__ __align__(256) __half g_H1h[(size_t)S_ * M_ * KP_];  // layer-1 out (fp16, padded K)
__device__ __align__(256) float  g_pooled[(size_t)S_ * D_];     // ragged-mean numerator
__device__ __align__(256) __half g_Yh[(size_t)S_ * H_];         // layer-3 out (fp16)
__device__ __align__(256) __half g_W1h[D_ * KP_];               // fp16 weights [N][KP]
__device__ __align__(256) __half g_W2h[D_ * KP_];
__device__ __align__(256) __half g_W3h[H_ * KP_];
__device__ __align__(256) __half g_W4h[D_ * H_];                // K=840, natural

__device__ __forceinline__ uint32_t packh2(float lo, float hi) {
    uint32_t r;
    asm("cvt.rn.f16x2.f32 %0, %1, %2;" : "=r"(r) : "f"(hi), "f"(lo));
    return r;
}
__device__ __forceinline__ void mma_f16(float& d0, float& d1, float& d2, float& d3,
                                        uint32_t a0, uint32_t a1, uint32_t a2,
                                        uint32_t a3, uint32_t b0, uint32_t b1) {
    asm volatile(
        "mma.sync.aligned.m16n8k16.row.col.f32.f16.f16.f32 "
        "{%0,%1,%2,%3}, {%4,%5,%6,%7}, {%8,%9}, {%0,%1,%2,%3};"
        : "+f"(d0), "+f"(d1), "+f"(d2), "+f"(d3)
        : "r"(a0), "r"(a1), "r"(a2), "r"(a3), "r"(b0), "r"(b1));
}
__device__ __forceinline__ void ldsm4(uint32_t& r0, uint32_t& r1, uint32_t& r2,
                                      uint32_t& r3, uint32_t addr) {
    asm volatile("ldmatrix.sync.aligned.m8n8.x4.shared.b16 {%0,%1,%2,%3}, [%4];"
                 : "=r"(r0), "=r"(r1), "=r"(r2), "=r"(r3) : "r"(addr));
}
__device__ __forceinline__ void ldsm2(uint32_t& r0, uint32_t& r1, uint32_t addr) {
    asm volatile("ldmatrix.sync.aligned.m8n8.x2.shared.b16 {%0,%1}, [%2];"
                 : "=r"(r0), "=r"(r1) : "r"(addr));
}
__device__ __forceinline__ uint32_t smem_u32(const void* p) {
    uint32_t a;
    asm("{ .reg .u64 t; cvta.to.shared.u64 t, %1; cvt.u32.u64 %0, t; }"
        : "=r"(a) : "l"(p));
    return a;
}
__device__ __forceinline__ void cp16(uint32_t dst, const void* src, uint32_t srcsz) {
    asm volatile("cp.async.cg.shared.global [%0], [%1], 16, %2;"
                 :: "r"(dst), "l"(src), "r"(srcsz) : "memory");
}
#define CP_COMMIT() asm volatile("cp.async.commit_group;" ::: "memory")
#define CP_WAIT(n)  asm volatile("cp.async.wait_group %0;" :: "n"(n) : "memory")

// ---------------- setup: prefix-scan numInputs, build compact row map -------------
__global__ void setup_kernel(const int* __restrict__ numInputs) {
    __shared__ int s_warp[8];
    __shared__ int s_woff[8];
    int t = threadIdx.x;
    int base = t * 16;
    int local[16];
    int run = 0;
#pragma unroll
    for (int j = 0; j < 16; j++) { local[j] = run; run += numInputs[base + j]; }
    int lane = t & 31, warp = t >> 5;
    int inc = run;
#pragma unroll
    for (int o = 1; o < 32; o <<= 1) {
        int v = __shfl_up_sync(0xffffffffu, inc, o);
        if (lane >= o) inc += v;
    }
    if (lane == 31) s_warp[warp] = inc;
    __syncthreads();
    if (t == 0) {
        int r = 0;
        for (int w = 0; w < 8; w++) { s_woff[w] = r; r += s_warp[w]; }
        g_nact = r;
    }
    __syncthreads();
    int thrOff = s_woff[warp] + (inc - run);
    for (int j = 0; j < 16; j++) {
        int s = base + j;
        int n = numInputs[s];
        g_invN[s] = 1.0f / (float)n;
        int off = thrOff + local[j];
        for (int m = 0; m < n; m++) g_rowmap[off + m] = s * M_ + m;
    }
}

// fused prep: zero g_pooled, convert weights to fp16 (padded stride, pad zeroed),
// and zero the K-pad of g_H1h (cols 420..423 of every row).
__global__ void prep_kernel(const float* __restrict__ W1, const float* __restrict__ W2,
                            const float* __restrict__ W3, const float* __restrict__ W4) {
    const int NP = S_ * D_;
    const int NW12 = D_ * KP_, NW3 = H_ * KP_, NW4 = D_ * H_;
    const int NH1P = S_ * M_ * 4;                 // pad elems of g_H1h
    int i = blockIdx.x * blockDim.x + threadIdx.x;
    if (i < NP) { g_pooled[i] = 0.0f; return; }
    i -= NP;
    if (i < NW12) {
        int r = i / KP_, c = i - r * KP_;
        g_W1h[i] = (c < D_) ? __float2half_rn(W1[r * D_ + c]) : __half(0.0f);
        return;
    }
    i -= NW12;
    if (i < NW12) {
        int r = i / KP_, c = i - r * KP_;
        g_W2h[i] = (c < D_) ? __float2half_rn(W2[r * D_ + c]) : __half(0.0f);
        return;
    }
    i -= NW12;
    if (i < NW3) {
        int r = i / KP_, c = i - r * KP_;
        g_W3h[i] = (c < D_) ? __float2half_rn(W3[r * D_ + c]) : __half(0.0f);
        return;
    }
    i -= NW3;
    if (i < NW4) { g_W4h[i] = __float2half_rn(W4[i]); return; }
    i -= NW4;
    if (i < NH1P) {
        int r = i >> 2, c = i & 3;
        g_H1h[(size_t)r * KP_ + D_ + c] = __half(0.0f);
    }
}

// ---------------- fp16 mma GEMM, BM=128, BK=64, warp tile 64x56 -------------------
// MODE 1 (CVTA): A = all_x fp32 gathered -> g_H1h (fp16, stride KP_), rows = g_nact
// MODE 2:        A = g_H1h fp16, epilogue = segmented reduce + atomicAdd g_pooled
// MODE 3 (CVTA): A = g_pooled fp32, 1/n in epilogue -> g_Yh (fp16), rows = S
// MODE 4:        A = g_Yh fp16 -> d_out fp32, rows = S
//
// CTA = 128 threads, 4 warps 2Mx2N, BM=128, BN=112, BK=64, warp tile 64x56.
// 2-stage cp.async pipeline (3 CTAs/SM in fp16-A modes). Row strides: fp16 144B,
// fp32 272B (both ≡16 mod 128 -> conflict-free ldmatrix / float2 loads).
template <int MODE, int K, bool CVTA>
__global__ void __launch_bounds__(128, CVTA ? 2 : 3)
gemm_h(const float* __restrict__ Aext, const float* __restrict__ bias,
       float* __restrict__ OutExt) {
    constexpr int BM = 128, BK = 64;
    constexpr int KT = (K + BK - 1) / BK;
    constexpr int NW  = (MODE == 3) ? H_ : D_;
    constexpr int ASTF = D_;                       // fp32 A row stride (modes 1,3)
    constexpr int ASTH = (MODE == 4) ? H_ : KP_;   // fp16 A row stride (modes 2,4)
    constexpr int WST  = (MODE == 4) ? H_ : KP_;   // weight row stride
    constexpr int KLIM = (MODE == 4) ? H_ : KP_;   // aligned copy limit (pad zeroed)
    constexpr int ARSTR = CVTA ? 272 : 144;        // smem A row stride bytes
    constexpr int ATILEB = BM * ARSTR;             // 34816 : 18432
    constexpr int BTILEB = 112 * 144;              // 16128
    constexpr int STAGEB = ATILEB + BTILEB;
    constexpr int EPSTR = 116;

    extern __shared__ __align__(16) char smemc[];
    const uint32_t sb = smem_u32(smemc);

    const int nrows = (MODE <= 2) ? g_nact : S_;
    const int row0 = blockIdx.x * BM;
    if (row0 >= nrows) return;
    const int yoff = blockIdx.y * 112;

    const float*  ApF = (MODE == 1) ? Aext : g_pooled;
    const __half* ApH = (MODE == 2) ? g_H1h : g_Yh;
    const __half* Wh  = (MODE == 1) ? g_W1h : (MODE == 2) ? g_W2h
                      : (MODE == 3) ? g_W3h : g_W4h;

    const int t = threadIdx.x, lane = t & 31, wid = t >> 5;
    const int warpM = wid & 1, warpN = wid >> 1;
    const int grp = lane >> 2, qid = lane & 3;
    const int r8 = lane & 7, sub = lane >> 3;      // ldmatrix lane decomposition

    // ---- ldmatrix per-lane base offsets (relative to stage start) ----
    const uint32_t bB = (uint32_t)(ATILEB + (warpN * 56 + (sub >> 1) * 8 + r8) * 144
                                   + (sub & 1) * 16);
    const uint32_t bB6 = (uint32_t)(ATILEB + (warpN * 56 + 48 + r8) * 144
                                    + (sub & 1) * 16);
    const uint32_t aB = (uint32_t)((warpM * 64 + (sub & 1) * 8 + r8) * 144
                                   + (sub >> 1) * 16);

    // ---- A copy row pointers (kept in regs; B recomputed in issue) ----
    const void* asrc[CVTA ? 16 : 8]; bool avalid[CVTA ? 16 : 8];
    if (CVTA) {
#pragma unroll
        for (int i = 0; i < 16; i++) {
            int idx = i * 128 + t;            // 0..2047 = 128 rows x 16 granules
            int m = idx >> 4, g = idx & 15;   // granule = 4 floats
            int grow = row0 + m;
            avalid[i] = grow < nrows;
            int arow = avalid[i] ? ((MODE == 1) ? g_rowmap[grow] : grow) : 0;
            asrc[i] = ApF + (size_t)arow * ASTF + g * 4;
        }
    } else {
#pragma unroll
        for (int i = 0; i < 8; i++) {
            int idx = i * 128 + t;            // 0..1023 = 128 rows x 8 granules
            int m = idx >> 3, g = idx & 7;    // granule = 8 halfs
            int grow = row0 + m;
            avalid[i] = grow < nrows;
            asrc[i] = ApH + (size_t)(avalid[i] ? grow : 0) * ASTH + g * 8;
        }
    }

    auto issue = [&](int kt) {
        const uint32_t sbase = sb + (uint32_t)(kt & 1) * STAGEB;
        const int kb = kt * BK;
        if (CVTA) {
#pragma unroll
            for (int i = 0; i < 16; i++) {
                int idx = i * 128 + t;
                int m = idx >> 4, g = idx & 15;
                uint32_t sz = (avalid[i] && (kb + g * 4) < K) ? 16u : 0u;
                cp16(sbase + (uint32_t)(m * 272 + g * 16),
                     (const float*)asrc[i] + kb, sz);
            }
        } else {
#pragma unroll
            for (int i = 0; i < 8; i++) {
                int idx = i * 128 + t;
                int m = idx >> 3, g = idx & 7;
                uint32_t sz = (avalid[i] && (kb + g * 8 + 8) <= KLIM) ? 16u : 0u;
                cp16(sbase + (uint32_t)(m * 144 + g * 16),
                     (const __half*)asrc[i] + kb, sz);
            }
        }
        // B tile: 112 rows x 8 granules = 896 slots = exactly 7 * 128 threads.
#pragma unroll
        for (int i = 0; i < 7; i++) {
            int idx = i * 128 + t;
            int n = idx >> 3, g = idx & 7;
            int gcol = yoff + n;
            bool v = gcol < NW;
            uint32_t sz = (v && (kb + g * 8 + 8) <= KLIM) ? 16u : 0u;
            cp16(sbase + (uint32_t)(ATILEB + n * 144 + g * 16),
                 Wh + (size_t)(v ? gcol : 0) * WST + g * 8 + kb, sz);
        }
        CP_COMMIT();
    };

    float acc[4][7][4];
#pragma unroll
    for (int mt = 0; mt < 4; mt++)
#pragma unroll
        for (int nt = 0; nt < 7; nt++)
#pragma unroll
            for (int c = 0; c < 4; c++) acc[mt][nt][c] = 0.0f;

    issue(0);
    for (int kt = 0; kt < KT; kt++) {
        CP_WAIT(0);
        __syncthreads();
        if (kt + 1 < KT) issue(kt + 1);

        const uint32_t stb = sb + (uint32_t)(kt & 1) * STAGEB;
        const char* stc = smemc + (size_t)(kt & 1) * STAGEB;
#pragma unroll
        for (int s16 = 0; s16 < 4; s16++) {
            const uint32_t ks = (uint32_t)(s16 * 32);
            uint32_t bf[7][2];
            ldsm4(bf[0][0], bf[0][1], bf[1][0], bf[1][1], stb + bB + ks);
            ldsm4(bf[2][0], bf[2][1], bf[3][0], bf[3][1], stb + bB + 2304 + ks);
            ldsm4(bf[4][0], bf[4][1], bf[5][0], bf[5][1], stb + bB + 4608 + ks);
            ldsm2(bf[6][0], bf[6][1], stb + bB6 + ks);
#pragma unroll
            for (int mt = 0; mt < 4; mt++) {
                uint32_t a0, a1, a2, a3;
                if (CVTA) {
                    const char* ap = stc + (warpM * 64 + grp) * 272
                                   + mt * 16 * 272 + s16 * 64 + qid * 8;
                    float2 p0 = *(const float2*)ap;
                    float2 p1 = *(const float2*)(ap + 2176);
                    float2 p2 = *(const float2*)(ap + 32);
                    float2 p3 = *(const float2*)(ap + 2208);
                    a0 = packh2(p0.x, p0.y);
                    a1 = packh2(p1.x, p1.y);
                    a2 = packh2(p2.x, p2.y);
                    a3 = packh2(p3.x, p3.y);
                } else {
                    ldsm4(a0, a1, a2, a3, stb + aB + (uint32_t)(mt * 2304) + ks);
                }
#pragma unroll
                for (int nt = 0; nt < 7; nt++)
                    mma_f16(acc[mt][nt][0], acc[mt][nt][1],
                            acc[mt][nt][2], acc[mt][nt][3],
                            a0, a1, a2, a3, bf[nt][0], bf[nt][1]);
            }
        }
    }

    // ---- MODE 3: fold 1/n scaling into epilogue ----
    float sc0[4], sc1[4];
#pragma unroll
    for (int mt = 0; mt < 4; mt++) {
        int r = row0 + warpM * 64 + mt * 16 + grp;
        sc0[mt] = (MODE == 3 && r < S_) ? g_invN[r] : 1.0f;
        sc1[mt] = (MODE == 3 && r + 8 < S_) ? g_invN[r + 8] : 1.0f;
    }

    // ---- epilogue ----
    if (MODE == 2) {
        __syncthreads();   // all warps done reading stage buffers before reuse
        float* ep = (float*)smemc;                 // 128 x 116 floats
        int* sample    = (int*)(ep + BM * EPSTR);
        int* segstart  = sample + BM;
        int* segsample = segstart + BM + 1;
        int* pnseg     = segsample + BM;
#pragma unroll
        for (int mt = 0; mt < 4; mt++) {
            int r = warpM * 64 + mt * 16 + grp;
#pragma unroll
            for (int nt = 0; nt < 7; nt++) {
                int c = warpN * 56 + nt * 8 + 2 * qid;
                int gcol = yoff + c;
                float b0 = (gcol < NW) ? bias[gcol] : 0.0f;
                float b1 = (gcol + 1 < NW) ? bias[gcol + 1] : 0.0f;
                *(float2*)(ep + r * EPSTR + c) =
                    make_float2(fmaxf(acc[mt][nt][0] + b0, 0.0f),
                                fmaxf(acc[mt][nt][1] + b1, 0.0f));
                *(float2*)(ep + (r + 8) * EPSTR + c) =
                    make_float2(fmaxf(acc[mt][nt][2] + b0, 0.0f),
                                fmaxf(acc[mt][nt][3] + b1, 0.0f));
            }
        }
        if (t < BM) {
            int g = row0 + t;
            sample[t] = (g < nrows) ? (g_rowmap[g] >> 5) : -1;
        }
        __syncthreads();
        if (t == 0) {
            int lim = nrows - row0; if (lim > BM) lim = BM;
            int ns = 0, cur = -2;
            for (int r = 0; r < lim; r++) {
                int s = sample[r];
                if (s != cur) { segstart[ns] = r; segsample[ns] = s; ns++; cur = s; }
            }
            segstart[ns] = lim;
            *pnseg = ns;
        }
        __syncthreads();
        if (t < 112) {
            int gcol = yoff + t;
            if (gcol < D_) {
                int ns = *pnseg;
                for (int seg = 0; seg < ns; seg++) {
                    int r = segstart[seg], e = segstart[seg + 1];
                    float s0 = 0.f, s1 = 0.f, s2 = 0.f, s3 = 0.f;
                    for (; r + 3 < e; r += 4) {     // 4 independent partials
                        s0 += ep[(r + 0) * EPSTR + t];
                        s1 += ep[(r + 1) * EPSTR + t];
                        s2 += ep[(r + 2) * EPSTR + t];
                        s3 += ep[(r + 3) * EPSTR + t];
                    }
                    for (; r < e; r++) s0 += ep[r * EPSTR + t];
                    atomicAdd(&g_pooled[(size_t)segsample[seg] * D_ + gcol],
                              (s0 + s1) + (s2 + s3));
                }
            }
        }
    } else {
#pragma unroll
        for (int mt = 0; mt < 4; mt++) {
            int r = row0 + warpM * 64 + mt * 16 + grp;
#pragma unroll
            for (int nt = 0; nt < 7; nt++) {
                int gcol = yoff + warpN * 56 + nt * 8 + 2 * qid;
                if (gcol >= NW) continue;
                float b0 = bias[gcol];
                float b1 = bias[gcol + 1];
                float v0 = fmaxf(acc[mt][nt][0] * sc0[mt] + b0, 0.0f);
                float v1 = fmaxf(acc[mt][nt][1] * sc0[mt] + b1, 0.0f);
                float v2 = fmaxf(acc[mt][nt][2] * sc1[mt] + b0, 0.0f);
                float v3 = fmaxf(acc[mt][nt][3] * sc1[mt] + b1, 0.0f);
                if (MODE == 4) {
                    if (r < nrows)
                        *(float2*)(OutExt + (size_t)r * D_ + gcol) = make_float2(v0, v1);
                    if (r + 8 < nrows)
                        *(float2*)(OutExt + (size_t)(r + 8) * D_ + gcol) = make_float2(v2, v3);
                } else {
                    __half* OH = (MODE == 1) ? g_H1h : g_Yh;
                    const int ost = (MODE == 1) ? KP_ : H_;
                    if (r < nrows)
                        *(uint32_t*)(OH + (size_t)r * ost + gcol) = packh2(v0, v1);
                    if (r + 8 < nrows)
                        *(uint32_t*)(OH + (size_t)(r + 8) * ost + gcol) = packh2(v2, v3);
                }
            }
        }
    }
}

// ---------------------------------------------------------------------------------
extern "C" void kernel_launch(void* const* d_in, const int* in_sizes, int n_in,
                              void* d_out, int out_size) {
    (void)in_sizes; (void)n_in; (void)out_size;
    const float* all_x     = (const float*)d_in[0];
    const int*   numInputs = (const int*)  d_in[1];
    const float* W1 = (const float*)d_in[2];
    const float* b1 = (const float*)d_in[3];
    const float* W2 = (const float*)d_in[4];
    const float* b2 = (const float*)d_in[5];
    const float* W3 = (const float*)d_in[6];
    const float* b3 = (const float*)d_in[7];
    const float* W4 = (const float*)d_in[8];
    const float* b4 = (const float*)d_in[9];
    float* out = (float*)d_out;

    const int SMEM_CVT = 2 * (128 * 272 + 112 * 144);   // 101888 (modes 1,3)
    const int SMEM_H   = 2 * (128 * 144 + 112 * 144);   // 69120 (modes 2,4)
    cudaFuncSetAttribute(gemm_h<1, D_, true>,  cudaFuncAttributeMaxDynamicSharedMemorySize, SMEM_CVT);
    cudaFuncSetAttribute(gemm_h<2, D_, false>, cudaFuncAttributeMaxDynamicSharedMemorySize, SMEM_H);
    cudaFuncSetAttribute(gemm_h<3, D_, true>,  cudaFuncAttributeMaxDynamicSharedMemorySize, SMEM_CVT);
    cudaFuncSetAttribute(gemm_h<4, H_, false>, cudaFuncAttributeMaxDynamicSharedMemorySize, SMEM_H);

    setup_kernel<<<1, 256>>>(numInputs);
    {
        int total = S_ * D_ + 2 * D_ * KP_ + H_ * KP_ + D_ * H_ + S_ * M_ * 4;
        prep_kernel<<<(total + 255) / 256, 256>>>(W1, W2, W3, W4);
    }

    // layer 1: H1 = relu(X_active @ W1^T + b1)     [nact, 420] -> fp16 (stride KP_)
    gemm_h<1, D_, true><<<dim3((S_ * M_ + 127) / 128, 4), 128, SMEM_CVT>>>(all_x, b1, nullptr);
    // layer 2 + ragged sum-pool into g_pooled      [nact, 420] -> [S, 420]
    gemm_h<2, D_, false><<<dim3((S_ * M_ + 127) / 128, 4), 128, SMEM_H>>>(nullptr, b2, nullptr);
    // layer 3: Y = relu((pooled @ W3^T)/n + b3)    [S, 840] -> fp16
    gemm_h<3, D_, true><<<dim3(S_ / 128, 8), 128, SMEM_CVT>>>(nullptr, b3, nullptr);
    // layer 4: out = relu(Y @ W4^T + b4)           [S, 420]
    gemm_h<4, H_, false><<<dim3(S_ / 128, 4), 128, SMEM_H>>>(nullptr, b4, out);
}

// round 15
// speedup vs baseline: 5.6336x; 1.0572x over previous
#include <cuda_runtime.h>
#include <cuda_fp16.h>
#include <cstdint>

#define S_ 4096
#define M_ 32
#define D_ 420
#define H_ 840
#define KP_ 424   // padded fp16 K-stride for K=420 rows (848B, 16B-aligned)

// ------------- scratch (static device globals; 256B-aligned for cp.async) --------
__device__ __align__(256) int    g_rowmap[S_ * M_];             // compact row -> s*32+m
__device__ int    g_nact;                                       // number of active rows
__device__ __align__(256) float  g_invN[S_];                    // 1/numInputs[s]
__device__ __align__(256) __half g_Xh[(size_t)S_ * M_ * KP_];   // gathered fp16 inputs
__device__ __align__(256) __half g_H1h[(size_t)S_ * M_ * KP_];  // layer-1 out (fp16)
__device__ __align__(256) float  g_pooled[(size_t)S_ * D_];     // ragged-mean numerator
__device__ __align__(256) __half g_Ph[(size_t)S_ * KP_];        // pooled, fp16 (padded)
__device__ __align__(256) __half g_Yh[(size_t)S_ * H_];         // layer-3 out (fp16)
__device__ __align__(256) __half g_W1h[D_ * KP_];               // fp16 weights [N][KP]
__device__ __align__(256) __half g_W2h[D_ * KP_];
__device__ __align__(256) __half g_W3h[H_ * KP_];
__device__ __align__(256) __half g_W4h[D_ * H_];                // K=840, natural

__device__ __forceinline__ uint32_t packh2(float lo, float hi) {
    uint32_t r;
    asm("cvt.rn.f16x2.f32 %0, %1, %2;" : "=r"(r) : "f"(hi), "f"(lo));
    return r;
}
__device__ __forceinline__ void mma_f16(float& d0, float& d1, float& d2, float& d3,
                                        uint32_t a0, uint32_t a1, uint32_t a2,
                                        uint32_t a3, uint32_t b0, uint32_t b1) {
    asm volatile(
        "mma.sync.aligned.m16n8k16.row.col.f32.f16.f16.f32 "
        "{%0,%1,%2,%3}, {%4,%5,%6,%7}, {%8,%9}, {%0,%1,%2,%3};"
        : "+f"(d0), "+f"(d1), "+f"(d2), "+f"(d3)
        : "r"(a0), "r"(a1), "r"(a2), "r"(a3), "r"(b0), "r"(b1));
}
__device__ __forceinline__ void ldsm4(uint32_t& r0, uint32_t& r1, uint32_t& r2,
                                      uint32_t& r3, uint32_t addr) {
    asm volatile("ldmatrix.sync.aligned.m8n8.x4.shared.b16 {%0,%1,%2,%3}, [%4];"
                 : "=r"(r0), "=r"(r1), "=r"(r2), "=r"(r3) : "r"(addr));
}
__device__ __forceinline__ void ldsm2(uint32_t& r0, uint32_t& r1, uint32_t addr) {
    asm volatile("ldmatrix.sync.aligned.m8n8.x2.shared.b16 {%0,%1}, [%2];"
                 : "=r"(r0), "=r"(r1) : "r"(addr));
}
__device__ __forceinline__ uint32_t smem_u32(const void* p) {
    uint32_t a;
    asm("{ .reg .u64 t; cvta.to.shared.u64 t, %1; cvt.u32.u64 %0, t; }"
        : "=r"(a) : "l"(p));
    return a;
}
__device__ __forceinline__ void cp16(uint32_t dst, const void* src, uint32_t srcsz) {
    asm volatile("cp.async.cg.shared.global [%0], [%1], 16, %2;"
                 :: "r"(dst), "l"(src), "r"(srcsz) : "memory");
}
#define CP_COMMIT() asm volatile("cp.async.commit_group;" ::: "memory")
#define CP_WAIT(n)  asm volatile("cp.async.wait_group %0;" :: "n"(n) : "memory")

// ---------------- setup: prefix-scan numInputs, build compact row map -------------
__global__ void setup_kernel(const int* __restrict__ numInputs) {
    __shared__ int s_warp[8];
    __shared__ int s_woff[8];
    int t = threadIdx.x;
    int base = t * 16;
    int local[16];
    int run = 0;
#pragma unroll
    for (int j = 0; j < 16; j++) { local[j] = run; run += numInputs[base + j]; }
    int lane = t & 31, warp = t >> 5;
    int inc = run;
#pragma unroll
    for (int o = 1; o < 32; o <<= 1) {
        int v = __shfl_up_sync(0xffffffffu, inc, o);
        if (lane >= o) inc += v;
    }
    if (lane == 31) s_warp[warp] = inc;
    __syncthreads();
    if (t == 0) {
        int r = 0;
        for (int w = 0; w < 8; w++) { s_woff[w] = r; r += s_warp[w]; }
        g_nact = r;
    }
    __syncthreads();
    int thrOff = s_woff[warp] + (inc - run);
    for (int j = 0; j < 16; j++) {
        int s = base + j;
        int n = numInputs[s];
        g_invN[s] = 1.0f / (float)n;
        int off = thrOff + local[j];
        for (int m = 0; m < n; m++) g_rowmap[off + m] = s * M_ + m;
    }
}

// fused prep: zero g_pooled, convert weights to fp16 (padded stride, pad zeroed),
// and zero the K-pad of g_H1h (cols 420..423 of every row).
__global__ void prep_kernel(const float* __restrict__ W1, const float* __restrict__ W2,
                            const float* __restrict__ W3, const float* __restrict__ W4) {
    const int NP = S_ * D_;
    const int NW12 = D_ * KP_, NW3 = H_ * KP_, NW4 = D_ * H_;
    const int NH1P = S_ * M_ * 4;                 // pad elems of g_H1h
    int i = blockIdx.x * blockDim.x + threadIdx.x;
    if (i < NP) { g_pooled[i] = 0.0f; return; }
    i -= NP;
    if (i < NW12) {
        int r = i / KP_, c = i - r * KP_;
        g_W1h[i] = (c < D_) ? __float2half_rn(W1[r * D_ + c]) : __half(0.0f);
        return;
    }
    i -= NW12;
    if (i < NW12) {
        int r = i / KP_, c = i - r * KP_;
        g_W2h[i] = (c < D_) ? __float2half_rn(W2[r * D_ + c]) : __half(0.0f);
        return;
    }
    i -= NW12;
    if (i < NW3) {
        int r = i / KP_, c = i - r * KP_;
        g_W3h[i] = (c < D_) ? __float2half_rn(W3[r * D_ + c]) : __half(0.0f);
        return;
    }
    i -= NW3;
    if (i < NW4) { g_W4h[i] = __float2half_rn(W4[i]); return; }
    i -= NW4;
    if (i < NH1P) {
        int r = i >> 2, c = i & 3;
        g_H1h[(size_t)r * KP_ + D_ + c] = __half(0.0f);
    }
}

// gather + convert active rows of all_x -> g_Xh fp16 (pad granule 105 zeroed)
__global__ void convert_x_kernel(const float* __restrict__ all_x) {
    const int total = g_nact * 106;               // 106 8B-granules per row
    int idx = blockIdx.x * blockDim.x + threadIdx.x;
    if (idx >= total) return;
    int r = idx / 106, g = idx - r * 106;
    __half2* dst = (__half2*)(g_Xh + (size_t)r * KP_ + g * 4);
    if (g == 105) {
        dst[0] = __half2half2(__half(0.0f));
        dst[1] = __half2half2(__half(0.0f));
    } else {
        float4 v = *(const float4*)(all_x + (size_t)g_rowmap[r] * D_ + g * 4);
        dst[0] = __floats2half2_rn(v.x, v.y);
        dst[1] = __floats2half2_rn(v.z, v.w);
    }
}

// convert g_pooled -> g_Ph fp16 (padded)
__global__ void convert_p_kernel() {
    int idx = blockIdx.x * blockDim.x + threadIdx.x;
    if (idx >= S_ * 106) return;
    int r = idx / 106, g = idx - r * 106;
    __half2* dst = (__half2*)(g_Ph + (size_t)r * KP_ + g * 4);
    if (g == 105) {
        dst[0] = __half2half2(__half(0.0f));
        dst[1] = __half2half2(__half(0.0f));
    } else {
        float4 v = *(const float4*)(g_pooled + (size_t)r * D_ + g * 4);
        dst[0] = __floats2half2_rn(v.x, v.y);
        dst[1] = __floats2half2_rn(v.z, v.w);
    }
}

// ---------------- fp16 mma GEMM, BM=128, BK=64, warp tile 64x56 -------------------
// MODE 1: A = g_Xh   -> g_H1h, rows = g_nact
// MODE 2: A = g_H1h, epilogue = segmented reduce + atomicAdd g_pooled
// MODE 3: A = g_Ph (1/n in epilogue) -> g_Yh, rows = S
// MODE 4: A = g_Yh -> d_out fp32, rows = S
//
// CTA = 128 threads, 4 warps 2Mx2N, BM=128, BN=112, BK=64, warp tile 64x56.
// 2-stage cp.async pipeline, 3 CTAs/SM. fp16 smem rows 144B (≡16 mod 128 ->
// conflict-free ldmatrix).
template <int MODE, int K>
__global__ void __launch_bounds__(128, 3)
gemm_h(const float* __restrict__ bias, float* __restrict__ OutExt) {
    constexpr int BM = 128, BK = 64;
    constexpr int KT = (K + BK - 1) / BK;
    constexpr int NW  = (MODE == 3) ? H_ : D_;
    constexpr int ASTH = (MODE == 4) ? H_ : KP_;   // fp16 A row stride
    constexpr int WST  = (MODE == 4) ? H_ : KP_;   // weight row stride
    constexpr int KLIM = (MODE == 4) ? H_ : KP_;   // aligned copy limit (pad zeroed)
    constexpr int ATILEB = BM * 144;               // 18432
    constexpr int BTILEB = 112 * 144;              // 16128
    constexpr int STAGEB = ATILEB + BTILEB;
    constexpr int EPSTR = 116;

    extern __shared__ __align__(16) char smemc[];
    const uint32_t sb = smem_u32(smemc);

    const int nrows = (MODE <= 2) ? g_nact : S_;
    const int row0 = blockIdx.x * BM;
    if (row0 >= nrows) return;
    const int yoff = blockIdx.y * 112;

    const __half* ApH = (MODE == 1) ? g_Xh : (MODE == 2) ? g_H1h
                      : (MODE == 3) ? g_Ph : g_Yh;
    const __half* Wh  = (MODE == 1) ? g_W1h : (MODE == 2) ? g_W2h
                      : (MODE == 3) ? g_W3h : g_W4h;

    const int t = threadIdx.x, lane = t & 31, wid = t >> 5;
    const int warpM = wid & 1, warpN = wid >> 1;
    const int grp = lane >> 2, qid = lane & 3;
    const int r8 = lane & 7, sub = lane >> 3;      // ldmatrix lane decomposition

    // ---- ldmatrix per-lane base offsets (relative to stage start) ----
    const uint32_t bB = (uint32_t)(ATILEB + (warpN * 56 + (sub >> 1) * 8 + r8) * 144
                                   + (sub & 1) * 16);
    const uint32_t bB6 = (uint32_t)(ATILEB + (warpN * 56 + 48 + r8) * 144
                                    + (sub & 1) * 16);
    const uint32_t aB = (uint32_t)((warpM * 64 + (sub & 1) * 8 + r8) * 144
                                   + (sub >> 1) * 16);

    // ---- A copy row pointers (kept in regs; B recomputed in issue) ----
    const __half* asrc[8]; bool avalid[8];
#pragma unroll
    for (int i = 0; i < 8; i++) {
        int idx = i * 128 + t;            // 0..1023 = 128 rows x 8 granules
        int m = idx >> 3, g = idx & 7;    // granule = 8 halfs
        int grow = row0 + m;
        avalid[i] = grow < nrows;
        asrc[i] = ApH + (size_t)(avalid[i] ? grow : 0) * ASTH + g * 8;
    }

    auto issue = [&](int kt) {
        const uint32_t sbase = sb + (uint32_t)(kt & 1) * STAGEB;
        const int kb = kt * BK;
#pragma unroll
        for (int i = 0; i < 8; i++) {
            int idx = i * 128 + t;
            int m = idx >> 3, g = idx & 7;
            uint32_t sz = (avalid[i] && (kb + g * 8 + 8) <= KLIM) ? 16u : 0u;
            cp16(sbase + (uint32_t)(m * 144 + g * 16),
                 asrc[i] + kb, sz);
        }
        // B tile: 112 rows x 8 granules = 896 slots = exactly 7 * 128 threads.
#pragma unroll
        for (int i = 0; i < 7; i++) {
            int idx = i * 128 + t;
            int n = idx >> 3, g = idx & 7;
            int gcol = yoff + n;
            bool v = gcol < NW;
            uint32_t sz = (v && (kb + g * 8 + 8) <= KLIM) ? 16u : 0u;
            cp16(sbase + (uint32_t)(ATILEB + n * 144 + g * 16),
                 Wh + (size_t)(v ? gcol : 0) * WST + g * 8 + kb, sz);
        }
        CP_COMMIT();
    };

    float acc[4][7][4];
#pragma unroll
    for (int mt = 0; mt < 4; mt++)
#pragma unroll
        for (int nt = 0; nt < 7; nt++)
#pragma unroll
            for (int c = 0; c < 4; c++) acc[mt][nt][c] = 0.0f;

    issue(0);
    for (int kt = 0; kt < KT; kt++) {
        CP_WAIT(0);
        __syncthreads();
        if (kt + 1 < KT) issue(kt + 1);

        const uint32_t stb = sb + (uint32_t)(kt & 1) * STAGEB;
#pragma unroll
        for (int s16 = 0; s16 < 4; s16++) {
            const uint32_t ks = (uint32_t)(s16 * 32);
            uint32_t bf[7][2];
            ldsm4(bf[0][0], bf[0][1], bf[1][0], bf[1][1], stb + bB + ks);
            ldsm4(bf[2][0], bf[2][1], bf[3][0], bf[3][1], stb + bB + 2304 + ks);
            ldsm4(bf[4][0], bf[4][1], bf[5][0], bf[5][1], stb + bB + 4608 + ks);
            ldsm2(bf[6][0], bf[6][1], stb + bB6 + ks);
#pragma unroll
            for (int mt = 0; mt < 4; mt++) {
                uint32_t a0, a1, a2, a3;
                ldsm4(a0, a1, a2, a3, stb + aB + (uint32_t)(mt * 2304) + ks);
#pragma unroll
                for (int nt = 0; nt < 7; nt++)
                    mma_f16(acc[mt][nt][0], acc[mt][nt][1],
                            acc[mt][nt][2], acc[mt][nt][3],
                            a0, a1, a2, a3, bf[nt][0], bf[nt][1]);
            }
        }
    }

    // ---- MODE 3: fold 1/n scaling into epilogue ----
    float sc0[4], sc1[4];
#pragma unroll
    for (int mt = 0; mt < 4; mt++) {
        int r = row0 + warpM * 64 + mt * 16 + grp;
        sc0[mt] = (MODE == 3 && r < S_) ? g_invN[r] : 1.0f;
        sc1[mt] = (MODE == 3 && r + 8 < S_) ? g_invN[r + 8] : 1.0f;
    }

    // ---- epilogue ----
    if (MODE == 2) {
        __syncthreads();   // all warps done reading stage buffers before reuse
        float* ep = (float*)smemc;                 // 128 x 116 floats
        int* sample    = (int*)(ep + BM * EPSTR);
        int* segstart  = sample + BM;
        int* segsample = segstart + BM + 1;
        int* pnseg     = segsample + BM;
#pragma unroll
        for (int mt = 0; mt < 4; mt++) {
            int r = warpM * 64 + mt * 16 + grp;
#pragma unroll
            for (int nt = 0; nt < 7; nt++) {
                int c = warpN * 56 + nt * 8 + 2 * qid;
                int gcol = yoff + c;
                float b0 = (gcol < NW) ? bias[gcol] : 0.0f;
                float b1 = (gcol + 1 < NW) ? bias[gcol + 1] : 0.0f;
                *(float2*)(ep + r * EPSTR + c) =
                    make_float2(fmaxf(acc[mt][nt][0] + b0, 0.0f),
                                fmaxf(acc[mt][nt][1] + b1, 0.0f));
                *(float2*)(ep + (r + 8) * EPSTR + c) =
                    make_float2(fmaxf(acc[mt][nt][2] + b0, 0.0f),
                                fmaxf(acc[mt][nt][3] + b1, 0.0f));
            }
        }
        if (t < BM) {
            int g = row0 + t;
            sample[t] = (g < nrows) ? (g_rowmap[g] >> 5) : -1;
        }
        __syncthreads();
        if (t == 0) {
            int lim = nrows - row0; if (lim > BM) lim = BM;
            int ns = 0, cur = -2;
            for (int r = 0; r < lim; r++) {
                int s = sample[r];
                if (s != cur) { segstart[ns] = r; segsample[ns] = s; ns++; cur = s; }
            }
            segstart[ns] = lim;
            *pnseg = ns;
        }
        __syncthreads();
        if (t < 112) {
            int gcol = yoff + t;
            if (gcol < D_) {
                int ns = *pnseg;
                for (int seg = 0; seg < ns; seg++) {
                    int r = segstart[seg], e = segstart[seg + 1];
                    float s0 = 0.f, s1 = 0.f, s2 = 0.f, s3 = 0.f;
                    for (; r + 3 < e; r += 4) {     // 4 independent partials
                        s0 += ep[(r + 0) * EPSTR + t];
                        s1 += ep[(r + 1) * EPSTR + t];
                        s2 += ep[(r + 2) * EPSTR + t];
                        s3 += ep[(r + 3) * EPSTR + t];
                    }
                    for (; r < e; r++) s0 += ep[r * EPSTR + t];
                    atomicAdd(&g_pooled[(size_t)segsample[seg] * D_ + gcol],
                              (s0 + s1) + (s2 + s3));
                }
            }
        }
    } else {
#pragma unroll
        for (int mt = 0; mt < 4; mt++) {
            int r = row0 + warpM * 64 + mt * 16 + grp;
#pragma unroll
            for (int nt = 0; nt < 7; nt++) {
                int gcol = yoff + warpN * 56 + nt * 8 + 2 * qid;
                if (gcol >= NW) continue;
                float b0 = bias[gcol];
                float b1 = bias[gcol + 1];
                float v0 = fmaxf(acc[mt][nt][0] * sc0[mt] + b0, 0.0f);
                float v1 = fmaxf(acc[mt][nt][1] * sc0[mt] + b1, 0.0f);
                float v2 = fmaxf(acc[mt][nt][2] * sc1[mt] + b0, 0.0f);
                float v3 = fmaxf(acc[mt][nt][3] * sc1[mt] + b1, 0.0f);
                if (MODE == 4) {
                    if (r < nrows)
                        *(float2*)(OutExt + (size_t)r * D_ + gcol) = make_float2(v0, v1);
                    if (r + 8 < nrows)
                        *(float2*)(OutExt + (size_t)(r + 8) * D_ + gcol) = make_float2(v2, v3);
                } else {
                    __half* OH = (MODE == 1) ? g_H1h : g_Yh;
                    const int ost = (MODE == 1) ? KP_ : H_;
                    if (r < nrows)
                        *(uint32_t*)(OH + (size_t)r * ost + gcol) = packh2(v0, v1);
                    if (r + 8 < nrows)
                        *(uint32_t*)(OH + (size_t)(r + 8) * ost + gcol) = packh2(v2, v3);
                }
            }
        }
    }
}

// ---------------------------------------------------------------------------------
extern "C" void kernel_launch(void* const* d_in, const int* in_sizes, int n_in,
                              void* d_out, int out_size) {
    (void)in_sizes; (void)n_in; (void)out_size;
    const float* all_x     = (const float*)d_in[0];
    const int*   numInputs = (const int*)  d_in[1];
    const float* W1 = (const float*)d_in[2];
    const float* b1 = (const float*)d_in[3];
    const float* W2 = (const float*)d_in[4];
    const float* b2 = (const float*)d_in[5];
    const float* W3 = (const float*)d_in[6];
    const float* b3 = (const float*)d_in[7];
    const float* W4 = (const float*)d_in[8];
    const float* b4 = (const float*)d_in[9];
    float* out = (float*)d_out;

    const int SMEM = 2 * (128 * 144 + 112 * 144);   // 69120 (all modes)
    cudaFuncSetAttribute(gemm_h<1, D_>, cudaFuncAttributeMaxDynamicSharedMemorySize, SMEM);
    cudaFuncSetAttribute(gemm_h<2, D_>, cudaFuncAttributeMaxDynamicSharedMemorySize, SMEM);
    cudaFuncSetAttribute(gemm_h<3, D_>, cudaFuncAttributeMaxDynamicSharedMemorySize, SMEM);
    cudaFuncSetAttribute(gemm_h<4, H_>, cudaFuncAttributeMaxDynamicSharedMemorySize, SMEM);

    setup_kernel<<<1, 256>>>(numInputs);
    {
        int total = S_ * D_ + 2 * D_ * KP_ + H_ * KP_ + D_ * H_ + S_ * M_ * 4;
        prep_kernel<<<(total + 255) / 256, 256>>>(W1, W2, W3, W4);
    }
    // gather + fp16-convert active input rows (worst-case grid, guarded by g_nact)
    convert_x_kernel<<<(S_ * M_ * 106 + 255) / 256, 256>>>(all_x);

    // layer 1: H1 = relu(Xh @ W1^T + b1)           [nact, 420] -> fp16
    gemm_h<1, D_><<<dim3((S_ * M_ + 127) / 128, 4), 128, SMEM>>>(b1, nullptr);
    // layer 2 + ragged sum-pool into g_pooled      [nact, 420] -> [S, 420]
    gemm_h<2, D_><<<dim3((S_ * M_ + 127) / 128, 4), 128, SMEM>>>(b2, nullptr);
    // pooled -> fp16
    convert_p_kernel<<<(S_ * 106 + 255) / 256, 256>>>();
    // layer 3: Y = relu((Ph @ W3^T)/n + b3)        [S, 840] -> fp16
    gemm_h<3, D_><<<dim3(S_ / 128, 8), 128, SMEM>>>(b3, nullptr);
    // layer 4: out = relu(Y @ W4^T + b4)           [S, 420]
    gemm_h<4, H_><<<dim3(S_ / 128, 4), 128, SMEM>>>(b4, out);
}

// round 16
// speedup vs baseline: 5.8073x; 1.0308x over previous
#include <cuda_runtime.h>
#include <cuda_fp16.h>
#include <cstdint>

#define S_ 4096
#define M_ 32
#define D_ 420
#define H_ 840
#define KP_ 424   // padded fp16 K-stride for K=420 rows (848B, 16B-aligned)

// ------------- scratch (static device globals; 256B-aligned for cp.async) --------
__device__ __align__(256) int    g_rowmap[S_ * M_];             // compact row -> s*32+m
__device__ int    g_nact;                                       // number of active rows
__device__ __align__(256) float  g_invN[S_];                    // 1/numInputs[s]
__device__ __align__(256) __half g_Xh[(size_t)S_ * M_ * KP_];   // gathered fp16 inputs
__device__ __align__(256) __half g_H1h[(size_t)S_ * M_ * KP_];  // layer-1 out (fp16)
__device__ __align__(256) float  g_pooled[(size_t)S_ * D_];     // ragged-mean numerator
__device__ __align__(256) __half g_Ph[(size_t)S_ * KP_];        // pooled, fp16 (padded)
__device__ __align__(256) __half g_Yh[(size_t)S_ * H_];         // layer-3 out (fp16)
__device__ __align__(256) __half g_W1h[D_ * KP_];               // fp16 weights [N][KP]
__device__ __align__(256) __half g_W2h[D_ * KP_];
__device__ __align__(256) __half g_W3h[H_ * KP_];
__device__ __align__(256) __half g_W4h[D_ * H_];                // K=840, natural

__device__ __forceinline__ uint32_t packh2(float lo, float hi) {
    uint32_t r;
    asm("cvt.rn.f16x2.f32 %0, %1, %2;" : "=r"(r) : "f"(hi), "f"(lo));
    return r;
}
__device__ __forceinline__ void mma_f16(float& d0, float& d1, float& d2, float& d3,
                                        uint32_t a0, uint32_t a1, uint32_t a2,
                                        uint32_t a3, uint32_t b0, uint32_t b1) {
    asm volatile(
        "mma.sync.aligned.m16n8k16.row.col.f32.f16.f16.f32 "
        "{%0,%1,%2,%3}, {%4,%5,%6,%7}, {%8,%9}, {%0,%1,%2,%3};"
        : "+f"(d0), "+f"(d1), "+f"(d2), "+f"(d3)
        : "r"(a0), "r"(a1), "r"(a2), "r"(a3), "r"(b0), "r"(b1));
}
__device__ __forceinline__ void ldsm4(uint32_t& r0, uint32_t& r1, uint32_t& r2,
                                      uint32_t& r3, uint32_t addr) {
    asm volatile("ldmatrix.sync.aligned.m8n8.x4.shared.b16 {%0,%1,%2,%3}, [%4];"
                 : "=r"(r0), "=r"(r1), "=r"(r2), "=r"(r3) : "r"(addr));
}
__device__ __forceinline__ void ldsm2(uint32_t& r0, uint32_t& r1, uint32_t addr) {
    asm volatile("ldmatrix.sync.aligned.m8n8.x2.shared.b16 {%0,%1}, [%2];"
                 : "=r"(r0), "=r"(r1) : "r"(addr));
}
__device__ __forceinline__ uint32_t smem_u32(const void* p) {
    uint32_t a;
    asm("{ .reg .u64 t; cvta.to.shared.u64 t, %1; cvt.u32.u64 %0, t; }"
        : "=r"(a) : "l"(p));
    return a;
}
__device__ __forceinline__ void cp16(uint32_t dst, const void* src, uint32_t srcsz) {
    asm volatile("cp.async.cg.shared.global [%0], [%1], 16, %2;"
                 :: "r"(dst), "l"(src), "r"(srcsz) : "memory");
}
#define CP_COMMIT() asm volatile("cp.async.commit_group;" ::: "memory")
#define CP_WAIT(n)  asm volatile("cp.async.wait_group %0;" :: "n"(n) : "memory")

// ---------------- setup: prefix-scan numInputs, build compact row map -------------
__global__ void setup_kernel(const int* __restrict__ numInputs) {
    __shared__ int s_warp[8];
    __shared__ int s_woff[8];
    int t = threadIdx.x;
    int base = t * 16;
    int local[16];
    int run = 0;
#pragma unroll
    for (int j = 0; j < 16; j++) { local[j] = run; run += numInputs[base + j]; }
    int lane = t & 31, warp = t >> 5;
    int inc = run;
#pragma unroll
    for (int o = 1; o < 32; o <<= 1) {
        int v = __shfl_up_sync(0xffffffffu, inc, o);
        if (lane >= o) inc += v;
    }
    if (lane == 31) s_warp[warp] = inc;
    __syncthreads();
    if (t == 0) {
        int r = 0;
        for (int w = 0; w < 8; w++) { s_woff[w] = r; r += s_warp[w]; }
        g_nact = r;
    }
    __syncthreads();
    int thrOff = s_woff[warp] + (inc - run);
    for (int j = 0; j < 16; j++) {
        int s = base + j;
        int n = numInputs[s];
        g_invN[s] = 1.0f / (float)n;
        int off = thrOff + local[j];
        for (int m = 0; m < n; m++) g_rowmap[off + m] = s * M_ + m;
    }
}

// granule-vectorized prep: zero g_pooled, weights->fp16 (pad zeroed), H1h K-pad zero
__global__ void prep_kernel(const float* __restrict__ W1, const float* __restrict__ W2,
                            const float* __restrict__ W3, const float* __restrict__ W4) {
    const int NPZ = S_ * D_ / 4;                  // float4 zeros of g_pooled
    const int GW12 = D_ * 53, GW3 = H_ * 53;      // 8-half granules (53 per padded row)
    const int GW4 = D_ * (H_ / 8);                // 105 granules per 840 row
    const int NH1P = S_ * M_;                     // one 8B pad store per row
    int i = blockIdx.x * blockDim.x + threadIdx.x;
    if (i < NPZ) {
        ((float4*)g_pooled)[i] = make_float4(0.f, 0.f, 0.f, 0.f);
        return;
    }
    i -= NPZ;
    if (i < 2 * GW12 + GW3) {
        const float* Ws; __half* Wd;
        if (i < GW12) { Ws = W1; Wd = g_W1h; }
        else if (i < 2 * GW12) { Ws = W2; Wd = g_W2h; i -= GW12; }
        else { Ws = W3; Wd = g_W3h; i -= 2 * GW12; }
        int r = i / 53, g = i - r * 53;
        uint4 u;
        if (g == 52) {
            float4 v = *(const float4*)(Ws + (size_t)r * D_ + 416);
            u.x = packh2(v.x, v.y); u.y = packh2(v.z, v.w);
            u.z = 0u; u.w = 0u;
        } else {
            float4 v0 = *(const float4*)(Ws + (size_t)r * D_ + g * 8);
            float4 v1 = *(const float4*)(Ws + (size_t)r * D_ + g * 8 + 4);
            u.x = packh2(v0.x, v0.y); u.y = packh2(v0.z, v0.w);
            u.z = packh2(v1.x, v1.y); u.w = packh2(v1.z, v1.w);
        }
        *(uint4*)(Wd + (size_t)r * KP_ + g * 8) = u;
        return;
    }
    i -= 2 * GW12 + GW3;
    if (i < GW4) {
        float4 v0 = *(const float4*)(W4 + (size_t)i * 8);
        float4 v1 = *(const float4*)(W4 + (size_t)i * 8 + 4);
        uint4 u;
        u.x = packh2(v0.x, v0.y); u.y = packh2(v0.z, v0.w);
        u.z = packh2(v1.x, v1.y); u.w = packh2(v1.z, v1.w);
        *(uint4*)(g_W4h + (size_t)i * 8) = u;
        return;
    }
    i -= GW4;
    if (i < NH1P) {
        *(uint2*)(g_H1h + (size_t)i * KP_ + D_) = make_uint2(0u, 0u);
    }
}

// gather + convert active rows of all_x -> g_Xh fp16, 16B granules (53 per row)
__global__ void convert_x_kernel(const float* __restrict__ all_x) {
    const int total = g_nact * 53;
    int idx = blockIdx.x * blockDim.x + threadIdx.x;
    if (idx >= total) return;
    int r = idx / 53, g = idx - r * 53;
    const float* src = all_x + (size_t)g_rowmap[r] * D_;
    uint4 u;
    if (g == 52) {
        float4 v = *(const float4*)(src + 416);
        u.x = packh2(v.x, v.y); u.y = packh2(v.z, v.w);
        u.z = 0u; u.w = 0u;
    } else {
        float4 v0 = *(const float4*)(src + g * 8);
        float4 v1 = *(const float4*)(src + g * 8 + 4);
        u.x = packh2(v0.x, v0.y); u.y = packh2(v0.z, v0.w);
        u.z = packh2(v1.x, v1.y); u.w = packh2(v1.z, v1.w);
    }
    *(uint4*)(g_Xh + (size_t)r * KP_ + g * 8) = u;
}

// convert g_pooled -> g_Ph fp16 (padded), 16B granules
__global__ void convert_p_kernel() {
    int idx = blockIdx.x * blockDim.x + threadIdx.x;
    if (idx >= S_ * 53) return;
    int r = idx / 53, g = idx - r * 53;
    const float* src = g_pooled + (size_t)r * D_;
    uint4 u;
    if (g == 52) {
        float4 v = *(const float4*)(src + 416);
        u.x = packh2(v.x, v.y); u.y = packh2(v.z, v.w);
        u.z = 0u; u.w = 0u;
    } else {
        float4 v0 = *(const float4*)(src + g * 8);
        float4 v1 = *(const float4*)(src + g * 8 + 4);
        u.x = packh2(v0.x, v0.y); u.y = packh2(v0.z, v0.w);
        u.z = packh2(v1.x, v1.y); u.w = packh2(v1.z, v1.w);
    }
    *(uint4*)(g_Ph + (size_t)r * KP_ + g * 8) = u;
}

// ---------------- fp16 mma GEMM, 256 threads, BM=128, BK=64, warp tile 32x56 ------
// MODE 1: A = g_Xh   -> g_H1h, rows = g_nact
// MODE 2: A = g_H1h, epilogue = segmented reduce + atomicAdd g_pooled
// MODE 3: A = g_Ph (1/n in epilogue) -> g_Yh, rows = S
// MODE 4: A = g_Yh -> d_out fp32, rows = S
//
// 8 warps (4M x 2N), warp tile 32x56 (acc 56 regs) -> 2 CTAs/SM = 4 warps/SMSP.
// 2-stage cp.async pipeline; fp16 smem rows 144B (conflict-free ldmatrix).
template <int MODE, int K>
__global__ void __launch_bounds__(256, 2)
gemm_h(const float* __restrict__ bias, float* __restrict__ OutExt) {
    constexpr int BM = 128, BK = 64;
    constexpr int KT = (K + BK - 1) / BK;
    constexpr int NW  = (MODE == 3) ? H_ : D_;
    constexpr int ASTH = (MODE == 4) ? H_ : KP_;   // fp16 A row stride
    constexpr int WST  = (MODE == 4) ? H_ : KP_;   // weight row stride
    constexpr int KLIM = (MODE == 4) ? H_ : KP_;   // aligned copy limit (pad zeroed)
    constexpr int ATILEB = BM * 144;               // 18432
    constexpr int BTILEB = 112 * 144;              // 16128
    constexpr int STAGEB = ATILEB + BTILEB;
    constexpr int EPSTR = 116;

    extern __shared__ __align__(16) char smemc[];
    const uint32_t sb = smem_u32(smemc);

    const int nrows = (MODE <= 2) ? g_nact : S_;
    const int row0 = blockIdx.x * BM;
    if (row0 >= nrows) return;
    const int yoff = blockIdx.y * 112;

    const __half* ApH = (MODE == 1) ? g_Xh : (MODE == 2) ? g_H1h
                      : (MODE == 3) ? g_Ph : g_Yh;
    const __half* Wh  = (MODE == 1) ? g_W1h : (MODE == 2) ? g_W2h
                      : (MODE == 3) ? g_W3h : g_W4h;

    const int t = threadIdx.x, lane = t & 31, wid = t >> 5;
    const int warpM = wid & 3, warpN = wid >> 2;
    const int grp = lane >> 2, qid = lane & 3;
    const int r8 = lane & 7, sub = lane >> 3;      // ldmatrix lane decomposition

    // ---- ldmatrix per-lane base offsets (relative to stage start) ----
    const uint32_t bB = (uint32_t)(ATILEB + (warpN * 56 + (sub >> 1) * 8 + r8) * 144
                                   + (sub & 1) * 16);
    const uint32_t bB6 = (uint32_t)(ATILEB + (warpN * 56 + 48 + r8) * 144
                                    + (sub & 1) * 16);
    const uint32_t aB = (uint32_t)((warpM * 32 + (sub & 1) * 8 + r8) * 144
                                   + (sub >> 1) * 16);

    // ---- A copy row pointers (kept in regs; B recomputed in issue) ----
    const __half* asrc[4]; bool avalid[4];
#pragma unroll
    for (int i = 0; i < 4; i++) {
        int idx = i * 256 + t;            // 0..1023 = 128 rows x 8 granules
        int m = idx >> 3, g = idx & 7;    // granule = 8 halfs
        int grow = row0 + m;
        avalid[i] = grow < nrows;
        asrc[i] = ApH + (size_t)(avalid[i] ? grow : 0) * ASTH + g * 8;
    }

    auto issue = [&](int kt) {
        const uint32_t sbase = sb + (uint32_t)(kt & 1) * STAGEB;
        const int kb = kt * BK;
#pragma unroll
        for (int i = 0; i < 4; i++) {
            int idx = i * 256 + t;
            int m = idx >> 3, g = idx & 7;
            uint32_t sz = (avalid[i] && (kb + g * 8 + 8) <= KLIM) ? 16u : 0u;
            cp16(sbase + (uint32_t)(m * 144 + g * 16), asrc[i] + kb, sz);
        }
        // B tile: 112 rows x 8 granules = 896 slots; slots >= 896 must not store.
#pragma unroll
        for (int i = 0; i < 4; i++) {
            int idx = i * 256 + t;
            if (idx < 896) {
                int n = idx >> 3, g = idx & 7;
                int gcol = yoff + n;
                bool v = gcol < NW;
                uint32_t sz = (v && (kb + g * 8 + 8) <= KLIM) ? 16u : 0u;
                cp16(sbase + (uint32_t)(ATILEB + n * 144 + g * 16),
                     Wh + (size_t)(v ? gcol : 0) * WST + g * 8 + kb, sz);
            }
        }
        CP_COMMIT();
    };

    float acc[2][7][4];
#pragma unroll
    for (int mt = 0; mt < 2; mt++)
#pragma unroll
        for (int nt = 0; nt < 7; nt++)
#pragma unroll
            for (int c = 0; c < 4; c++) acc[mt][nt][c] = 0.0f;

    issue(0);
    for (int kt = 0; kt < KT; kt++) {
        CP_WAIT(0);
        __syncthreads();
        if (kt + 1 < KT) issue(kt + 1);

        const uint32_t stb = sb + (uint32_t)(kt & 1) * STAGEB;
#pragma unroll
        for (int s16 = 0; s16 < 4; s16++) {
            const uint32_t ks = (uint32_t)(s16 * 32);
            uint32_t bf[7][2];
            ldsm4(bf[0][0], bf[0][1], bf[1][0], bf[1][1], stb + bB + ks);
            ldsm4(bf[2][0], bf[2][1], bf[3][0], bf[3][1], stb + bB + 2304 + ks);
            ldsm4(bf[4][0], bf[4][1], bf[5][0], bf[5][1], stb + bB + 4608 + ks);
            ldsm2(bf[6][0], bf[6][1], stb + bB6 + ks);
#pragma unroll
            for (int mt = 0; mt < 2; mt++) {
                uint32_t a0, a1, a2, a3;
                ldsm4(a0, a1, a2, a3, stb + aB + (uint32_t)(mt * 2304) + ks);
#pragma unroll
                for (int nt = 0; nt < 7; nt++)
                    mma_f16(acc[mt][nt][0], acc[mt][nt][1],
                            acc[mt][nt][2], acc[mt][nt][3],
                            a0, a1, a2, a3, bf[nt][0], bf[nt][1]);
            }
        }
    }

    // ---- MODE 3: fold 1/n scaling into epilogue ----
    float sc0[2], sc1[2];
#pragma unroll
    for (int mt = 0; mt < 2; mt++) {
        int r = row0 + warpM * 32 + mt * 16 + grp;
        sc0[mt] = (MODE == 3 && r < S_) ? g_invN[r] : 1.0f;
        sc1[mt] = (MODE == 3 && r + 8 < S_) ? g_invN[r + 8] : 1.0f;
    }

    // ---- epilogue ----
    if (MODE == 2) {
        __syncthreads();   // all warps done reading stage buffers before reuse
        float* ep = (float*)smemc;                 // 128 x 116 floats
        int* sample    = (int*)(ep + BM * EPSTR);
        int* segstart  = sample + BM;
        int* segsample = segstart + BM + 1;
        int* pnseg     = segsample + BM;
#pragma unroll
        for (int mt = 0; mt < 2; mt++) {
            int r = warpM * 32 + mt * 16 + grp;
#pragma unroll
            for (int nt = 0; nt < 7; nt++) {
                int c = warpN * 56 + nt * 8 + 2 * qid;
                int gcol = yoff + c;
                float b0 = (gcol < NW) ? bias[gcol] : 0.0f;
                float b1 = (gcol + 1 < NW) ? bias[gcol + 1] : 0.0f;
                *(float2*)(ep + r * EPSTR + c) =
                    make_float2(fmaxf(acc[mt][nt][0] + b0, 0.0f),
                                fmaxf(acc[mt][nt][1] + b1, 0.0f));
                *(float2*)(ep + (r + 8) * EPSTR + c) =
                    make_float2(fmaxf(acc[mt][nt][2] + b0, 0.0f),
                                fmaxf(acc[mt][nt][3] + b1, 0.0f));
            }
        }
        if (t < BM) {
            int g = row0 + t;
            sample[t] = (g < nrows) ? (g_rowmap[g] >> 5) : -1;
        }
        __syncthreads();
        if (t == 0) {
            int lim = nrows - row0; if (lim > BM) lim = BM;
            int ns = 0, cur = -2;
            for (int r = 0; r < lim; r++) {
                int s = sample[r];
                if (s != cur) { segstart[ns] = r; segsample[ns] = s; ns++; cur = s; }
            }
            segstart[ns] = lim;
            *pnseg = ns;
        }
        __syncthreads();
        if (t < 224) {
            int c = (t < 112) ? t : t - 112;
            int sset = (t < 112) ? 0 : 1;
            int gcol = yoff + c;
            if (gcol < D_) {
                int ns = *pnseg;
                for (int seg = sset; seg < ns; seg += 2) {
                    int r = segstart[seg], e = segstart[seg + 1];
                    float s0 = 0.f, s1 = 0.f, s2 = 0.f, s3 = 0.f;
                    for (; r + 3 < e; r += 4) {     // 4 independent partials
                        s0 += ep[(r + 0) * EPSTR + c];
                        s1 += ep[(r + 1) * EPSTR + c];
                        s2 += ep[(r + 2) * EPSTR + c];
                        s3 += ep[(r + 3) * EPSTR + c];
                    }
                    for (; r < e; r++) s0 += ep[r * EPSTR + c];
                    atomicAdd(&g_pooled[(size_t)segsample[seg] * D_ + gcol],
                              (s0 + s1) + (s2 + s3));
                }
            }
        }
    } else {
#pragma unroll
        for (int mt = 0; mt < 2; mt++) {
            int r = row0 + warpM * 32 + mt * 16 + grp;
#pragma unroll
            for (int nt = 0; nt < 7; nt++) {
                int gcol = yoff + warpN * 56 + nt * 8 + 2 * qid;
                if (gcol >= NW) continue;
                float b0 = bias[gcol];
                float b1 = bias[gcol + 1];
                float v0 = fmaxf(acc[mt][nt][0] * sc0[mt] + b0, 0.0f);
                float v1 = fmaxf(acc[mt][nt][1] * sc0[mt] + b1, 0.0f);
                float v2 = fmaxf(acc[mt][nt][2] * sc1[mt] + b0, 0.0f);
                float v3 = fmaxf(acc[mt][nt][3] * sc1[mt] + b1, 0.0f);
                if (MODE == 4) {
                    if (r < nrows)
                        *(float2*)(OutExt + (size_t)r * D_ + gcol) = make_float2(v0, v1);
                    if (r + 8 < nrows)
                        *(float2*)(OutExt + (size_t)(r + 8) * D_ + gcol) = make_float2(v2, v3);
                } else {
                    __half* OH = (MODE == 1) ? g_H1h : g_Yh;
                    const int ost = (MODE == 1) ? KP_ : H_;
                    if (r < nrows)
                        *(uint32_t*)(OH + (size_t)r * ost + gcol) = packh2(v0, v1);
                    if (r + 8 < nrows)
                        *(uint32_t*)(OH + (size_t)(r + 8) * ost + gcol) = packh2(v2, v3);
                }
            }
        }
    }
}

// ---------------------------------------------------------------------------------
extern "C" void kernel_launch(void* const* d_in, const int* in_sizes, int n_in,
                              void* d_out, int out_size) {
    (void)in_sizes; (void)n_in; (void)out_size;
    const float* all_x     = (const float*)d_in[0];
    const int*   numInputs = (const int*)  d_in[1];
    const float* W1 = (const float*)d_in[2];
    const float* b1 = (const float*)d_in[3];
    const float* W2 = (const float*)d_in[4];
    const float* b2 = (const float*)d_in[5];
    const float* W3 = (const float*)d_in[6];
    const float* b3 = (const float*)d_in[7];
    const float* W4 = (const float*)d_in[8];
    const float* b4 = (const float*)d_in[9];
    float* out = (float*)d_out;

    const int SMEM = 2 * (128 * 144 + 112 * 144);   // 69120 (all modes)
    cudaFuncSetAttribute(gemm_h<1, D_>, cudaFuncAttributeMaxDynamicSharedMemorySize, SMEM);
    cudaFuncSetAttribute(gemm_h<2, D_>, cudaFuncAttributeMaxDynamicSharedMemorySize, SMEM);
    cudaFuncSetAttribute(gemm_h<3, D_>, cudaFuncAttributeMaxDynamicSharedMemorySize, SMEM);
    cudaFuncSetAttribute(gemm_h<4, H_>, cudaFuncAttributeMaxDynamicSharedMemorySize, SMEM);

    setup_kernel<<<1, 256>>>(numInputs);
    {
        int total = S_ * D_ / 4 + 2 * (D_ * 53) + H_ * 53 + D_ * (H_ / 8) + S_ * M_;
        prep_kernel<<<(total + 255) / 256, 256>>>(W1, W2, W3, W4);
    }
    // gather + fp16-convert active input rows (worst-case grid, guarded by g_nact)
    convert_x_kernel<<<(S_ * M_ * 53 + 255) / 256, 256>>>(all_x);

    // layer 1: H1 = relu(Xh @ W1^T + b1)           [nact, 420] -> fp16
    gemm_h<1, D_><<<dim3((S_ * M_ + 127) / 128, 4), 256, SMEM>>>(b1, nullptr);
    // layer 2 + ragged sum-pool into g_pooled      [nact, 420] -> [S, 420]
    gemm_h<2, D_><<<dim3((S_ * M_ + 127) / 128, 4), 256, SMEM>>>(b2, nullptr);
    // pooled -> fp16
    convert_p_kernel<<<(S_ * 53 + 255) / 256, 256>>>();
    // layer 3: Y = relu((Ph @ W3^T)/n + b3)        [S, 840] -> fp16
    gemm_h<3, D_><<<dim3(S_ / 128, 8), 256, SMEM>>>(b3, nullptr);
    // layer 4: out = relu(Y @ W4^T + b4)           [S, 420]
    gemm_h<4, H_><<<dim3(S_ / 128, 4), 256, SMEM>>>(b4, out);
}